// round 7
// baseline (speedup 1.0000x reference)
#include <cuda_runtime.h>
#include <cuda_bf16.h>
#include <math.h>
#include <stdint.h>

// Problem constants
#define BATCH 4
#define SEQT  1024
#define DMODEL 1024
#define NHEAD 16
#define DHEAD 64
#define NBH   (BATCH*NHEAD)      // 64
#define BT    (BATCH*SEQT)       // 4096
#define NSTEPS 3

#define HEADEL (NBH*SEQT*DHEAD)          // 4,194,304
#define FEL    (2L*HEADEL)               // fused re|im D buffer: [bh][128][1024]
#define AEL    ((size_t)NBH*SEQT*SEQT)   // 67,108,864

// ---------------- scratch (device globals; no allocation allowed) ------------
__device__ float g_proj[(size_t)BT*5120];          // packed [Q|K|Dre|Dim|V] fp32
__device__ float g_S[AEL];                         // scores fp32
__device__ float g_DT[2L*FEL];                     // D fused: [pp][bh][reim*64+d][t]
__device__ float g_gate_scratch[HEADEL];

__device__ __nv_bfloat16 g_xh[BT*DMODEL],  g_xl[BT*DMODEL];
__device__ __nv_bfloat16 g_W5h[5*DMODEL*DMODEL], g_W5l[5*DMODEL*DMODEL];
__device__ __nv_bfloat16 g_WOh[DMODEL*DMODEL],   g_WOl[DMODEL*DMODEL];
__device__ __nv_bfloat16 g_Qh[HEADEL], g_Ql[HEADEL], g_Kh[HEADEL], g_Kl[HEADEL];
__device__ __nv_bfloat16 g_Ah[AEL], g_Al[AEL];
__device__ __nv_bfloat16 g_DTh[2L*FEL], g_DTl[2L*FEL];
__device__ __nv_bfloat16 g_Ph[BT*DMODEL], g_Pl[BT*DMODEL];

// ---------------- PTX helpers ------------------------------------------------
__device__ __forceinline__ uint32_t smem_u32(const void* p) {
    return (uint32_t)__cvta_generic_to_shared(p);
}
__device__ __forceinline__ void cp16(uint32_t dst, const void* src) {
    asm volatile("cp.async.cg.shared.global [%0], [%1], 16;\n" :: "r"(dst), "l"(src));
}
__device__ __forceinline__ void cp_commit() { asm volatile("cp.async.commit_group;\n"); }
template<int N> __device__ __forceinline__ void cp_wait() {
    asm volatile("cp.async.wait_group %0;\n" :: "n"(N));
}
__device__ __forceinline__ void ldsm4(uint32_t& r0, uint32_t& r1, uint32_t& r2, uint32_t& r3, uint32_t addr) {
    asm volatile("ldmatrix.sync.aligned.m8n8.x4.shared.b16 {%0,%1,%2,%3}, [%4];\n"
                 : "=r"(r0), "=r"(r1), "=r"(r2), "=r"(r3) : "r"(addr));
}
__device__ __forceinline__ void mma16816(float* c, const uint32_t* a, const uint32_t* b) {
    asm volatile("mma.sync.aligned.m16n8k16.row.col.f32.bf16.bf16.f32 "
                 "{%0,%1,%2,%3}, {%4,%5,%6,%7}, {%8,%9}, {%0,%1,%2,%3};\n"
                 : "+f"(c[0]), "+f"(c[1]), "+f"(c[2]), "+f"(c[3])
                 : "r"(a[0]), "r"(a[1]), "r"(a[2]), "r"(a[3]), "r"(b[0]), "r"(b[1]));
}
__device__ __forceinline__ __nv_bfloat16 bf_hi(float v) { return __float2bfloat16(v); }
__device__ __forceinline__ __nv_bfloat16 bf_lo(float v, __nv_bfloat16 h) {
    return __float2bfloat16(v - __bfloat162float(h));
}

// ---------------- split-bf16 tensor-core GEMM --------------------------------
// C[m][n] = alpha * sum_k (A[m][k] * B[n][k])   (A row-major, B stored [n][k])
// 3-product split: Ah*Bh + Ah*Bl + Al*Bh.
// EPI==1: v = lam*acc + (1-lam)*Cin; writes fp32 C AND bf16 hi/lo for next step.
// K % 32 == 0. BK = 32. 256 threads. STAGES-deep cp.async ring.
// smem swizzle: phys_chunk = kchunk ^ ((row>>1)&3)  (conflict-free ldmatrix)
template<int BM, int BN, int WM, int WN, int EPI, int STAGES>
__global__ __launch_bounds__(256)
void mma_gemm(const __nv_bfloat16* __restrict__ Ahi, const __nv_bfloat16* __restrict__ Alo,
              long sA, int lda,
              const __nv_bfloat16* __restrict__ Bhi, const __nv_bfloat16* __restrict__ Blo,
              long sB, int ldb,
              float* __restrict__ C, long sC, int ldc,
              const float* __restrict__ Cin, long sI,
              __nv_bfloat16* __restrict__ Chi, __nv_bfloat16* __restrict__ Clo,
              int K, float alpha, const float* __restrict__ lam_ptr)
{
    constexpr int ACH = BM * 4;   // 16B chunks per A tile (BK=32 -> 4 chunks/row)
    constexpr int BCH = BN * 4;
    constexpr int MI = WM / 16;
    constexpr int NI = WN / 8;
    constexpr int WROWS = BM / WM;

    extern __shared__ uint4 sm[];
    uint4* sAh_ = sm;                          // [STAGES][ACH]
    uint4* sAl_ = sAh_ + STAGES * ACH;
    uint4* sBh_ = sAl_ + STAGES * ACH;
    uint4* sBl_ = sBh_ + STAGES * BCH;

    const int z = blockIdx.z;
    const __nv_bfloat16* pAh = Ahi + (long)z * sA;
    const __nv_bfloat16* pAl = Alo + (long)z * sA;
    const __nv_bfloat16* pBh = Bhi + (long)z * sB;
    const __nv_bfloat16* pBl = Blo + (long)z * sB;

    const int row0 = blockIdx.y * BM;
    const int col0 = blockIdx.x * BN;
    const int tid  = threadIdx.x;
    const int warp = tid >> 5, lane = tid & 31;
    const int wm = (warp % WROWS) * WM;
    const int wn = (warp / WROWS) * WN;

    float acc[MI][NI][4];
#pragma unroll
    for (int i = 0; i < MI; i++)
#pragma unroll
        for (int j = 0; j < NI; j++)
#pragma unroll
            for (int q = 0; q < 4; q++) acc[i][j][q] = 0.f;

    auto load_tile = [&](int st, int kt) {
#pragma unroll
        for (int i = tid; i < ACH; i += 256) {
            int r = i >> 2, c = i & 3;
            int phys = c ^ ((r >> 1) & 3);
            long src = (long)(row0 + r) * lda + kt * 32 + c * 8;
            cp16(smem_u32(&sAh_[st * ACH + r * 4 + phys]), pAh + src);
            cp16(smem_u32(&sAl_[st * ACH + r * 4 + phys]), pAl + src);
        }
#pragma unroll
        for (int i = tid; i < BCH; i += 256) {
            int r = i >> 2, c = i & 3;
            int phys = c ^ ((r >> 1) & 3);
            long src = (long)(col0 + r) * ldb + kt * 32 + c * 8;
            cp16(smem_u32(&sBh_[st * BCH + r * 4 + phys]), pBh + src);
            cp16(smem_u32(&sBl_[st * BCH + r * 4 + phys]), pBl + src);
        }
        cp_commit();
    };

    const int KT = K / 32;
#pragma unroll
    for (int i = 0; i < STAGES - 1; i++) {
        if (i < KT) load_tile(i, i);
        else cp_commit();
    }

    for (int kt = 0; kt < KT; kt++) {
        cp_wait<STAGES - 2>();
        __syncthreads();                       // tile kt ready; stage being reloaded is drained

        {   // issue next tile into the slot consumed at iteration kt-1
            int next = kt + STAGES - 1;
            if (next < KT) load_tile(next % STAGES, next);
            else cp_commit();                  // empty group keeps wait arithmetic valid
        }

        const int st = kt % STAGES;
        const uint4* tAh = sAh_ + st * ACH;
        const uint4* tAl = sAl_ + st * ACH;
        const uint4* tBh = sBh_ + st * BCH;
        const uint4* tBl = sBl_ + st * BCH;
        const int tr = lane & 7;

#pragma unroll
        for (int ks8 = 0; ks8 < 2; ks8++) {   // two k16 steps per 32-tile
            uint32_t ah[MI][4], al[MI][4];
            const int akc = ks8 * 2 + (lane >> 4);
#pragma unroll
            for (int mi = 0; mi < MI; mi++) {
                int r = wm + mi * 16 + tr + ((lane >> 3) & 1) * 8;
                int off = r * 4 + (akc ^ ((r >> 1) & 3));
                ldsm4(ah[mi][0], ah[mi][1], ah[mi][2], ah[mi][3], smem_u32(tAh + off));
                ldsm4(al[mi][0], al[mi][1], al[mi][2], al[mi][3], smem_u32(tAl + off));
            }
            const int bkc = ks8 * 2 + ((lane >> 3) & 1);
            // process NI in halves of 4 to bound live B-fragment registers
#pragma unroll
            for (int half = 0; half < NI / 4; half++) {
                uint32_t bh[4][2], bl[4][2];
#pragma unroll
                for (int p = 0; p < 2; p++) {
                    int r = wn + (half * 2 + p) * 16 + tr + (lane >> 4) * 8;
                    int off = r * 4 + (bkc ^ ((r >> 1) & 3));
                    ldsm4(bh[2*p][0], bh[2*p][1], bh[2*p+1][0], bh[2*p+1][1], smem_u32(tBh + off));
                    ldsm4(bl[2*p][0], bl[2*p][1], bl[2*p+1][0], bl[2*p+1][1], smem_u32(tBl + off));
                }
#pragma unroll
                for (int mi = 0; mi < MI; mi++)
#pragma unroll
                    for (int nj = 0; nj < 4; nj++) {
                        float* a_ = acc[mi][half * 4 + nj];
                        mma16816(a_, ah[mi], bh[nj]);
                        mma16816(a_, ah[mi], bl[nj]);
                        mma16816(a_, al[mi], bh[nj]);
                    }
            }
        }
    }

    // ------- epilogue -------
    float al_ = alpha, be_ = 0.f;
    if (EPI == 1) {
        float lm = 1.f / (1.f + __expf(-lam_ptr[0]));
        al_ = lm; be_ = 1.f - lm;
    }
    const long zC = (long)z * sC;
    const long zI = (long)z * sI;
    const int g = lane >> 2, tig = lane & 3;
#pragma unroll
    for (int mi = 0; mi < MI; mi++) {
#pragma unroll
        for (int ni = 0; ni < NI; ni++) {
            int r = row0 + wm + mi * 16 + g;
            int cc = col0 + wn + ni * 8 + tig * 2;
#pragma unroll
            for (int half = 0; half < 2; half++) {
                int rr = r + half * 8;
                float v0 = al_ * acc[mi][ni][half * 2 + 0];
                float v1 = al_ * acc[mi][ni][half * 2 + 1];
                long o = zC + (long)rr * ldc + cc;
                if (EPI == 1) {
                    long oi = zI + (long)rr * ldc + cc;
                    v0 += be_ * Cin[oi];
                    v1 += be_ * Cin[oi + 1];
                }
                float2 f2; f2.x = v0; f2.y = v1;
                *(float2*)&C[o] = f2;
                if (EPI == 1) {
                    __nv_bfloat162 hv, lv;
                    hv.x = bf_hi(v0); hv.y = bf_hi(v1);
                    lv.x = bf_lo(v0, hv.x); lv.y = bf_lo(v1, hv.y);
                    *(__nv_bfloat162*)&Chi[o] = hv;
                    *(__nv_bfloat162*)&Clo[o] = lv;
                }
            }
        }
    }
}

// ---------------- conversions ------------------------------------------------
__global__ void split_ew_k(const float* __restrict__ src,
                           __nv_bfloat16* __restrict__ hi, __nv_bfloat16* __restrict__ lo, int n)
{
    int i = blockIdx.x * 256 + threadIdx.x;
    if (i < n) {
        float v = src[i];
        __nv_bfloat16 h = bf_hi(v);
        hi[i] = h; lo[i] = bf_lo(v, h);
    }
}

// W [1024][1024] (k rows, n cols) -> out [n][k] split
__global__ void splitT_w_k(const float* __restrict__ W,
                           __nv_bfloat16* __restrict__ hi, __nv_bfloat16* __restrict__ lo)
{
    __shared__ float t[32][33];
    int k0 = blockIdx.y * 32, n0 = blockIdx.x * 32;
    for (int i = threadIdx.y; i < 32; i += 8)
        t[i][threadIdx.x] = W[(k0 + i) * DMODEL + n0 + threadIdx.x];
    __syncthreads();
    for (int i = threadIdx.y; i < 32; i += 8) {
        float v = t[threadIdx.x][i];             // W[k0+tx][n0+i]
        __nv_bfloat16 h = bf_hi(v);
        long o = (long)(n0 + i) * DMODEL + k0 + threadIdx.x;
        hi[o] = h; lo[o] = bf_lo(v, h);
    }
}

// proj column slice -> per-head [bh][t][d] split (no transpose)
__global__ void split_heads_k(const float* __restrict__ proj, int coloff,
                              __nv_bfloat16* __restrict__ hi, __nv_bfloat16* __restrict__ lo)
{
    int i = blockIdx.x * 256 + threadIdx.x;     // over NBH*SEQT*DHEAD
    int d = i & 63, t = (i >> 6) & 1023, bh = i >> 16;
    int b = bh >> 4, h = bh & 15;
    float v = proj[((long)(b * SEQT + t)) * 5120 + coloff + h * DHEAD + d];
    __nv_bfloat16 hh = bf_hi(v);
    hi[i] = hh; lo[i] = bf_lo(v, hh);
}

// proj D slice -> fused transposed [bh][rowoff+d][t], fp32 + split
__global__ void split_D_init_k(const float* __restrict__ proj, int coloff, int rowoff,
                               float* __restrict__ f,
                               __nv_bfloat16* __restrict__ hi, __nv_bfloat16* __restrict__ lo)
{
    __shared__ float tb[32][33];
    int bh = blockIdx.z, b = bh >> 4, h = bh & 15;
    int t0 = blockIdx.x * 32, d0 = blockIdx.y * 32;
    for (int i = threadIdx.y; i < 32; i += 8)
        tb[i][threadIdx.x] = proj[((long)(b * SEQT + t0 + i)) * 5120 + coloff + h * DHEAD + d0 + threadIdx.x];
    __syncthreads();
    long base = (long)bh * (128 * SEQT);
    for (int i = threadIdx.y; i < 32; i += 8) {
        float v = tb[threadIdx.x][i];            // (t=t0+tx, d=d0+i)
        long o = base + (long)(rowoff + d0 + i) * SEQT + t0 + threadIdx.x;
        __nv_bfloat16 hh = bf_hi(v);
        f[o] = v; hi[o] = hh; lo[o] = bf_lo(v, hh);
    }
}

// ---------------- single-pass softmax over rows of 1024, writes bf16 hi/lo ---
__global__ void softmax_split_k(const float* __restrict__ S,
                                __nv_bfloat16* __restrict__ Ah, __nv_bfloat16* __restrict__ Al)
{
    const long rb = (long)blockIdx.x * SEQT;
    const int tid = threadIdx.x;
    __shared__ float sh[8];

    float4 v = *(const float4*)(S + rb + tid * 4);

    float m = fmaxf(fmaxf(v.x, v.y), fmaxf(v.z, v.w));
#pragma unroll
    for (int o = 16; o; o >>= 1) m = fmaxf(m, __shfl_xor_sync(0xffffffffu, m, o));
    if ((tid & 31) == 0) sh[tid >> 5] = m;
    __syncthreads();
    if (tid < 8) {
        float mm = sh[tid];
#pragma unroll
        for (int o = 4; o; o >>= 1) mm = fmaxf(mm, __shfl_xor_sync(0xffu, mm, o));
        sh[tid] = mm;
    }
    __syncthreads();
    m = sh[0];
    __syncthreads();

    float e0 = __expf(v.x - m), e1 = __expf(v.y - m);
    float e2 = __expf(v.z - m), e3 = __expf(v.w - m);
    float s = e0 + e1 + e2 + e3;
#pragma unroll
    for (int o = 16; o; o >>= 1) s += __shfl_xor_sync(0xffffffffu, s, o);
    if ((tid & 31) == 0) sh[tid >> 5] = s;
    __syncthreads();
    if (tid < 8) {
        float ss = sh[tid];
#pragma unroll
        for (int o = 4; o; o >>= 1) ss += __shfl_xor_sync(0xffu, ss, o);
        sh[tid] = ss;
    }
    __syncthreads();
    const float inv = 1.f / sh[0];

    e0 *= inv; e1 *= inv; e2 *= inv; e3 *= inv;
    __nv_bfloat162 h01, h23, l01, l23;
    h01.x = bf_hi(e0); h01.y = bf_hi(e1);
    h23.x = bf_hi(e2); h23.y = bf_hi(e3);
    l01.x = bf_lo(e0, h01.x); l01.y = bf_lo(e1, h01.y);
    l23.x = bf_lo(e2, h23.x); l23.y = bf_lo(e3, h23.y);
    *(__nv_bfloat162*)(Ah + rb + tid * 4)     = h01;
    *(__nv_bfloat162*)(Ah + rb + tid * 4 + 2) = h23;
    *(__nv_bfloat162*)(Al + rb + tid * 4)     = l01;
    *(__nv_bfloat162*)(Al + rb + tid * 4 + 2) = l23;
}

// ---------------- readout on fused transposed D: one warp per (bh,d) row -----
__global__ void readout2_k(const float* __restrict__ F,   // [bh][128][1024], re rows 0-63
                           const float* __restrict__ proj,
                           float* __restrict__ gate,
                           __nv_bfloat16* __restrict__ Ph, __nv_bfloat16* __restrict__ Pl)
{
    int warp = threadIdx.x >> 5, lane = threadIdx.x & 31;
    int gid = blockIdx.x * 8 + warp;            // 0..4095
    int bh = gid >> 6, d = gid & 63;
    int b = bh >> 4, h = bh & 15;
    const float* rre = F + (long)bh * (128 * SEQT) + d * SEQT;
    const float* rim = rre + 64 * SEQT;

    float re[32], im[32];
    float sre = 0.f, sim = 0.f;
#pragma unroll
    for (int j = 0; j < 32; j++) {
        re[j] = rre[lane + j * 32]; im[j] = rim[lane + j * 32];
        sre += re[j]; sim += im[j];
    }
#pragma unroll
    for (int o = 16; o; o >>= 1) {
        sre += __shfl_xor_sync(0xffffffffu, sre, o);
        sim += __shfl_xor_sync(0xffffffffu, sim, o);
    }
    float mr = sre * (1.f / SEQT), mi = sim * (1.f / SEQT);
    float mn = sqrtf(mr * mr + mi * mi);

    float cs[32]; float mx = -1e30f;
#pragma unroll
    for (int j = 0; j < 32; j++) {
        float dot = re[j] * mr + im[j] * mi;
        float nrm = sqrtf(re[j] * re[j] + im[j] * im[j]) * mn + 1e-8f;
        cs[j] = dot / nrm;
        mx = fmaxf(mx, cs[j]);
    }
#pragma unroll
    for (int o = 16; o; o >>= 1) mx = fmaxf(mx, __shfl_xor_sync(0xffffffffu, mx, o));
    float s = 0.f;
#pragma unroll
    for (int j = 0; j < 32; j++) { cs[j] = __expf(cs[j] - mx); s += cs[j]; }
#pragma unroll
    for (int o = 16; o; o >>= 1) s += __shfl_xor_sync(0xffffffffu, s, o);
    float inv = 1.f / s;

#pragma unroll
    for (int j = 0; j < 32; j++) {
        int t = lane + j * 32;
        float g = cs[j] * inv;
        gate[(long)bh * (SEQT * DHEAD) + t * DHEAD + d] = g;
        float v = proj[((long)(b * SEQT + t)) * 5120 + 4096 + h * DHEAD + d];
        float pv = g * v;
        __nv_bfloat16 hh = bf_hi(pv);
        long po = ((long)(b * SEQT + t)) * DMODEL + h * DHEAD + d;
        Ph[po] = hh; Pl[po] = bf_lo(pv, hh);
    }
}

// -----------------------------------------------------------------------------
extern "C" void kernel_launch(void* const* d_in, const int* in_sizes, int n_in,
                              void* d_out, int out_size)
{
    const float* x   = (const float*)d_in[0];
    const float* WQ  = (const float*)d_in[1];
    const float* WK  = (const float*)d_in[2];
    const float* Wre = (const float*)d_in[3];
    const float* Wim = (const float*)d_in[4];
    const float* WV  = (const float*)d_in[5];
    const float* WO  = (const float*)d_in[6];
    const float* lam = (const float*)d_in[7];
    float* out = (float*)d_out;

    float *pproj, *pS, *pDT, *pGateScr;
    __nv_bfloat16 *pxh, *pxl, *pW5h, *pW5l, *pWOh, *pWOl;
    __nv_bfloat16 *pQh, *pQl, *pKh, *pKl, *pAh, *pAl, *pDTh, *pDTl, *pPh, *pPl;
    cudaGetSymbolAddress((void**)&pproj, g_proj);
    cudaGetSymbolAddress((void**)&pS, g_S);
    cudaGetSymbolAddress((void**)&pDT, g_DT);
    cudaGetSymbolAddress((void**)&pGateScr, g_gate_scratch);
    cudaGetSymbolAddress((void**)&pxh, g_xh);
    cudaGetSymbolAddress((void**)&pxl, g_xl);
    cudaGetSymbolAddress((void**)&pW5h, g_W5h);
    cudaGetSymbolAddress((void**)&pW5l, g_W5l);
    cudaGetSymbolAddress((void**)&pWOh, g_WOh);
    cudaGetSymbolAddress((void**)&pWOl, g_WOl);
    cudaGetSymbolAddress((void**)&pQh, g_Qh);
    cudaGetSymbolAddress((void**)&pQl, g_Ql);
    cudaGetSymbolAddress((void**)&pKh, g_Kh);
    cudaGetSymbolAddress((void**)&pKl, g_Kl);
    cudaGetSymbolAddress((void**)&pAh, g_Ah);
    cudaGetSymbolAddress((void**)&pAl, g_Al);
    cudaGetSymbolAddress((void**)&pDTh, g_DTh);
    cudaGetSymbolAddress((void**)&pDTl, g_DTl);
    cudaGetSymbolAddress((void**)&pPh, g_Ph);
    cudaGetSymbolAddress((void**)&pPl, g_Pl);

    const long OUT_ELEMS  = (long)BT * DMODEL;
    const long GATE_ELEMS = (long)HEADEL;
    float* gate = (out_size >= (int)(OUT_ELEMS + GATE_ELEMS)) ? (out + OUT_ELEMS) : pGateScr;

    // 4 stages x (A:128 + B:256 rows) x 4 chunks x hi/lo x 16B = 192 KB
    const int SMEM = 4 * (128 * 4 + 256 * 4) * 2 * 16;
    cudaFuncSetAttribute(mma_gemm<128,256,64,64,0,4>, cudaFuncAttributeMaxDynamicSharedMemorySize, SMEM);
    cudaFuncSetAttribute(mma_gemm<128,256,64,64,1,4>, cudaFuncAttributeMaxDynamicSharedMemorySize, SMEM);

    // ---- input splits ----
    split_ew_k<<<(BT * DMODEL + 255) / 256, 256>>>(x, pxh, pxl, BT * DMODEL);
    dim3 tb(32, 8), tg(32, 32);
    const float* Ws[5] = {WQ, WK, Wre, Wim, WV};
    for (int w = 0; w < 5; w++)
        splitT_w_k<<<tg, tb>>>(Ws[w], pW5h + (long)w * DMODEL * DMODEL, pW5l + (long)w * DMODEL * DMODEL);
    splitT_w_k<<<tg, tb>>>(WO, pWOh, pWOl);

    // ---- fused 5-way projection: [4096,5120] = x @ [WQ|WK|Wre|Wim|WV] ----
    mma_gemm<128,256,64,64,0,4><<<dim3(5120/256, BT/128, 1), 256, SMEM>>>(
        pxh, pxl, 0, DMODEL, pW5h, pW5l, 0, DMODEL,
        pproj, 0, 5120, nullptr, 0, nullptr, nullptr, DMODEL, 1.f, nullptr);

    // ---- per-head splits of Q, K; fused transposed split of Dre/Dim ----
    split_heads_k<<<HEADEL / 256, 256>>>(pproj, 0,    pQh, pQl);
    split_heads_k<<<HEADEL / 256, 256>>>(pproj, 1024, pKh, pKl);
    split_D_init_k<<<dim3(32, 2, NBH), tb>>>(pproj, 2048, 0,  pDT, pDTh, pDTl);
    split_D_init_k<<<dim3(32, 2, NBH), tb>>>(pproj, 3072, 64, pDT, pDTh, pDTl);

    // ---- scores: S[bh][t][s] = Q @ K^T / 8 ----
    mma_gemm<128,256,64,64,0,4><<<dim3(SEQT/256, SEQT/128, NBH), 256, SMEM>>>(
        pQh, pQl, (long)SEQT * DHEAD, DHEAD,
        pKh, pKl, (long)SEQT * DHEAD, DHEAD,
        pS, (long)SEQT * SEQT, SEQT, nullptr, 0, nullptr, nullptr, DHEAD, 0.125f, nullptr);

    // ---- softmax rows -> A bf16 hi/lo (single pass) ----
    softmax_split_k<<<NBH * SEQT, 256>>>(pS, pAh, pAl);

    // ---- propagation, re/im fused M=128: F' = lam*(F @ A^T) + (1-lam)*F ----
    for (int s = 0; s < NSTEPS; s++) {
        long iin = (long)(s & 1) * FEL;
        long iou = (long)(1 - (s & 1)) * FEL;
        mma_gemm<128,256,64,64,1,4><<<dim3(SEQT/256, 1, NBH), 256, SMEM>>>(
            pDTh + iin, pDTl + iin, 128L * SEQT, SEQT,
            pAh, pAl, (long)SEQT * SEQT, SEQT,
            pDT + iou, 128L * SEQT, SEQT,
            pDT + iin, 128L * SEQT,
            pDTh + iou, pDTl + iou,
            SEQT, 0.f, lam);
    }
    // after 3 steps final is pp index 1

    // ---- readout + gating (writes gate + P hi/lo) ----
    readout2_k<<<NBH * DHEAD / 8, 256>>>(pDT + FEL, pproj, gate, pPh, pPl);

    // ---- out = P @ W_O ----
    mma_gemm<128,256,64,64,0,4><<<dim3(DMODEL/256, BT/128, 1), 256, SMEM>>>(
        pPh, pPl, 0, DMODEL, pWOh, pWOl, 0, DMODEL,
        out, 0, DMODEL, nullptr, 0, nullptr, nullptr, DMODEL, 1.f, nullptr);
}

// round 8
// speedup vs baseline: 1.2305x; 1.2305x over previous
#include <cuda_runtime.h>
#include <cuda_bf16.h>
#include <cuda_fp16.h>
#include <math.h>
#include <stdint.h>

// Problem constants
#define BATCH 4
#define SEQT  1024
#define DMODEL 1024
#define NHEAD 16
#define DHEAD 64
#define NBH   (BATCH*NHEAD)      // 64
#define BT    (BATCH*SEQT)       // 4096
#define NSTEPS 3

#define HEADEL (NBH*SEQT*DHEAD)          // 4,194,304
#define FEL    (2L*HEADEL)               // fused re|im D: [bh][128][1024]
#define AEL    ((size_t)NBH*SEQT*SEQT)   // 67,108,864

// ---------------- scratch (device globals; no allocation allowed) ------------
__device__ float g_proj[(size_t)BT*5120];          // packed [Q|K|Dre|Dim|V] fp32
__device__ float g_S[AEL];                         // scores fp32
__device__ float g_DT[FEL];                        // final-step D fp32 for readout
__device__ float g_gate_scratch[HEADEL];

__device__ __nv_bfloat16 g_xh[BT*DMODEL],  g_xl[BT*DMODEL];
__device__ __nv_bfloat16 g_W5h[5*DMODEL*DMODEL], g_W5l[5*DMODEL*DMODEL];
__device__ __nv_bfloat16 g_WOh[DMODEL*DMODEL],   g_WOl[DMODEL*DMODEL];
__device__ __nv_bfloat16 g_Qh[HEADEL], g_Ql[HEADEL], g_Kh[HEADEL], g_Kl[HEADEL];
__device__ __half        g_Af[AEL];                // adjacency, single fp16
__device__ __half        g_DTh[2L*FEL], g_DTl[2L*FEL];   // [pp] fp16 hi/lo
__device__ __nv_bfloat16 g_Ph[BT*DMODEL], g_Pl[BT*DMODEL];

// ---------------- PTX helpers ------------------------------------------------
__device__ __forceinline__ uint32_t smem_u32(const void* p) {
    return (uint32_t)__cvta_generic_to_shared(p);
}
__device__ __forceinline__ void cp16(uint32_t dst, const void* src) {
    asm volatile("cp.async.cg.shared.global [%0], [%1], 16;\n" :: "r"(dst), "l"(src));
}
__device__ __forceinline__ void cp_commit() { asm volatile("cp.async.commit_group;\n"); }
template<int N> __device__ __forceinline__ void cp_wait() {
    asm volatile("cp.async.wait_group %0;\n" :: "n"(N));
}
__device__ __forceinline__ void ldsm4(uint32_t& r0, uint32_t& r1, uint32_t& r2, uint32_t& r3, uint32_t addr) {
    asm volatile("ldmatrix.sync.aligned.m8n8.x4.shared.b16 {%0,%1,%2,%3}, [%4];\n"
                 : "=r"(r0), "=r"(r1), "=r"(r2), "=r"(r3) : "r"(addr));
}
__device__ __forceinline__ void mma_bf16(float* c, const uint32_t* a, const uint32_t* b) {
    asm volatile("mma.sync.aligned.m16n8k16.row.col.f32.bf16.bf16.f32 "
                 "{%0,%1,%2,%3}, {%4,%5,%6,%7}, {%8,%9}, {%0,%1,%2,%3};\n"
                 : "+f"(c[0]), "+f"(c[1]), "+f"(c[2]), "+f"(c[3])
                 : "r"(a[0]), "r"(a[1]), "r"(a[2]), "r"(a[3]), "r"(b[0]), "r"(b[1]));
}
__device__ __forceinline__ void mma_f16(float* c, const uint32_t* a, const uint32_t* b) {
    asm volatile("mma.sync.aligned.m16n8k16.row.col.f32.f16.f16.f32 "
                 "{%0,%1,%2,%3}, {%4,%5,%6,%7}, {%8,%9}, {%0,%1,%2,%3};\n"
                 : "+f"(c[0]), "+f"(c[1]), "+f"(c[2]), "+f"(c[3])
                 : "r"(a[0]), "r"(a[1]), "r"(a[2]), "r"(a[3]), "r"(b[0]), "r"(b[1]));
}
__device__ __forceinline__ __nv_bfloat16 bf_hi(float v) { return __float2bfloat16(v); }
__device__ __forceinline__ __nv_bfloat16 bf_lo(float v, __nv_bfloat16 h) {
    return __float2bfloat16(v - __bfloat162float(h));
}
__device__ __forceinline__ __half hf_hi(float v) { return __float2half(v); }
__device__ __forceinline__ __half hf_lo(float v, __half h) {
    return __float2half(v - __half2float(h));
}

// ---------------- split-bf16 tensor-core GEMM (R5 config) --------------------
// C[m][n] = alpha * sum_k (A[m][k] * B[n][k])   (A row-major, B stored [n][k])
// 3-product split: Ah*Bh + Ah*Bl + Al*Bh. BK=32, 3-stage cp.async ring.
// smem swizzle: phys_chunk = kchunk ^ ((row>>1)&3)  (conflict-free ldmatrix)
template<int BM, int BN, int WM, int WN, int STAGES>
__global__ __launch_bounds__(256)
void mma_gemm(const __nv_bfloat16* __restrict__ Ahi, const __nv_bfloat16* __restrict__ Alo,
              long sA, int lda,
              const __nv_bfloat16* __restrict__ Bhi, const __nv_bfloat16* __restrict__ Blo,
              long sB, int ldb,
              float* __restrict__ C, long sC, int ldc,
              int K, float alpha)
{
    constexpr int ACH = BM * 4;
    constexpr int BCH = BN * 4;
    constexpr int MI = WM / 16;
    constexpr int NI = WN / 8;
    constexpr int WROWS = BM / WM;

    extern __shared__ uint4 sm[];
    uint4* sAh_ = sm;
    uint4* sAl_ = sAh_ + STAGES * ACH;
    uint4* sBh_ = sAl_ + STAGES * ACH;
    uint4* sBl_ = sBh_ + STAGES * BCH;

    const int z = blockIdx.z;
    const __nv_bfloat16* pAh = Ahi + (long)z * sA;
    const __nv_bfloat16* pAl = Alo + (long)z * sA;
    const __nv_bfloat16* pBh = Bhi + (long)z * sB;
    const __nv_bfloat16* pBl = Blo + (long)z * sB;

    const int row0 = blockIdx.y * BM;
    const int col0 = blockIdx.x * BN;
    const int tid  = threadIdx.x;
    const int warp = tid >> 5, lane = tid & 31;
    const int wm = (warp % WROWS) * WM;
    const int wn = (warp / WROWS) * WN;

    float acc[MI][NI][4];
#pragma unroll
    for (int i = 0; i < MI; i++)
#pragma unroll
        for (int j = 0; j < NI; j++)
#pragma unroll
            for (int q = 0; q < 4; q++) acc[i][j][q] = 0.f;

    auto load_tile = [&](int st, int kt) {
#pragma unroll
        for (int i = tid; i < ACH; i += 256) {
            int r = i >> 2, c = i & 3;
            int phys = c ^ ((r >> 1) & 3);
            long src = (long)(row0 + r) * lda + kt * 32 + c * 8;
            cp16(smem_u32(&sAh_[st * ACH + r * 4 + phys]), pAh + src);
            cp16(smem_u32(&sAl_[st * ACH + r * 4 + phys]), pAl + src);
        }
#pragma unroll
        for (int i = tid; i < BCH; i += 256) {
            int r = i >> 2, c = i & 3;
            int phys = c ^ ((r >> 1) & 3);
            long src = (long)(col0 + r) * ldb + kt * 32 + c * 8;
            cp16(smem_u32(&sBh_[st * BCH + r * 4 + phys]), pBh + src);
            cp16(smem_u32(&sBl_[st * BCH + r * 4 + phys]), pBl + src);
        }
        cp_commit();
    };

    const int KT = K / 32;
#pragma unroll
    for (int i = 0; i < STAGES - 1; i++) {
        if (i < KT) load_tile(i, i);
        else cp_commit();
    }

    for (int kt = 0; kt < KT; kt++) {
        cp_wait<STAGES - 2>();
        __syncthreads();

        {
            int next = kt + STAGES - 1;
            if (next < KT) load_tile(next % STAGES, next);
            else cp_commit();
        }

        const int st = kt % STAGES;
        const uint4* tAh = sAh_ + st * ACH;
        const uint4* tAl = sAl_ + st * ACH;
        const uint4* tBh = sBh_ + st * BCH;
        const uint4* tBl = sBl_ + st * BCH;
        const int tr = lane & 7;

#pragma unroll
        for (int ks8 = 0; ks8 < 2; ks8++) {
            uint32_t ah[MI][4], al[MI][4];
            const int akc = ks8 * 2 + (lane >> 4);
#pragma unroll
            for (int mi = 0; mi < MI; mi++) {
                int r = wm + mi * 16 + tr + ((lane >> 3) & 1) * 8;
                int off = r * 4 + (akc ^ ((r >> 1) & 3));
                ldsm4(ah[mi][0], ah[mi][1], ah[mi][2], ah[mi][3], smem_u32(tAh + off));
                ldsm4(al[mi][0], al[mi][1], al[mi][2], al[mi][3], smem_u32(tAl + off));
            }
            uint32_t bh[NI][2], bl[NI][2];
            const int bkc = ks8 * 2 + ((lane >> 3) & 1);
#pragma unroll
            for (int p = 0; p < NI / 2; p++) {
                int r = wn + p * 16 + tr + (lane >> 4) * 8;
                int off = r * 4 + (bkc ^ ((r >> 1) & 3));
                ldsm4(bh[2*p][0], bh[2*p][1], bh[2*p+1][0], bh[2*p+1][1], smem_u32(tBh + off));
                ldsm4(bl[2*p][0], bl[2*p][1], bl[2*p+1][0], bl[2*p+1][1], smem_u32(tBl + off));
            }
#pragma unroll
            for (int mi = 0; mi < MI; mi++)
#pragma unroll
                for (int ni = 0; ni < NI; ni++) {
                    mma_bf16(acc[mi][ni], ah[mi], bh[ni]);
                    mma_bf16(acc[mi][ni], ah[mi], bl[ni]);
                    mma_bf16(acc[mi][ni], al[mi], bh[ni]);
                }
        }
    }

    const long zC = (long)z * sC;
    const int g = lane >> 2, tig = lane & 3;
#pragma unroll
    for (int mi = 0; mi < MI; mi++) {
#pragma unroll
        for (int ni = 0; ni < NI; ni++) {
            int r = row0 + wm + mi * 16 + g;
            int cc = col0 + wn + ni * 8 + tig * 2;
#pragma unroll
            for (int half_ = 0; half_ < 2; half_++) {
                int rr = r + half_ * 8;
                float2 f2;
                f2.x = alpha * acc[mi][ni][half_ * 2 + 0];
                f2.y = alpha * acc[mi][ni][half_ * 2 + 1];
                *(float2*)&C[zC + (long)rr * ldc + cc] = f2;
            }
        }
    }
}

// ---------------- fp16 propagation GEMM --------------------------------------
// DT'[m][t] = lam * sum_s (DT[m][s]*Aadj[t][s]) + (1-lam)*DT[m][t]
// A-operand = DT fp16 hi/lo (2 products), B-operand = adjacency single fp16.
// Writes fp16 hi/lo always; fp32 C only when Cf != nullptr (final step).
// BM=128, BN=128, WM=64, WN=32, BK=32, 4-stage ring (24KB/stage).
__global__ __launch_bounds__(256)
void prop_gemm(const __half* __restrict__ Ahi, const __half* __restrict__ Alo,
               long sA, int lda,
               const __half* __restrict__ Bh_, long sB, int ldb,
               float* __restrict__ Cf,
               const __half* __restrict__ Cinh, const __half* __restrict__ Cinl,
               __half* __restrict__ Chi, __half* __restrict__ Clo,
               long sZ, int ldz, int K, const float* __restrict__ lam_ptr)
{
    constexpr int BM = 128, BN = 128, WM = 64, WN = 32, STAGES = 4;
    constexpr int ACH = BM * 4;
    constexpr int BCH = BN * 4;
    constexpr int MI = WM / 16;   // 4
    constexpr int NI = WN / 8;    // 4
    constexpr int WROWS = BM / WM;

    extern __shared__ uint4 sm[];
    uint4* sAh_ = sm;
    uint4* sAl_ = sAh_ + STAGES * ACH;
    uint4* sBh_ = sAl_ + STAGES * ACH;

    const int z = blockIdx.z;
    const __half* pAh = Ahi + (long)z * sA;
    const __half* pAl = Alo + (long)z * sA;
    const __half* pBh = Bh_ + (long)z * sB;

    const int row0 = blockIdx.y * BM;
    const int col0 = blockIdx.x * BN;
    const int tid  = threadIdx.x;
    const int warp = tid >> 5, lane = tid & 31;
    const int wm = (warp % WROWS) * WM;
    const int wn = (warp / WROWS) * WN;

    float acc[MI][NI][4];
#pragma unroll
    for (int i = 0; i < MI; i++)
#pragma unroll
        for (int j = 0; j < NI; j++)
#pragma unroll
            for (int q = 0; q < 4; q++) acc[i][j][q] = 0.f;

    auto load_tile = [&](int st, int kt) {
#pragma unroll
        for (int i = tid; i < ACH; i += 256) {
            int r = i >> 2, c = i & 3;
            int phys = c ^ ((r >> 1) & 3);
            long src = (long)(row0 + r) * lda + kt * 32 + c * 8;
            cp16(smem_u32(&sAh_[st * ACH + r * 4 + phys]), pAh + src);
            cp16(smem_u32(&sAl_[st * ACH + r * 4 + phys]), pAl + src);
        }
#pragma unroll
        for (int i = tid; i < BCH; i += 256) {
            int r = i >> 2, c = i & 3;
            int phys = c ^ ((r >> 1) & 3);
            long src = (long)(col0 + r) * ldb + kt * 32 + c * 8;
            cp16(smem_u32(&sBh_[st * BCH + r * 4 + phys]), pBh + src);
        }
        cp_commit();
    };

    const int KT = K / 32;
#pragma unroll
    for (int i = 0; i < STAGES - 1; i++) {
        if (i < KT) load_tile(i, i);
        else cp_commit();
    }

    for (int kt = 0; kt < KT; kt++) {
        cp_wait<STAGES - 2>();
        __syncthreads();

        {
            int next = kt + STAGES - 1;
            if (next < KT) load_tile(next % STAGES, next);
            else cp_commit();
        }

        const int st = kt % STAGES;
        const uint4* tAh = sAh_ + st * ACH;
        const uint4* tAl = sAl_ + st * ACH;
        const uint4* tBh = sBh_ + st * BCH;
        const int tr = lane & 7;

#pragma unroll
        for (int ks8 = 0; ks8 < 2; ks8++) {
            uint32_t ah[MI][4], al[MI][4];
            const int akc = ks8 * 2 + (lane >> 4);
#pragma unroll
            for (int mi = 0; mi < MI; mi++) {
                int r = wm + mi * 16 + tr + ((lane >> 3) & 1) * 8;
                int off = r * 4 + (akc ^ ((r >> 1) & 3));
                ldsm4(ah[mi][0], ah[mi][1], ah[mi][2], ah[mi][3], smem_u32(tAh + off));
                ldsm4(al[mi][0], al[mi][1], al[mi][2], al[mi][3], smem_u32(tAl + off));
            }
            uint32_t bh[NI][2];
            const int bkc = ks8 * 2 + ((lane >> 3) & 1);
#pragma unroll
            for (int p = 0; p < NI / 2; p++) {
                int r = wn + p * 16 + tr + (lane >> 4) * 8;
                int off = r * 4 + (bkc ^ ((r >> 1) & 3));
                ldsm4(bh[2*p][0], bh[2*p][1], bh[2*p+1][0], bh[2*p+1][1], smem_u32(tBh + off));
            }
#pragma unroll
            for (int mi = 0; mi < MI; mi++)
#pragma unroll
                for (int ni = 0; ni < NI; ni++) {
                    mma_f16(acc[mi][ni], ah[mi], bh[ni]);
                    mma_f16(acc[mi][ni], al[mi], bh[ni]);
                }
        }
    }

    const float lm = 1.f / (1.f + __expf(-lam_ptr[0]));
    const float be = 1.f - lm;
    const long zZ = (long)z * sZ;
    const int g = lane >> 2, tig = lane & 3;
#pragma unroll
    for (int mi = 0; mi < MI; mi++) {
#pragma unroll
        for (int ni = 0; ni < NI; ni++) {
            int r = row0 + wm + mi * 16 + g;
            int cc = col0 + wn + ni * 8 + tig * 2;
#pragma unroll
            for (int half_ = 0; half_ < 2; half_++) {
                int rr = r + half_ * 8;
                long o = zZ + (long)rr * ldz + cc;
                __half2 ch = *(const __half2*)&Cinh[o];
                __half2 cl = *(const __half2*)&Cinl[o];
                float c0 = __half2float(ch.x) + __half2float(cl.x);
                float c1 = __half2float(ch.y) + __half2float(cl.y);
                float v0 = lm * acc[mi][ni][half_ * 2 + 0] + be * c0;
                float v1 = lm * acc[mi][ni][half_ * 2 + 1] + be * c1;
                __half2 hv, lv;
                hv.x = hf_hi(v0); hv.y = hf_hi(v1);
                lv.x = hf_lo(v0, hv.x); lv.y = hf_lo(v1, hv.y);
                *(__half2*)&Chi[o] = hv;
                *(__half2*)&Clo[o] = lv;
                if (Cf) {
                    float2 f2; f2.x = v0; f2.y = v1;
                    *(float2*)&Cf[o] = f2;
                }
            }
        }
    }
}

// ---------------- conversions ------------------------------------------------
__global__ void split_ew_k(const float* __restrict__ src,
                           __nv_bfloat16* __restrict__ hi, __nv_bfloat16* __restrict__ lo, int n)
{
    int i = blockIdx.x * 256 + threadIdx.x;
    if (i < n) {
        float v = src[i];
        __nv_bfloat16 h = bf_hi(v);
        hi[i] = h; lo[i] = bf_lo(v, h);
    }
}

// W [1024][1024] (k rows, n cols) -> out [n][k] split
__global__ void splitT_w_k(const float* __restrict__ W,
                           __nv_bfloat16* __restrict__ hi, __nv_bfloat16* __restrict__ lo)
{
    __shared__ float t[32][33];
    int k0 = blockIdx.y * 32, n0 = blockIdx.x * 32;
    for (int i = threadIdx.y; i < 32; i += 8)
        t[i][threadIdx.x] = W[(k0 + i) * DMODEL + n0 + threadIdx.x];
    __syncthreads();
    for (int i = threadIdx.y; i < 32; i += 8) {
        float v = t[threadIdx.x][i];
        __nv_bfloat16 h = bf_hi(v);
        long o = (long)(n0 + i) * DMODEL + k0 + threadIdx.x;
        hi[o] = h; lo[o] = bf_lo(v, h);
    }
}

// proj column slice -> per-head [bh][t][d] split (no transpose)
__global__ void split_heads_k(const float* __restrict__ proj, int coloff,
                              __nv_bfloat16* __restrict__ hi, __nv_bfloat16* __restrict__ lo)
{
    int i = blockIdx.x * 256 + threadIdx.x;
    int d = i & 63, t = (i >> 6) & 1023, bh = i >> 16;
    int b = bh >> 4, h = bh & 15;
    float v = proj[((long)(b * SEQT + t)) * 5120 + coloff + h * DHEAD + d];
    __nv_bfloat16 hh = bf_hi(v);
    hi[i] = hh; lo[i] = bf_lo(v, hh);
}

// proj D slice -> fused transposed [bh][rowoff+d][t], fp16 hi/lo
__global__ void split_D16_k(const float* __restrict__ proj, int coloff, int rowoff,
                            __half* __restrict__ hi, __half* __restrict__ lo)
{
    __shared__ float tb[32][33];
    int bh = blockIdx.z, b = bh >> 4, h = bh & 15;
    int t0 = blockIdx.x * 32, d0 = blockIdx.y * 32;
    for (int i = threadIdx.y; i < 32; i += 8)
        tb[i][threadIdx.x] = proj[((long)(b * SEQT + t0 + i)) * 5120 + coloff + h * DHEAD + d0 + threadIdx.x];
    __syncthreads();
    long base = (long)bh * (128 * SEQT);
    for (int i = threadIdx.y; i < 32; i += 8) {
        float v = tb[threadIdx.x][i];
        long o = base + (long)(rowoff + d0 + i) * SEQT + t0 + threadIdx.x;
        __half hh = hf_hi(v);
        hi[o] = hh; lo[o] = hf_lo(v, hh);
    }
}

// ---------------- single-pass softmax over rows of 1024 -> fp16 A ------------
__global__ void softmax_f16_k(const float* __restrict__ S, __half* __restrict__ Af)
{
    const long rb = (long)blockIdx.x * SEQT;
    const int tid = threadIdx.x;
    __shared__ float sh[8];

    float4 v = *(const float4*)(S + rb + tid * 4);

    float m = fmaxf(fmaxf(v.x, v.y), fmaxf(v.z, v.w));
#pragma unroll
    for (int o = 16; o; o >>= 1) m = fmaxf(m, __shfl_xor_sync(0xffffffffu, m, o));
    if ((tid & 31) == 0) sh[tid >> 5] = m;
    __syncthreads();
    if (tid < 8) {
        float mm = sh[tid];
#pragma unroll
        for (int o = 4; o; o >>= 1) mm = fmaxf(mm, __shfl_xor_sync(0xffu, mm, o));
        sh[tid] = mm;
    }
    __syncthreads();
    m = sh[0];
    __syncthreads();

    float e0 = __expf(v.x - m), e1 = __expf(v.y - m);
    float e2 = __expf(v.z - m), e3 = __expf(v.w - m);
    float s = e0 + e1 + e2 + e3;
#pragma unroll
    for (int o = 16; o; o >>= 1) s += __shfl_xor_sync(0xffffffffu, s, o);
    if ((tid & 31) == 0) sh[tid >> 5] = s;
    __syncthreads();
    if (tid < 8) {
        float ss = sh[tid];
#pragma unroll
        for (int o = 4; o; o >>= 1) ss += __shfl_xor_sync(0xffu, ss, o);
        sh[tid] = ss;
    }
    __syncthreads();
    const float inv = 1.f / sh[0];

    __half2 a01, a23;
    a01.x = __float2half(e0 * inv); a01.y = __float2half(e1 * inv);
    a23.x = __float2half(e2 * inv); a23.y = __float2half(e3 * inv);
    *(__half2*)(Af + rb + tid * 4)     = a01;
    *(__half2*)(Af + rb + tid * 4 + 2) = a23;
}

// ---------------- readout on fused transposed D: one warp per (bh,d) row -----
__global__ void readout2_k(const float* __restrict__ F,   // [bh][128][1024], re rows 0-63
                           const float* __restrict__ proj,
                           float* __restrict__ gate,
                           __nv_bfloat16* __restrict__ Ph, __nv_bfloat16* __restrict__ Pl)
{
    int warp = threadIdx.x >> 5, lane = threadIdx.x & 31;
    int gid = blockIdx.x * 8 + warp;
    int bh = gid >> 6, d = gid & 63;
    int b = bh >> 4, h = bh & 15;
    const float* rre = F + (long)bh * (128 * SEQT) + d * SEQT;
    const float* rim = rre + 64 * SEQT;

    float re[32], im[32];
    float sre = 0.f, sim = 0.f;
#pragma unroll
    for (int j = 0; j < 32; j++) {
        re[j] = rre[lane + j * 32]; im[j] = rim[lane + j * 32];
        sre += re[j]; sim += im[j];
    }
#pragma unroll
    for (int o = 16; o; o >>= 1) {
        sre += __shfl_xor_sync(0xffffffffu, sre, o);
        sim += __shfl_xor_sync(0xffffffffu, sim, o);
    }
    float mr = sre * (1.f / SEQT), mi = sim * (1.f / SEQT);
    float mn = sqrtf(mr * mr + mi * mi);

    float cs[32]; float mx = -1e30f;
#pragma unroll
    for (int j = 0; j < 32; j++) {
        float dot = re[j] * mr + im[j] * mi;
        float nrm = sqrtf(re[j] * re[j] + im[j] * im[j]) * mn + 1e-8f;
        cs[j] = dot / nrm;
        mx = fmaxf(mx, cs[j]);
    }
#pragma unroll
    for (int o = 16; o; o >>= 1) mx = fmaxf(mx, __shfl_xor_sync(0xffffffffu, mx, o));
    float s = 0.f;
#pragma unroll
    for (int j = 0; j < 32; j++) { cs[j] = __expf(cs[j] - mx); s += cs[j]; }
#pragma unroll
    for (int o = 16; o; o >>= 1) s += __shfl_xor_sync(0xffffffffu, s, o);
    float inv = 1.f / s;

#pragma unroll
    for (int j = 0; j < 32; j++) {
        int t = lane + j * 32;
        float g = cs[j] * inv;
        gate[(long)bh * (SEQT * DHEAD) + t * DHEAD + d] = g;
        float v = proj[((long)(b * SEQT + t)) * 5120 + 4096 + h * DHEAD + d];
        float pv = g * v;
        __nv_bfloat16 hh = bf_hi(pv);
        long po = ((long)(b * SEQT + t)) * DMODEL + h * DHEAD + d;
        Ph[po] = hh; Pl[po] = bf_lo(pv, hh);
    }
}

// -----------------------------------------------------------------------------
extern "C" void kernel_launch(void* const* d_in, const int* in_sizes, int n_in,
                              void* d_out, int out_size)
{
    const float* x   = (const float*)d_in[0];
    const float* WQ  = (const float*)d_in[1];
    const float* WK  = (const float*)d_in[2];
    const float* Wre = (const float*)d_in[3];
    const float* Wim = (const float*)d_in[4];
    const float* WV  = (const float*)d_in[5];
    const float* WO  = (const float*)d_in[6];
    const float* lam = (const float*)d_in[7];
    float* out = (float*)d_out;

    float *pproj, *pS, *pDT, *pGateScr;
    __nv_bfloat16 *pxh, *pxl, *pW5h, *pW5l, *pWOh, *pWOl;
    __nv_bfloat16 *pQh, *pQl, *pKh, *pKl, *pPh, *pPl;
    __half *pAf, *pDTh, *pDTl;
    cudaGetSymbolAddress((void**)&pproj, g_proj);
    cudaGetSymbolAddress((void**)&pS, g_S);
    cudaGetSymbolAddress((void**)&pDT, g_DT);
    cudaGetSymbolAddress((void**)&pGateScr, g_gate_scratch);
    cudaGetSymbolAddress((void**)&pxh, g_xh);
    cudaGetSymbolAddress((void**)&pxl, g_xl);
    cudaGetSymbolAddress((void**)&pW5h, g_W5h);
    cudaGetSymbolAddress((void**)&pW5l, g_W5l);
    cudaGetSymbolAddress((void**)&pWOh, g_WOh);
    cudaGetSymbolAddress((void**)&pWOl, g_WOl);
    cudaGetSymbolAddress((void**)&pQh, g_Qh);
    cudaGetSymbolAddress((void**)&pQl, g_Ql);
    cudaGetSymbolAddress((void**)&pKh, g_Kh);
    cudaGetSymbolAddress((void**)&pKl, g_Kl);
    cudaGetSymbolAddress((void**)&pAf, g_Af);
    cudaGetSymbolAddress((void**)&pDTh, g_DTh);
    cudaGetSymbolAddress((void**)&pDTl, g_DTl);
    cudaGetSymbolAddress((void**)&pPh, g_Ph);
    cudaGetSymbolAddress((void**)&pPl, g_Pl);

    const long OUT_ELEMS  = (long)BT * DMODEL;
    const long GATE_ELEMS = (long)HEADEL;
    float* gate = (out_size >= (int)(OUT_ELEMS + GATE_ELEMS)) ? (out + OUT_ELEMS) : pGateScr;

    // bf16 GEMM: 3 stages x 4 arrays x 8KB = 96 KB
    const int SMEM  = 3 * (128 * 4 + 128 * 4) * 2 * 16;
    // prop GEMM: 4 stages x 3 arrays x 8KB = 96 KB
    const int SMEMP = 4 * (128 * 4 * 3) * 16;
    cudaFuncSetAttribute(mma_gemm<128,128,64,32,3>, cudaFuncAttributeMaxDynamicSharedMemorySize, SMEM);
    cudaFuncSetAttribute(prop_gemm, cudaFuncAttributeMaxDynamicSharedMemorySize, SMEMP);

    // ---- input splits ----
    split_ew_k<<<(BT * DMODEL + 255) / 256, 256>>>(x, pxh, pxl, BT * DMODEL);
    dim3 tb(32, 8), tg(32, 32);
    const float* Ws[5] = {WQ, WK, Wre, Wim, WV};
    for (int w = 0; w < 5; w++)
        splitT_w_k<<<tg, tb>>>(Ws[w], pW5h + (long)w * DMODEL * DMODEL, pW5l + (long)w * DMODEL * DMODEL);
    splitT_w_k<<<tg, tb>>>(WO, pWOh, pWOl);

    // ---- fused 5-way projection: [4096,5120] = x @ [WQ|WK|Wre|Wim|WV] ----
    mma_gemm<128,128,64,32,3><<<dim3(5120/128, BT/128, 1), 256, SMEM>>>(
        pxh, pxl, 0, DMODEL, pW5h, pW5l, 0, DMODEL,
        pproj, 0, 5120, DMODEL, 1.f);

    // ---- per-head splits of Q, K; fused transposed fp16 split of Dre/Dim ----
    split_heads_k<<<HEADEL / 256, 256>>>(pproj, 0,    pQh, pQl);
    split_heads_k<<<HEADEL / 256, 256>>>(pproj, 1024, pKh, pKl);
    split_D16_k<<<dim3(32, 2, NBH), tb>>>(pproj, 2048, 0,  pDTh, pDTl);
    split_D16_k<<<dim3(32, 2, NBH), tb>>>(pproj, 3072, 64, pDTh, pDTl);

    // ---- scores: S[bh][t][s] = Q @ K^T / 8 ----
    mma_gemm<128,128,64,32,3><<<dim3(8, 8, NBH), 256, SMEM>>>(
        pQh, pQl, (long)SEQT * DHEAD, DHEAD,
        pKh, pKl, (long)SEQT * DHEAD, DHEAD,
        pS, (long)SEQT * SEQT, SEQT, DHEAD, 0.125f);

    // ---- softmax rows -> A fp16 (single pass) ----
    softmax_f16_k<<<NBH * SEQT, 256>>>(pS, pAf);

    // ---- propagation, fp16 2-product: F' = lam*(F @ A^T) + (1-lam)*F ----
    for (int s = 0; s < NSTEPS; s++) {
        long iin = (long)(s & 1) * FEL;
        long iou = (long)(1 - (s & 1)) * FEL;
        prop_gemm<<<dim3(8, 1, NBH), 256, SMEMP>>>(
            pDTh + iin, pDTl + iin, 128L * SEQT, SEQT,
            pAf, (long)SEQT * SEQT, SEQT,
            (s == NSTEPS - 1) ? pDT : nullptr,
            pDTh + iin, pDTl + iin,
            pDTh + iou, pDTl + iou,
            128L * SEQT, SEQT, SEQT, lam);
    }

    // ---- readout + gating (writes gate + P hi/lo) ----
    readout2_k<<<NBH * DHEAD / 8, 256>>>(pDT, pproj, gate, pPh, pPl);

    // ---- out = P @ W_O ----
    mma_gemm<128,128,64,32,3><<<dim3(DMODEL/128, BT/128, 1), 256, SMEM>>>(
        pPh, pPl, 0, DMODEL, pWOh, pWOl, 0, DMODEL,
        out, 0, DMODEL, DMODEL, 1.f);
}

// round 9
// speedup vs baseline: 1.3764x; 1.1185x over previous
#include <cuda_runtime.h>
#include <cuda_bf16.h>
#include <cuda_fp16.h>
#include <math.h>
#include <stdint.h>

// Problem constants
#define BATCH 4
#define SEQT  1024
#define DMODEL 1024
#define NHEAD 16
#define DHEAD 64
#define NBH   (BATCH*NHEAD)      // 64
#define BT    (BATCH*SEQT)       // 4096
#define NSTEPS 3

#define HEADEL (NBH*SEQT*DHEAD)          // 4,194,304
#define FEL    (2L*HEADEL)               // fused re|im D: [bh][128][1024]
#define AEL    ((size_t)NBH*SEQT*SEQT)   // 67,108,864

// ---------------- scratch (device globals; no allocation allowed) ------------
__device__ float g_proj[(size_t)BT*5120];          // packed [Q|K|Dre|Dim|V] fp32
__device__ float g_S[AEL];                         // scores fp32
__device__ float g_DT[FEL];                        // final-step D fp32 for readout
__device__ float g_gate_scratch[HEADEL];

__device__ __half g_xh[BT*DMODEL], g_xl[BT*DMODEL];        // x fp16 hi/lo
__device__ __half g_W5f[5*DMODEL*DMODEL];                  // [n][k] single fp16
__device__ __half g_WOf[DMODEL*DMODEL];                    // [n][k] single fp16
__device__ __half g_Qh[HEADEL], g_Ql[HEADEL];              // Q fp16 hi/lo
__device__ __half g_Kf[HEADEL];                            // K single fp16
__device__ __half g_Af[AEL];                               // adjacency single fp16
__device__ __half g_DTh[2L*FEL], g_DTl[2L*FEL];            // D fp16 hi/lo [pp]
__device__ __half g_Ph[BT*DMODEL], g_Pl[BT*DMODEL];        // P fp16 hi/lo

// ---------------- PTX helpers ------------------------------------------------
__device__ __forceinline__ uint32_t smem_u32(const void* p) {
    return (uint32_t)__cvta_generic_to_shared(p);
}
__device__ __forceinline__ void cp16(uint32_t dst, const void* src) {
    asm volatile("cp.async.cg.shared.global [%0], [%1], 16;\n" :: "r"(dst), "l"(src));
}
__device__ __forceinline__ void cp_commit() { asm volatile("cp.async.commit_group;\n"); }
template<int N> __device__ __forceinline__ void cp_wait() {
    asm volatile("cp.async.wait_group %0;\n" :: "n"(N));
}
__device__ __forceinline__ void ldsm4(uint32_t& r0, uint32_t& r1, uint32_t& r2, uint32_t& r3, uint32_t addr) {
    asm volatile("ldmatrix.sync.aligned.m8n8.x4.shared.b16 {%0,%1,%2,%3}, [%4];\n"
                 : "=r"(r0), "=r"(r1), "=r"(r2), "=r"(r3) : "r"(addr));
}
__device__ __forceinline__ void mma_f16(float* c, const uint32_t* a, const uint32_t* b) {
    asm volatile("mma.sync.aligned.m16n8k16.row.col.f32.f16.f16.f32 "
                 "{%0,%1,%2,%3}, {%4,%5,%6,%7}, {%8,%9}, {%0,%1,%2,%3};\n"
                 : "+f"(c[0]), "+f"(c[1]), "+f"(c[2]), "+f"(c[3])
                 : "r"(a[0]), "r"(a[1]), "r"(a[2]), "r"(a[3]), "r"(b[0]), "r"(b[1]));
}
__device__ __forceinline__ __half hf_hi(float v) { return __float2half(v); }
__device__ __forceinline__ __half hf_lo(float v, __half h) {
    return __float2half(v - __half2float(h));
}

// ---------------- fp16 2-product GEMM ----------------------------------------
// C[m][n] = alpha * sum_k (A[m][k] * B[n][k])
// A given as fp16 hi/lo (22-bit effective), B single fp16.
// products: Ah*B + Al*B, fp32 accum.
// BM=128, BN=128, WM=64, WN=32, BK=32, 4-stage cp.async ring (24 KB/stage).
// smem swizzle: phys_chunk = kchunk ^ ((row>>1)&3)
__global__ __launch_bounds__(256)
void fgemm(const __half* __restrict__ Ahi, const __half* __restrict__ Alo,
           long sA, int lda,
           const __half* __restrict__ Bf, long sB, int ldb,
           float* __restrict__ C, long sC, int ldc,
           int K, float alpha)
{
    constexpr int BM = 128, BN = 128, WM = 64, WN = 32, STAGES = 4;
    constexpr int ACH = BM * 4;
    constexpr int BCH = BN * 4;
    constexpr int MI = WM / 16;   // 4
    constexpr int NI = WN / 8;    // 4
    constexpr int WROWS = BM / WM;

    extern __shared__ uint4 sm[];
    uint4* sAh_ = sm;
    uint4* sAl_ = sAh_ + STAGES * ACH;
    uint4* sBh_ = sAl_ + STAGES * ACH;

    const int z = blockIdx.z;
    const __half* pAh = Ahi + (long)z * sA;
    const __half* pAl = Alo + (long)z * sA;
    const __half* pBh = Bf  + (long)z * sB;

    const int row0 = blockIdx.y * BM;
    const int col0 = blockIdx.x * BN;
    const int tid  = threadIdx.x;
    const int warp = tid >> 5, lane = tid & 31;
    const int wm = (warp % WROWS) * WM;
    const int wn = (warp / WROWS) * WN;

    float acc[MI][NI][4];
#pragma unroll
    for (int i = 0; i < MI; i++)
#pragma unroll
        for (int j = 0; j < NI; j++)
#pragma unroll
            for (int q = 0; q < 4; q++) acc[i][j][q] = 0.f;

    auto load_tile = [&](int st, int kt) {
#pragma unroll
        for (int i = tid; i < ACH; i += 256) {
            int r = i >> 2, c = i & 3;
            int phys = c ^ ((r >> 1) & 3);
            long src = (long)(row0 + r) * lda + kt * 32 + c * 8;
            cp16(smem_u32(&sAh_[st * ACH + r * 4 + phys]), pAh + src);
            cp16(smem_u32(&sAl_[st * ACH + r * 4 + phys]), pAl + src);
        }
#pragma unroll
        for (int i = tid; i < BCH; i += 256) {
            int r = i >> 2, c = i & 3;
            int phys = c ^ ((r >> 1) & 3);
            long src = (long)(col0 + r) * ldb + kt * 32 + c * 8;
            cp16(smem_u32(&sBh_[st * BCH + r * 4 + phys]), pBh + src);
        }
        cp_commit();
    };

    const int KT = K / 32;
#pragma unroll
    for (int i = 0; i < STAGES - 1; i++) {
        if (i < KT) load_tile(i, i);
        else cp_commit();
    }

    for (int kt = 0; kt < KT; kt++) {
        cp_wait<STAGES - 2>();
        __syncthreads();

        {
            int next = kt + STAGES - 1;
            if (next < KT) load_tile(next % STAGES, next);
            else cp_commit();
        }

        const int st = kt % STAGES;
        const uint4* tAh = sAh_ + st * ACH;
        const uint4* tAl = sAl_ + st * ACH;
        const uint4* tBh = sBh_ + st * BCH;
        const int tr = lane & 7;

#pragma unroll
        for (int ks8 = 0; ks8 < 2; ks8++) {
            uint32_t ah[MI][4], al[MI][4];
            const int akc = ks8 * 2 + (lane >> 4);
#pragma unroll
            for (int mi = 0; mi < MI; mi++) {
                int r = wm + mi * 16 + tr + ((lane >> 3) & 1) * 8;
                int off = r * 4 + (akc ^ ((r >> 1) & 3));
                ldsm4(ah[mi][0], ah[mi][1], ah[mi][2], ah[mi][3], smem_u32(tAh + off));
                ldsm4(al[mi][0], al[mi][1], al[mi][2], al[mi][3], smem_u32(tAl + off));
            }
            uint32_t bh[NI][2];
            const int bkc = ks8 * 2 + ((lane >> 3) & 1);
#pragma unroll
            for (int p = 0; p < NI / 2; p++) {
                int r = wn + p * 16 + tr + (lane >> 4) * 8;
                int off = r * 4 + (bkc ^ ((r >> 1) & 3));
                ldsm4(bh[2*p][0], bh[2*p][1], bh[2*p+1][0], bh[2*p+1][1], smem_u32(tBh + off));
            }
#pragma unroll
            for (int mi = 0; mi < MI; mi++)
#pragma unroll
                for (int ni = 0; ni < NI; ni++) {
                    mma_f16(acc[mi][ni], ah[mi], bh[ni]);
                    mma_f16(acc[mi][ni], al[mi], bh[ni]);
                }
        }
    }

    const long zC = (long)z * sC;
    const int g = lane >> 2, tig = lane & 3;
#pragma unroll
    for (int mi = 0; mi < MI; mi++) {
#pragma unroll
        for (int ni = 0; ni < NI; ni++) {
            int r = row0 + wm + mi * 16 + g;
            int cc = col0 + wn + ni * 8 + tig * 2;
#pragma unroll
            for (int half_ = 0; half_ < 2; half_++) {
                int rr = r + half_ * 8;
                float2 f2;
                f2.x = alpha * acc[mi][ni][half_ * 2 + 0];
                f2.y = alpha * acc[mi][ni][half_ * 2 + 1];
                *(float2*)&C[zC + (long)rr * ldc + cc] = f2;
            }
        }
    }
}

// ---------------- fp16 propagation GEMM (R7, proven) -------------------------
// DT'[m][t] = lam * sum_s (DT[m][s]*Aadj[t][s]) + (1-lam)*DT[m][t]
__global__ __launch_bounds__(256)
void prop_gemm(const __half* __restrict__ Ahi, const __half* __restrict__ Alo,
               long sA, int lda,
               const __half* __restrict__ Bh_, long sB, int ldb,
               float* __restrict__ Cf,
               const __half* __restrict__ Cinh, const __half* __restrict__ Cinl,
               __half* __restrict__ Chi, __half* __restrict__ Clo,
               long sZ, int ldz, int K, const float* __restrict__ lam_ptr)
{
    constexpr int BM = 128, BN = 128, WM = 64, WN = 32, STAGES = 4;
    constexpr int ACH = BM * 4;
    constexpr int BCH = BN * 4;
    constexpr int MI = WM / 16;
    constexpr int NI = WN / 8;
    constexpr int WROWS = BM / WM;

    extern __shared__ uint4 sm[];
    uint4* sAh_ = sm;
    uint4* sAl_ = sAh_ + STAGES * ACH;
    uint4* sBh_ = sAl_ + STAGES * ACH;

    const int z = blockIdx.z;
    const __half* pAh = Ahi + (long)z * sA;
    const __half* pAl = Alo + (long)z * sA;
    const __half* pBh = Bh_ + (long)z * sB;

    const int row0 = blockIdx.y * BM;
    const int col0 = blockIdx.x * BN;
    const int tid  = threadIdx.x;
    const int warp = tid >> 5, lane = tid & 31;
    const int wm = (warp % WROWS) * WM;
    const int wn = (warp / WROWS) * WN;

    float acc[MI][NI][4];
#pragma unroll
    for (int i = 0; i < MI; i++)
#pragma unroll
        for (int j = 0; j < NI; j++)
#pragma unroll
            for (int q = 0; q < 4; q++) acc[i][j][q] = 0.f;

    auto load_tile = [&](int st, int kt) {
#pragma unroll
        for (int i = tid; i < ACH; i += 256) {
            int r = i >> 2, c = i & 3;
            int phys = c ^ ((r >> 1) & 3);
            long src = (long)(row0 + r) * lda + kt * 32 + c * 8;
            cp16(smem_u32(&sAh_[st * ACH + r * 4 + phys]), pAh + src);
            cp16(smem_u32(&sAl_[st * ACH + r * 4 + phys]), pAl + src);
        }
#pragma unroll
        for (int i = tid; i < BCH; i += 256) {
            int r = i >> 2, c = i & 3;
            int phys = c ^ ((r >> 1) & 3);
            long src = (long)(col0 + r) * ldb + kt * 32 + c * 8;
            cp16(smem_u32(&sBh_[st * BCH + r * 4 + phys]), pBh + src);
        }
        cp_commit();
    };

    const int KT = K / 32;
#pragma unroll
    for (int i = 0; i < STAGES - 1; i++) {
        if (i < KT) load_tile(i, i);
        else cp_commit();
    }

    for (int kt = 0; kt < KT; kt++) {
        cp_wait<STAGES - 2>();
        __syncthreads();

        {
            int next = kt + STAGES - 1;
            if (next < KT) load_tile(next % STAGES, next);
            else cp_commit();
        }

        const int st = kt % STAGES;
        const uint4* tAh = sAh_ + st * ACH;
        const uint4* tAl = sAl_ + st * ACH;
        const uint4* tBh = sBh_ + st * BCH;
        const int tr = lane & 7;

#pragma unroll
        for (int ks8 = 0; ks8 < 2; ks8++) {
            uint32_t ah[MI][4], al[MI][4];
            const int akc = ks8 * 2 + (lane >> 4);
#pragma unroll
            for (int mi = 0; mi < MI; mi++) {
                int r = wm + mi * 16 + tr + ((lane >> 3) & 1) * 8;
                int off = r * 4 + (akc ^ ((r >> 1) & 3));
                ldsm4(ah[mi][0], ah[mi][1], ah[mi][2], ah[mi][3], smem_u32(tAh + off));
                ldsm4(al[mi][0], al[mi][1], al[mi][2], al[mi][3], smem_u32(tAl + off));
            }
            uint32_t bh[NI][2];
            const int bkc = ks8 * 2 + ((lane >> 3) & 1);
#pragma unroll
            for (int p = 0; p < NI / 2; p++) {
                int r = wn + p * 16 + tr + (lane >> 4) * 8;
                int off = r * 4 + (bkc ^ ((r >> 1) & 3));
                ldsm4(bh[2*p][0], bh[2*p][1], bh[2*p+1][0], bh[2*p+1][1], smem_u32(tBh + off));
            }
#pragma unroll
            for (int mi = 0; mi < MI; mi++)
#pragma unroll
                for (int ni = 0; ni < NI; ni++) {
                    mma_f16(acc[mi][ni], ah[mi], bh[ni]);
                    mma_f16(acc[mi][ni], al[mi], bh[ni]);
                }
        }
    }

    const float lm = 1.f / (1.f + __expf(-lam_ptr[0]));
    const float be = 1.f - lm;
    const long zZ = (long)z * sZ;
    const int g = lane >> 2, tig = lane & 3;
#pragma unroll
    for (int mi = 0; mi < MI; mi++) {
#pragma unroll
        for (int ni = 0; ni < NI; ni++) {
            int r = row0 + wm + mi * 16 + g;
            int cc = col0 + wn + ni * 8 + tig * 2;
#pragma unroll
            for (int half_ = 0; half_ < 2; half_++) {
                int rr = r + half_ * 8;
                long o = zZ + (long)rr * ldz + cc;
                __half2 ch = *(const __half2*)&Cinh[o];
                __half2 cl = *(const __half2*)&Cinl[o];
                float c0 = __half2float(ch.x) + __half2float(cl.x);
                float c1 = __half2float(ch.y) + __half2float(cl.y);
                float v0 = lm * acc[mi][ni][half_ * 2 + 0] + be * c0;
                float v1 = lm * acc[mi][ni][half_ * 2 + 1] + be * c1;
                __half2 hv, lv;
                hv.x = hf_hi(v0); hv.y = hf_hi(v1);
                lv.x = hf_lo(v0, hv.x); lv.y = hf_lo(v1, hv.y);
                *(__half2*)&Chi[o] = hv;
                *(__half2*)&Clo[o] = lv;
                if (Cf) {
                    float2 f2; f2.x = v0; f2.y = v1;
                    *(float2*)&Cf[o] = f2;
                }
            }
        }
    }
}

// ---------------- conversions ------------------------------------------------
// x fp32 -> fp16 hi/lo
__global__ void split_x_k(const float* __restrict__ src,
                          __half* __restrict__ hi, __half* __restrict__ lo, int n)
{
    int i = blockIdx.x * 256 + threadIdx.x;
    if (i < n) {
        float v = src[i];
        __half h = hf_hi(v);
        hi[i] = h; lo[i] = hf_lo(v, h);
    }
}

// 6 weight matrices [k][n] -> [n][k] single fp16, z selects matrix
__global__ void splitT_w_all(const float* __restrict__ W0, const float* __restrict__ W1,
                             const float* __restrict__ W2, const float* __restrict__ W3,
                             const float* __restrict__ W4, const float* __restrict__ W5,
                             __half* __restrict__ W5f, __half* __restrict__ WOf)
{
    __shared__ float t[32][33];
    int zz = blockIdx.z;
    const float* W = (zz == 0) ? W0 : (zz == 1) ? W1 : (zz == 2) ? W2
                   : (zz == 3) ? W3 : (zz == 4) ? W4 : W5;
    __half* dst = (zz < 5) ? (W5f + (long)zz * DMODEL * DMODEL) : WOf;
    int k0 = blockIdx.y * 32, n0 = blockIdx.x * 32;
    for (int i = threadIdx.y; i < 32; i += 8)
        t[i][threadIdx.x] = W[(k0 + i) * DMODEL + n0 + threadIdx.x];
    __syncthreads();
    for (int i = threadIdx.y; i < 32; i += 8)
        dst[(long)(n0 + i) * DMODEL + k0 + threadIdx.x] = __float2half(t[threadIdx.x][i]);
}

// Q (hi/lo) and K (single) per-head split; blockIdx.y: 0=Q, 1=K
__global__ void split_QK_k(const float* __restrict__ proj,
                           __half* __restrict__ Qh, __half* __restrict__ Ql,
                           __half* __restrict__ Kf)
{
    int i = blockIdx.x * 256 + threadIdx.x;
    int d = i & 63, t = (i >> 6) & 1023, bh = i >> 16;
    int b = bh >> 4, h = bh & 15;
    int coloff = blockIdx.y * 1024;
    float v = proj[((long)(b * SEQT + t)) * 5120 + coloff + h * DHEAD + d];
    if (blockIdx.y == 0) {
        __half hh = hf_hi(v);
        Qh[i] = hh; Ql[i] = hf_lo(v, hh);
    } else {
        Kf[i] = __float2half(v);
    }
}

// proj D slice -> fused transposed [bh][rowoff+d][t], fp16 hi/lo; z = 2*NBH
__global__ void split_D16_k(const float* __restrict__ proj,
                            __half* __restrict__ hi, __half* __restrict__ lo)
{
    __shared__ float tb[32][33];
    int zz = blockIdx.z;
    int bh = zz >> 1, half_ = zz & 1;
    int coloff = 2048 + half_ * 1024, rowoff = half_ * 64;
    int b = bh >> 4, h = bh & 15;
    int t0 = blockIdx.x * 32, d0 = blockIdx.y * 32;
    for (int i = threadIdx.y; i < 32; i += 8)
        tb[i][threadIdx.x] = proj[((long)(b * SEQT + t0 + i)) * 5120 + coloff + h * DHEAD + d0 + threadIdx.x];
    __syncthreads();
    long base = (long)bh * (128 * SEQT);
    for (int i = threadIdx.y; i < 32; i += 8) {
        float v = tb[threadIdx.x][i];
        long o = base + (long)(rowoff + d0 + i) * SEQT + t0 + threadIdx.x;
        __half hh = hf_hi(v);
        hi[o] = hh; lo[o] = hf_lo(v, hh);
    }
}

// ---------------- single-pass softmax over rows of 1024 -> fp16 A ------------
__global__ void softmax_f16_k(const float* __restrict__ S, __half* __restrict__ Af)
{
    const long rb = (long)blockIdx.x * SEQT;
    const int tid = threadIdx.x;
    __shared__ float sh[8];

    float4 v = *(const float4*)(S + rb + tid * 4);

    float m = fmaxf(fmaxf(v.x, v.y), fmaxf(v.z, v.w));
#pragma unroll
    for (int o = 16; o; o >>= 1) m = fmaxf(m, __shfl_xor_sync(0xffffffffu, m, o));
    if ((tid & 31) == 0) sh[tid >> 5] = m;
    __syncthreads();
    if (tid < 8) {
        float mm = sh[tid];
#pragma unroll
        for (int o = 4; o; o >>= 1) mm = fmaxf(mm, __shfl_xor_sync(0xffu, mm, o));
        sh[tid] = mm;
    }
    __syncthreads();
    m = sh[0];
    __syncthreads();

    float e0 = __expf(v.x - m), e1 = __expf(v.y - m);
    float e2 = __expf(v.z - m), e3 = __expf(v.w - m);
    float s = e0 + e1 + e2 + e3;
#pragma unroll
    for (int o = 16; o; o >>= 1) s += __shfl_xor_sync(0xffffffffu, s, o);
    if ((tid & 31) == 0) sh[tid >> 5] = s;
    __syncthreads();
    if (tid < 8) {
        float ss = sh[tid];
#pragma unroll
        for (int o = 4; o; o >>= 1) ss += __shfl_xor_sync(0xffu, ss, o);
        sh[tid] = ss;
    }
    __syncthreads();
    const float inv = 1.f / sh[0];

    __half2 a01, a23;
    a01.x = __float2half(e0 * inv); a01.y = __float2half(e1 * inv);
    a23.x = __float2half(e2 * inv); a23.y = __float2half(e3 * inv);
    *(__half2*)(Af + rb + tid * 4)     = a01;
    *(__half2*)(Af + rb + tid * 4 + 2) = a23;
}

// ---------------- readout on fused transposed D: one warp per (bh,d) row -----
__global__ void readout2_k(const float* __restrict__ F,   // [bh][128][1024], re rows 0-63
                           const float* __restrict__ proj,
                           float* __restrict__ gate,
                           __half* __restrict__ Ph, __half* __restrict__ Pl)
{
    int warp = threadIdx.x >> 5, lane = threadIdx.x & 31;
    int gid = blockIdx.x * 8 + warp;
    int bh = gid >> 6, d = gid & 63;
    int b = bh >> 4, h = bh & 15;
    const float* rre = F + (long)bh * (128 * SEQT) + d * SEQT;
    const float* rim = rre + 64 * SEQT;

    float re[32], im[32];
    float sre = 0.f, sim = 0.f;
#pragma unroll
    for (int j = 0; j < 32; j++) {
        re[j] = rre[lane + j * 32]; im[j] = rim[lane + j * 32];
        sre += re[j]; sim += im[j];
    }
#pragma unroll
    for (int o = 16; o; o >>= 1) {
        sre += __shfl_xor_sync(0xffffffffu, sre, o);
        sim += __shfl_xor_sync(0xffffffffu, sim, o);
    }
    float mr = sre * (1.f / SEQT), mi = sim * (1.f / SEQT);
    float mn = sqrtf(mr * mr + mi * mi);

    float cs[32]; float mx = -1e30f;
#pragma unroll
    for (int j = 0; j < 32; j++) {
        float dot = re[j] * mr + im[j] * mi;
        float nrm = sqrtf(re[j] * re[j] + im[j] * im[j]) * mn + 1e-8f;
        cs[j] = dot / nrm;
        mx = fmaxf(mx, cs[j]);
    }
#pragma unroll
    for (int o = 16; o; o >>= 1) mx = fmaxf(mx, __shfl_xor_sync(0xffffffffu, mx, o));
    float s = 0.f;
#pragma unroll
    for (int j = 0; j < 32; j++) { cs[j] = __expf(cs[j] - mx); s += cs[j]; }
#pragma unroll
    for (int o = 16; o; o >>= 1) s += __shfl_xor_sync(0xffffffffu, s, o);
    float inv = 1.f / s;

#pragma unroll
    for (int j = 0; j < 32; j++) {
        int t = lane + j * 32;
        float g = cs[j] * inv;
        gate[(long)bh * (SEQT * DHEAD) + t * DHEAD + d] = g;
        float v = proj[((long)(b * SEQT + t)) * 5120 + 4096 + h * DHEAD + d];
        float pv = g * v;
        __half hh = hf_hi(pv);
        long po = ((long)(b * SEQT + t)) * DMODEL + h * DHEAD + d;
        Ph[po] = hh; Pl[po] = hf_lo(pv, hh);
    }
}

// -----------------------------------------------------------------------------
extern "C" void kernel_launch(void* const* d_in, const int* in_sizes, int n_in,
                              void* d_out, int out_size)
{
    const float* x   = (const float*)d_in[0];
    const float* WQ  = (const float*)d_in[1];
    const float* WK  = (const float*)d_in[2];
    const float* Wre = (const float*)d_in[3];
    const float* Wim = (const float*)d_in[4];
    const float* WV  = (const float*)d_in[5];
    const float* WO  = (const float*)d_in[6];
    const float* lam = (const float*)d_in[7];
    float* out = (float*)d_out;

    float *pproj, *pS, *pDT, *pGateScr;
    __half *pxh, *pxl, *pW5f, *pWOf, *pQh, *pQl, *pKf, *pAf, *pDTh, *pDTl, *pPh, *pPl;
    cudaGetSymbolAddress((void**)&pproj, g_proj);
    cudaGetSymbolAddress((void**)&pS, g_S);
    cudaGetSymbolAddress((void**)&pDT, g_DT);
    cudaGetSymbolAddress((void**)&pGateScr, g_gate_scratch);
    cudaGetSymbolAddress((void**)&pxh, g_xh);
    cudaGetSymbolAddress((void**)&pxl, g_xl);
    cudaGetSymbolAddress((void**)&pW5f, g_W5f);
    cudaGetSymbolAddress((void**)&pWOf, g_WOf);
    cudaGetSymbolAddress((void**)&pQh, g_Qh);
    cudaGetSymbolAddress((void**)&pQl, g_Ql);
    cudaGetSymbolAddress((void**)&pKf, g_Kf);
    cudaGetSymbolAddress((void**)&pAf, g_Af);
    cudaGetSymbolAddress((void**)&pDTh, g_DTh);
    cudaGetSymbolAddress((void**)&pDTl, g_DTl);
    cudaGetSymbolAddress((void**)&pPh, g_Ph);
    cudaGetSymbolAddress((void**)&pPl, g_Pl);

    const long OUT_ELEMS  = (long)BT * DMODEL;
    const long GATE_ELEMS = (long)HEADEL;
    float* gate = (out_size >= (int)(OUT_ELEMS + GATE_ELEMS)) ? (out + OUT_ELEMS) : pGateScr;

    // 4 stages x 3 arrays x 8 KB = 96 KB (2 CTA/SM)
    const int SMEM = 4 * (128 * 4 * 3) * 16;
    cudaFuncSetAttribute(fgemm,     cudaFuncAttributeMaxDynamicSharedMemorySize, SMEM);
    cudaFuncSetAttribute(prop_gemm, cudaFuncAttributeMaxDynamicSharedMemorySize, SMEM);

    // launch 1: x -> fp16 hi/lo
    split_x_k<<<(BT * DMODEL + 255) / 256, 256>>>(x, pxh, pxl, BT * DMODEL);
    // launch 2: all 6 weights -> [n][k] fp16 single
    splitT_w_all<<<dim3(32, 32, 6), dim3(32, 8)>>>(WQ, WK, Wre, Wim, WV, WO, pW5f, pWOf);

    // launch 3: fused 5-way projection [4096,5120] = x @ [WQ|WK|Wre|Wim|WV]
    fgemm<<<dim3(5120 / 128, BT / 128, 1), 256, SMEM>>>(
        pxh, pxl, 0, DMODEL, pW5f, 0, DMODEL,
        pproj, 0, 5120, DMODEL, 1.f);

    // launch 4: Q (hi/lo) + K (single) per-head splits
    split_QK_k<<<dim3(HEADEL / 256, 2), 256>>>(pproj, pQh, pQl, pKf);
    // launch 5: D fused transposed fp16 hi/lo
    split_D16_k<<<dim3(32, 2, 2 * NBH), dim3(32, 8)>>>(pproj, pDTh, pDTl);

    // launch 6 (ncu -s 5 -c 1 captures this): scores = Q @ K^T / 8
    fgemm<<<dim3(8, 8, NBH), 256, SMEM>>>(
        pQh, pQl, (long)SEQT * DHEAD, DHEAD,
        pKf, (long)SEQT * DHEAD, DHEAD,
        pS, (long)SEQT * SEQT, SEQT, DHEAD, 0.125f);

    // softmax rows -> A fp16 (single pass)
    softmax_f16_k<<<NBH * SEQT, 256>>>(pS, pAf);

    // propagation, fp16 2-product: F' = lam*(F @ A^T) + (1-lam)*F
    for (int s = 0; s < NSTEPS; s++) {
        long iin = (long)(s & 1) * FEL;
        long iou = (long)(1 - (s & 1)) * FEL;
        prop_gemm<<<dim3(8, 1, NBH), 256, SMEM>>>(
            pDTh + iin, pDTl + iin, 128L * SEQT, SEQT,
            pAf, (long)SEQT * SEQT, SEQT,
            (s == NSTEPS - 1) ? pDT : nullptr,
            pDTh + iin, pDTl + iin,
            pDTh + iou, pDTl + iou,
            128L * SEQT, SEQT, SEQT, lam);
    }

    // readout + gating (writes gate + P fp16 hi/lo)
    readout2_k<<<NBH * DHEAD / 8, 256>>>(pDT, pproj, gate, pPh, pPl);

    // out = P @ W_O
    fgemm<<<dim3(DMODEL / 128, BT / 128, 1), 256, SMEM>>>(
        pPh, pPl, 0, DMODEL, pWOf, 0, DMODEL,
        out, 0, DMODEL, DMODEL, 1.f);
}

// round 12
// speedup vs baseline: 1.4817x; 1.0765x over previous
#include <cuda_runtime.h>
#include <cuda_bf16.h>
#include <cuda_fp16.h>
#include <math.h>
#include <stdint.h>

// Problem constants
#define BATCH 4
#define SEQT  1024
#define DMODEL 1024
#define NHEAD 16
#define DHEAD 64
#define NBH   (BATCH*NHEAD)      // 64
#define BT    (BATCH*SEQT)       // 4096
#define NSTEPS 3

#define HEADEL (NBH*SEQT*DHEAD)          // 4,194,304
#define FEL    (2L*HEADEL)               // fused re|im D: [bh][128][1024]
#define AEL    ((size_t)NBH*SEQT*SEQT)   // 67,108,864

// ---------------- scratch (device globals; no allocation allowed) ------------
// proj layout: packed columns [Q | K | V | re | im]
__device__ float g_proj[(size_t)BT*5120];
__device__ float g_DT[FEL];                        // final-step D fp32 for readout
__device__ float g_gate_scratch[HEADEL];

__device__ __half g_xh[BT*DMODEL], g_xl[BT*DMODEL];        // x fp16 hi/lo
__device__ __half g_Wqkv[3*DMODEL*DMODEL];                 // [n][k] single fp16
__device__ __half g_Wri_h[2*DMODEL*DMODEL], g_Wri_l[2*DMODEL*DMODEL]; // re/im hi/lo
__device__ __half g_WOf[DMODEL*DMODEL];                    // [n][k] single fp16
__device__ __half g_Qh[HEADEL], g_Ql[HEADEL];              // Q fp16 hi/lo
__device__ __half g_Kf[HEADEL];                            // K single fp16
__device__ __half g_Sh[AEL];                               // scores fp16
__device__ __half g_Af[AEL];                               // adjacency single fp16
__device__ __half g_DTh[2L*FEL], g_DTl[2L*FEL];            // D fp16 hi/lo [pp]
__device__ __half g_Ph[BT*DMODEL], g_Pl[BT*DMODEL];        // P fp16 hi/lo

// ---------------- PTX helpers ------------------------------------------------
__device__ __forceinline__ uint32_t smem_u32(const void* p) {
    return (uint32_t)__cvta_generic_to_shared(p);
}
__device__ __forceinline__ void cp16(uint32_t dst, const void* src) {
    asm volatile("cp.async.cg.shared.global [%0], [%1], 16;\n" :: "r"(dst), "l"(src));
}
__device__ __forceinline__ void cp_commit() { asm volatile("cp.async.commit_group;\n"); }
template<int N> __device__ __forceinline__ void cp_wait() {
    asm volatile("cp.async.wait_group %0;\n" :: "n"(N));
}
__device__ __forceinline__ void ldsm4(uint32_t& r0, uint32_t& r1, uint32_t& r2, uint32_t& r3, uint32_t addr) {
    asm volatile("ldmatrix.sync.aligned.m8n8.x4.shared.b16 {%0,%1,%2,%3}, [%4];\n"
                 : "=r"(r0), "=r"(r1), "=r"(r2), "=r"(r3) : "r"(addr));
}
__device__ __forceinline__ void mma_f16(float* c, const uint32_t* a, const uint32_t* b) {
    asm volatile("mma.sync.aligned.m16n8k16.row.col.f32.f16.f16.f32 "
                 "{%0,%1,%2,%3}, {%4,%5,%6,%7}, {%8,%9}, {%0,%1,%2,%3};\n"
                 : "+f"(c[0]), "+f"(c[1]), "+f"(c[2]), "+f"(c[3])
                 : "r"(a[0]), "r"(a[1]), "r"(a[2]), "r"(a[3]), "r"(b[0]), "r"(b[1]));
}
__device__ __forceinline__ __half hf_hi(float v) { return __float2half(v); }
__device__ __forceinline__ __half hf_lo(float v, __half h) {
    return __float2half(v - __half2float(h));
}

// ---------------- fp16 GEMM --------------------------------------------------
// C[m][n] = alpha * sum_k (A[m][k] * B[n][k])
// A always fp16 hi/lo. NPROD==2: B single (Ah*B + Al*B).
// NPROD==3: B hi/lo (Ah*Bh + Al*Bh + Ah*Bl) — ~22-bit effective both sides.
// OUTF16: write __half C16 instead of float C.
// BM=128, BN=128, WM=64, WN=32, BK=32.
template<int NPROD, int OUTF16>
__global__ __launch_bounds__(256)
void fgemm(const __half* __restrict__ Ahi, const __half* __restrict__ Alo,
           long sA, int lda,
           const __half* __restrict__ Bh_, const __half* __restrict__ Bl_,
           long sB, int ldb,
           float* __restrict__ C, __half* __restrict__ C16, long sC, int ldc,
           int K, float alpha)
{
    constexpr int BM = 128, BN = 128, WM = 64, WN = 32;
    constexpr int STAGES = (NPROD == 3) ? 3 : 4;
    constexpr int ACH = BM * 4;
    constexpr int BCH = BN * 4;
    constexpr int MI = WM / 16;   // 4
    constexpr int NI = WN / 8;    // 4
    constexpr int WROWS = BM / WM;

    extern __shared__ uint4 sm[];
    uint4* sAh_ = sm;
    uint4* sAl_ = sAh_ + STAGES * ACH;
    uint4* sBh_ = sAl_ + STAGES * ACH;
    uint4* sBl_ = sBh_ + STAGES * BCH;   // only used for NPROD==3

    const int z = blockIdx.z;
    const __half* pAh = Ahi + (long)z * sA;
    const __half* pAl = Alo + (long)z * sA;
    const __half* pBh = Bh_ + (long)z * sB;
    const __half* pBl = (NPROD == 3) ? (Bl_ + (long)z * sB) : nullptr;

    const int row0 = blockIdx.y * BM;
    const int col0 = blockIdx.x * BN;
    const int tid  = threadIdx.x;
    const int warp = tid >> 5, lane = tid & 31;
    const int wm = (warp % WROWS) * WM;
    const int wn = (warp / WROWS) * WN;

    float acc[MI][NI][4];
#pragma unroll
    for (int i = 0; i < MI; i++)
#pragma unroll
        for (int j = 0; j < NI; j++)
#pragma unroll
            for (int q = 0; q < 4; q++) acc[i][j][q] = 0.f;

    auto load_tile = [&](int st, int kt) {
#pragma unroll
        for (int i = tid; i < ACH; i += 256) {
            int r = i >> 2, c = i & 3;
            int phys = c ^ ((r >> 1) & 3);
            long src = (long)(row0 + r) * lda + kt * 32 + c * 8;
            cp16(smem_u32(&sAh_[st * ACH + r * 4 + phys]), pAh + src);
            cp16(smem_u32(&sAl_[st * ACH + r * 4 + phys]), pAl + src);
        }
#pragma unroll
        for (int i = tid; i < BCH; i += 256) {
            int r = i >> 2, c = i & 3;
            int phys = c ^ ((r >> 1) & 3);
            long src = (long)(col0 + r) * ldb + kt * 32 + c * 8;
            cp16(smem_u32(&sBh_[st * BCH + r * 4 + phys]), pBh + src);
            if (NPROD == 3)
                cp16(smem_u32(&sBl_[st * BCH + r * 4 + phys]), pBl + src);
        }
        cp_commit();
    };

    const int KT = K / 32;
#pragma unroll
    for (int i = 0; i < STAGES - 1; i++) {
        if (i < KT) load_tile(i, i);
        else cp_commit();
    }

    for (int kt = 0; kt < KT; kt++) {
        cp_wait<STAGES - 2>();
        __syncthreads();

        {
            int next = kt + STAGES - 1;
            if (next < KT) load_tile(next % STAGES, next);
            else cp_commit();
        }

        const int st = kt % STAGES;
        const uint4* tAh = sAh_ + st * ACH;
        const uint4* tAl = sAl_ + st * ACH;
        const uint4* tBh = sBh_ + st * BCH;
        const uint4* tBl = sBl_ + st * BCH;
        const int tr = lane & 7;

#pragma unroll
        for (int ks8 = 0; ks8 < 2; ks8++) {
            uint32_t ah[MI][4], al[MI][4];
            const int akc = ks8 * 2 + (lane >> 4);
#pragma unroll
            for (int mi = 0; mi < MI; mi++) {
                int r = wm + mi * 16 + tr + ((lane >> 3) & 1) * 8;
                int off = r * 4 + (akc ^ ((r >> 1) & 3));
                ldsm4(ah[mi][0], ah[mi][1], ah[mi][2], ah[mi][3], smem_u32(tAh + off));
                ldsm4(al[mi][0], al[mi][1], al[mi][2], al[mi][3], smem_u32(tAl + off));
            }
            uint32_t bh[NI][2], bl[NI][2];
            const int bkc = ks8 * 2 + ((lane >> 3) & 1);
#pragma unroll
            for (int p = 0; p < NI / 2; p++) {
                int r = wn + p * 16 + tr + (lane >> 4) * 8;
                int off = r * 4 + (bkc ^ ((r >> 1) & 3));
                ldsm4(bh[2*p][0], bh[2*p][1], bh[2*p+1][0], bh[2*p+1][1], smem_u32(tBh + off));
                if (NPROD == 3)
                    ldsm4(bl[2*p][0], bl[2*p][1], bl[2*p+1][0], bl[2*p+1][1], smem_u32(tBl + off));
            }
#pragma unroll
            for (int mi = 0; mi < MI; mi++)
#pragma unroll
                for (int ni = 0; ni < NI; ni++) {
                    mma_f16(acc[mi][ni], ah[mi], bh[ni]);
                    mma_f16(acc[mi][ni], al[mi], bh[ni]);
                    if (NPROD == 3) mma_f16(acc[mi][ni], ah[mi], bl[ni]);
                }
        }
    }

    const long zC = (long)z * sC;
    const int g = lane >> 2, tig = lane & 3;
#pragma unroll
    for (int mi = 0; mi < MI; mi++) {
#pragma unroll
        for (int ni = 0; ni < NI; ni++) {
            int r = row0 + wm + mi * 16 + g;
            int cc = col0 + wn + ni * 8 + tig * 2;
#pragma unroll
            for (int half_ = 0; half_ < 2; half_++) {
                int rr = r + half_ * 8;
                float v0 = alpha * acc[mi][ni][half_ * 2 + 0];
                float v1 = alpha * acc[mi][ni][half_ * 2 + 1];
                long o = zC + (long)rr * ldc + cc;
                if (OUTF16) {
                    __half2 hv; hv.x = __float2half(v0); hv.y = __float2half(v1);
                    *(__half2*)&C16[o] = hv;
                } else {
                    float2 f2; f2.x = v0; f2.y = v1;
                    *(float2*)&C[o] = f2;
                }
            }
        }
    }
}

// ---------------- fp16 propagation GEMM (single-product mma) ------------------
// DT'[m][t] = lam * sum_s (DThi[m][s]*Aadj[t][s]) + (1-lam)*(DThi+DTlo)[m][t]
// mma uses D-hi only; the carry path reconstructs exact D from hi+lo.
__global__ __launch_bounds__(256)
void prop_gemm(const __half* __restrict__ Ahi,
               long sA, int lda,
               const __half* __restrict__ Bh_, long sB, int ldb,
               float* __restrict__ Cf,
               const __half* __restrict__ Cinh, const __half* __restrict__ Cinl,
               __half* __restrict__ Chi, __half* __restrict__ Clo,
               long sZ, int ldz, int K, const float* __restrict__ lam_ptr)
{
    constexpr int BM = 128, BN = 128, WM = 64, WN = 32, STAGES = 4;
    constexpr int ACH = BM * 4;
    constexpr int BCH = BN * 4;
    constexpr int MI = WM / 16;
    constexpr int NI = WN / 8;
    constexpr int WROWS = BM / WM;

    extern __shared__ uint4 sm[];
    uint4* sAh_ = sm;
    uint4* sBh_ = sAh_ + STAGES * ACH;

    const int z = blockIdx.z;
    const __half* pAh = Ahi + (long)z * sA;
    const __half* pBh = Bh_ + (long)z * sB;

    const int row0 = blockIdx.y * BM;
    const int col0 = blockIdx.x * BN;
    const int tid  = threadIdx.x;
    const int warp = tid >> 5, lane = tid & 31;
    const int wm = (warp % WROWS) * WM;
    const int wn = (warp / WROWS) * WN;

    float acc[MI][NI][4];
#pragma unroll
    for (int i = 0; i < MI; i++)
#pragma unroll
        for (int j = 0; j < NI; j++)
#pragma unroll
            for (int q = 0; q < 4; q++) acc[i][j][q] = 0.f;

    auto load_tile = [&](int st, int kt) {
#pragma unroll
        for (int i = tid; i < ACH; i += 256) {
            int r = i >> 2, c = i & 3;
            int phys = c ^ ((r >> 1) & 3);
            long src = (long)(row0 + r) * lda + kt * 32 + c * 8;
            cp16(smem_u32(&sAh_[st * ACH + r * 4 + phys]), pAh + src);
        }
#pragma unroll
        for (int i = tid; i < BCH; i += 256) {
            int r = i >> 2, c = i & 3;
            int phys = c ^ ((r >> 1) & 3);
            long src = (long)(col0 + r) * ldb + kt * 32 + c * 8;
            cp16(smem_u32(&sBh_[st * BCH + r * 4 + phys]), pBh + src);
        }
        cp_commit();
    };

    const int KT = K / 32;
#pragma unroll
    for (int i = 0; i < STAGES - 1; i++) {
        if (i < KT) load_tile(i, i);
        else cp_commit();
    }

    for (int kt = 0; kt < KT; kt++) {
        cp_wait<STAGES - 2>();
        __syncthreads();

        {
            int next = kt + STAGES - 1;
            if (next < KT) load_tile(next % STAGES, next);
            else cp_commit();
        }

        const int st = kt % STAGES;
        const uint4* tAh = sAh_ + st * ACH;
        const uint4* tBh = sBh_ + st * BCH;
        const int tr = lane & 7;

#pragma unroll
        for (int ks8 = 0; ks8 < 2; ks8++) {
            uint32_t ah[MI][4];
            const int akc = ks8 * 2 + (lane >> 4);
#pragma unroll
            for (int mi = 0; mi < MI; mi++) {
                int r = wm + mi * 16 + tr + ((lane >> 3) & 1) * 8;
                int off = r * 4 + (akc ^ ((r >> 1) & 3));
                ldsm4(ah[mi][0], ah[mi][1], ah[mi][2], ah[mi][3], smem_u32(tAh + off));
            }
            uint32_t bh[NI][2];
            const int bkc = ks8 * 2 + ((lane >> 3) & 1);
#pragma unroll
            for (int p = 0; p < NI / 2; p++) {
                int r = wn + p * 16 + tr + (lane >> 4) * 8;
                int off = r * 4 + (bkc ^ ((r >> 1) & 3));
                ldsm4(bh[2*p][0], bh[2*p][1], bh[2*p+1][0], bh[2*p+1][1], smem_u32(tBh + off));
            }
#pragma unroll
            for (int mi = 0; mi < MI; mi++)
#pragma unroll
                for (int ni = 0; ni < NI; ni++)
                    mma_f16(acc[mi][ni], ah[mi], bh[ni]);
        }
    }

    const float lm = 1.f / (1.f + __expf(-lam_ptr[0]));
    const float be = 1.f - lm;
    const long zZ = (long)z * sZ;
    const int g = lane >> 2, tig = lane & 3;
#pragma unroll
    for (int mi = 0; mi < MI; mi++) {
#pragma unroll
        for (int ni = 0; ni < NI; ni++) {
            int r = row0 + wm + mi * 16 + g;
            int cc = col0 + wn + ni * 8 + tig * 2;
#pragma unroll
            for (int half_ = 0; half_ < 2; half_++) {
                int rr = r + half_ * 8;
                long o = zZ + (long)rr * ldz + cc;
                __half2 ch = *(const __half2*)&Cinh[o];
                __half2 cl = *(const __half2*)&Cinl[o];
                float c0 = __half2float(ch.x) + __half2float(cl.x);
                float c1 = __half2float(ch.y) + __half2float(cl.y);
                float v0 = lm * acc[mi][ni][half_ * 2 + 0] + be * c0;
                float v1 = lm * acc[mi][ni][half_ * 2 + 1] + be * c1;
                __half2 hv, lv;
                hv.x = hf_hi(v0); hv.y = hf_hi(v1);
                lv.x = hf_lo(v0, hv.x); lv.y = hf_lo(v1, hv.y);
                *(__half2*)&Chi[o] = hv;
                *(__half2*)&Clo[o] = lv;
                if (Cf) {
                    float2 f2; f2.x = v0; f2.y = v1;
                    *(float2*)&Cf[o] = f2;
                }
            }
        }
    }
}

// ---------------- conversions ------------------------------------------------
__global__ void split_x_k(const float* __restrict__ src,
                          __half* __restrict__ hi, __half* __restrict__ lo, int n)
{
    int i = blockIdx.x * 256 + threadIdx.x;
    if (i < n) {
        float v = src[i];
        __half h = hf_hi(v);
        hi[i] = h; lo[i] = hf_lo(v, h);
    }
}

// 6 weights [k][n] -> [n][k]; zz 0-2 -> Wqkv single (expects WQ, WK, WV!);
// zz 3-4 -> Wri hi/lo (Wre, Wim); zz 5 -> WO single.
__global__ void splitT_w_all(const float* __restrict__ W0, const float* __restrict__ W1,
                             const float* __restrict__ W2, const float* __restrict__ W3,
                             const float* __restrict__ W4, const float* __restrict__ W5,
                             __half* __restrict__ Wqkv,
                             __half* __restrict__ Wri_h, __half* __restrict__ Wri_l,
                             __half* __restrict__ WOf)
{
    __shared__ float t[32][33];
    int zz = blockIdx.z;
    const float* W = (zz == 0) ? W0 : (zz == 1) ? W1 : (zz == 2) ? W2
                   : (zz == 3) ? W3 : (zz == 4) ? W4 : W5;
    int k0 = blockIdx.y * 32, n0 = blockIdx.x * 32;
    for (int i = threadIdx.y; i < 32; i += 8)
        t[i][threadIdx.x] = W[(k0 + i) * DMODEL + n0 + threadIdx.x];
    __syncthreads();
    for (int i = threadIdx.y; i < 32; i += 8) {
        float v = t[threadIdx.x][i];
        long o = (long)(n0 + i) * DMODEL + k0 + threadIdx.x;
        if (zz < 3) {
            Wqkv[(long)zz * DMODEL * DMODEL + o] = __float2half(v);
        } else if (zz < 5) {
            __half h = hf_hi(v);
            Wri_h[(long)(zz - 3) * DMODEL * DMODEL + o] = h;
            Wri_l[(long)(zz - 3) * DMODEL * DMODEL + o] = hf_lo(v, h);
        } else {
            WOf[o] = __float2half(v);
        }
    }
}

// Q (hi/lo) and K (single) per-head split; blockIdx.y: 0=Q, 1=K
__global__ void split_QK_k(const float* __restrict__ proj,
                           __half* __restrict__ Qh, __half* __restrict__ Ql,
                           __half* __restrict__ Kf)
{
    int i = blockIdx.x * 256 + threadIdx.x;
    int d = i & 63, t = (i >> 6) & 1023, bh = i >> 16;
    int b = bh >> 4, h = bh & 15;
    int coloff = blockIdx.y * 1024;
    float v = proj[((long)(b * SEQT + t)) * 5120 + coloff + h * DHEAD + d];
    if (blockIdx.y == 0) {
        __half hh = hf_hi(v);
        Qh[i] = hh; Ql[i] = hf_lo(v, hh);
    } else {
        Kf[i] = __float2half(v);
    }
}

// proj re/im slice (cols 3072..5119) -> fused transposed [bh][rowoff+d][t] fp16 hi/lo
__global__ void split_D16_k(const float* __restrict__ proj,
                            __half* __restrict__ hi, __half* __restrict__ lo)
{
    __shared__ float tb[32][33];
    int zz = blockIdx.z;
    int bh = zz >> 1, half_ = zz & 1;
    int coloff = 3072 + half_ * 1024, rowoff = half_ * 64;
    int b = bh >> 4, h = bh & 15;
    int t0 = blockIdx.x * 32, d0 = blockIdx.y * 32;
    for (int i = threadIdx.y; i < 32; i += 8)
        tb[i][threadIdx.x] = proj[((long)(b * SEQT + t0 + i)) * 5120 + coloff + h * DHEAD + d0 + threadIdx.x];
    __syncthreads();
    long base = (long)bh * (128 * SEQT);
    for (int i = threadIdx.y; i < 32; i += 8) {
        float v = tb[threadIdx.x][i];
        long o = base + (long)(rowoff + d0 + i) * SEQT + t0 + threadIdx.x;
        __half hh = hf_hi(v);
        hi[o] = hh; lo[o] = hf_lo(v, hh);
    }
}

// ---------------- single-pass softmax over fp16 rows of 1024 -> fp16 A -------
__global__ void softmax_f16_k(const __half* __restrict__ S, __half* __restrict__ Af)
{
    const long rb = (long)blockIdx.x * SEQT;
    const int tid = threadIdx.x;
    __shared__ float sh[8];

    __half2 h01 = *(const __half2*)(S + rb + tid * 4);
    __half2 h23 = *(const __half2*)(S + rb + tid * 4 + 2);
    float v0 = __half2float(h01.x), v1 = __half2float(h01.y);
    float v2 = __half2float(h23.x), v3 = __half2float(h23.y);

    float m = fmaxf(fmaxf(v0, v1), fmaxf(v2, v3));
#pragma unroll
    for (int o = 16; o; o >>= 1) m = fmaxf(m, __shfl_xor_sync(0xffffffffu, m, o));
    if ((tid & 31) == 0) sh[tid >> 5] = m;
    __syncthreads();
    if (tid < 8) {
        float mm = sh[tid];
#pragma unroll
        for (int o = 4; o; o >>= 1) mm = fmaxf(mm, __shfl_xor_sync(0xffu, mm, o));
        sh[tid] = mm;
    }
    __syncthreads();
    m = sh[0];
    __syncthreads();

    float e0 = __expf(v0 - m), e1 = __expf(v1 - m);
    float e2 = __expf(v2 - m), e3 = __expf(v3 - m);
    float s = e0 + e1 + e2 + e3;
#pragma unroll
    for (int o = 16; o; o >>= 1) s += __shfl_xor_sync(0xffffffffu, s, o);
    if ((tid & 31) == 0) sh[tid >> 5] = s;
    __syncthreads();
    if (tid < 8) {
        float ss = sh[tid];
#pragma unroll
        for (int o = 4; o; o >>= 1) ss += __shfl_xor_sync(0xffu, ss, o);
        sh[tid] = ss;
    }
    __syncthreads();
    const float inv = 1.f / sh[0];

    __half2 a01, a23;
    a01.x = __float2half(e0 * inv); a01.y = __float2half(e1 * inv);
    a23.x = __float2half(e2 * inv); a23.y = __float2half(e3 * inv);
    *(__half2*)(Af + rb + tid * 4)     = a01;
    *(__half2*)(Af + rb + tid * 4 + 2) = a23;
}

// ---------------- readout on fused transposed D: one warp per (bh,d) row -----
__global__ void readout2_k(const float* __restrict__ F,   // [bh][128][1024], re rows 0-63
                           const float* __restrict__ proj,
                           float* __restrict__ gate,
                           __half* __restrict__ Ph, __half* __restrict__ Pl)
{
    int warp = threadIdx.x >> 5, lane = threadIdx.x & 31;
    int gid = blockIdx.x * 8 + warp;
    int bh = gid >> 6, d = gid & 63;
    int b = bh >> 4, h = bh & 15;
    const float* rre = F + (long)bh * (128 * SEQT) + d * SEQT;
    const float* rim = rre + 64 * SEQT;

    float re[32], im[32];
    float sre = 0.f, sim = 0.f;
#pragma unroll
    for (int j = 0; j < 32; j++) {
        re[j] = rre[lane + j * 32]; im[j] = rim[lane + j * 32];
        sre += re[j]; sim += im[j];
    }
#pragma unroll
    for (int o = 16; o; o >>= 1) {
        sre += __shfl_xor_sync(0xffffffffu, sre, o);
        sim += __shfl_xor_sync(0xffffffffu, sim, o);
    }
    float mr = sre * (1.f / SEQT), mi = sim * (1.f / SEQT);
    float mn = sqrtf(mr * mr + mi * mi);

    float cs[32]; float mx = -1e30f;
#pragma unroll
    for (int j = 0; j < 32; j++) {
        float dot = re[j] * mr + im[j] * mi;
        float nrm = sqrtf(re[j] * re[j] + im[j] * im[j]) * mn + 1e-8f;
        cs[j] = dot / nrm;
        mx = fmaxf(mx, cs[j]);
    }
#pragma unroll
    for (int o = 16; o; o >>= 1) mx = fmaxf(mx, __shfl_xor_sync(0xffffffffu, mx, o));
    float s = 0.f;
#pragma unroll
    for (int j = 0; j < 32; j++) { cs[j] = __expf(cs[j] - mx); s += cs[j]; }
#pragma unroll
    for (int o = 16; o; o >>= 1) s += __shfl_xor_sync(0xffffffffu, s, o);
    float inv = 1.f / s;

#pragma unroll
    for (int j = 0; j < 32; j++) {
        int t = lane + j * 32;
        float g = cs[j] * inv;
        gate[(long)bh * (SEQT * DHEAD) + t * DHEAD + d] = g;
        // V lives at proj cols [2048, 3072)
        float v = proj[((long)(b * SEQT + t)) * 5120 + 2048 + h * DHEAD + d];
        float pv = g * v;
        __half hh = hf_hi(pv);
        long po = ((long)(b * SEQT + t)) * DMODEL + h * DHEAD + d;
        Ph[po] = hh; Pl[po] = hf_lo(pv, hh);
    }
}

// -----------------------------------------------------------------------------
extern "C" void kernel_launch(void* const* d_in, const int* in_sizes, int n_in,
                              void* d_out, int out_size)
{
    const float* x   = (const float*)d_in[0];
    const float* WQ  = (const float*)d_in[1];
    const float* WK  = (const float*)d_in[2];
    const float* Wre = (const float*)d_in[3];
    const float* Wim = (const float*)d_in[4];
    const float* WV  = (const float*)d_in[5];
    const float* WO  = (const float*)d_in[6];
    const float* lam = (const float*)d_in[7];
    float* out = (float*)d_out;

    float *pproj, *pDT, *pGateScr;
    __half *pxh, *pxl, *pWqkv, *pWrih, *pWril, *pWOf;
    __half *pQh, *pQl, *pKf, *pSh, *pAf, *pDTh, *pDTl, *pPh, *pPl;
    cudaGetSymbolAddress((void**)&pproj, g_proj);
    cudaGetSymbolAddress((void**)&pDT, g_DT);
    cudaGetSymbolAddress((void**)&pGateScr, g_gate_scratch);
    cudaGetSymbolAddress((void**)&pxh, g_xh);
    cudaGetSymbolAddress((void**)&pxl, g_xl);
    cudaGetSymbolAddress((void**)&pWqkv, g_Wqkv);
    cudaGetSymbolAddress((void**)&pWrih, g_Wri_h);
    cudaGetSymbolAddress((void**)&pWril, g_Wri_l);
    cudaGetSymbolAddress((void**)&pWOf, g_WOf);
    cudaGetSymbolAddress((void**)&pQh, g_Qh);
    cudaGetSymbolAddress((void**)&pQl, g_Ql);
    cudaGetSymbolAddress((void**)&pKf, g_Kf);
    cudaGetSymbolAddress((void**)&pSh, g_Sh);
    cudaGetSymbolAddress((void**)&pAf, g_Af);
    cudaGetSymbolAddress((void**)&pDTh, g_DTh);
    cudaGetSymbolAddress((void**)&pDTl, g_DTl);
    cudaGetSymbolAddress((void**)&pPh, g_Ph);
    cudaGetSymbolAddress((void**)&pPl, g_Pl);

    const long OUT_ELEMS  = (long)BT * DMODEL;
    const long GATE_ELEMS = (long)HEADEL;
    float* gate = (out_size >= (int)(OUT_ELEMS + GATE_ELEMS)) ? (out + OUT_ELEMS) : pGateScr;

    const int SMEM2 = 4 * (128 * 4 * 3) * 16;   // NPROD=2: 4 stages x 3 arrays = 96 KB
    const int SMEM3 = 3 * (128 * 4 * 4) * 16;   // NPROD=3: 3 stages x 4 arrays = 96 KB
    const int SMEMP = 4 * (128 * 4 * 2) * 16;   // prop: 4 stages x 2 arrays = 64 KB
    cudaFuncSetAttribute(fgemm<2,0>, cudaFuncAttributeMaxDynamicSharedMemorySize, SMEM2);
    cudaFuncSetAttribute(fgemm<2,1>, cudaFuncAttributeMaxDynamicSharedMemorySize, SMEM2);
    cudaFuncSetAttribute(fgemm<3,0>, cudaFuncAttributeMaxDynamicSharedMemorySize, SMEM3);
    cudaFuncSetAttribute(prop_gemm,  cudaFuncAttributeMaxDynamicSharedMemorySize, SMEMP);

    // x -> fp16 hi/lo; weights -> transposed fp16 (re/im hi/lo)
    split_x_k<<<(BT * DMODEL + 255) / 256, 256>>>(x, pxh, pxl, BT * DMODEL);
    // FIX (R10 bug): argument order must match kernel's zz mapping:
    // zz0-2 = Wqkv = {WQ, WK, WV};  zz3-4 = {Wre, Wim};  zz5 = WO.
    splitT_w_all<<<dim3(32, 32, 6), dim3(32, 8)>>>(WQ, WK, WV, Wre, Wim, WO,
                                                   pWqkv, pWrih, pWril, pWOf);

    // proj part A: cols [0,3072) = x @ [WQ|WK|WV], 2-product
    fgemm<2,0><<<dim3(3072 / 128, BT / 128, 1), 256, SMEM2>>>(
        pxh, pxl, 0, DMODEL, pWqkv, nullptr, 0, DMODEL,
        pproj, nullptr, 0, 5120, DMODEL, 1.f);
    // proj part B: cols [3072,5120) = x @ [Wre|Wim], 3-product (gate-critical path)
    fgemm<3,0><<<dim3(2048 / 128, BT / 128, 1), 256, SMEM3>>>(
        pxh, pxl, 0, DMODEL, pWrih, pWril, 0, DMODEL,
        pproj + 3072, nullptr, 0, 5120, DMODEL, 1.f);

    // per-head splits
    split_QK_k<<<dim3(HEADEL / 256, 2), 256>>>(pproj, pQh, pQl, pKf);
    split_D16_k<<<dim3(32, 2, 2 * NBH), dim3(32, 8)>>>(pproj, pDTh, pDTl);

    // scores = Q @ K^T / 8, fp16 output
    fgemm<2,1><<<dim3(8, 8, NBH), 256, SMEM2>>>(
        pQh, pQl, (long)SEQT * DHEAD, DHEAD,
        pKf, nullptr, (long)SEQT * DHEAD, DHEAD,
        nullptr, pSh, (long)SEQT * SEQT, SEQT, DHEAD, 0.125f);

    // softmax rows -> A fp16
    softmax_f16_k<<<NBH * SEQT, 256>>>(pSh, pAf);

    // propagation: single-product mma on D-hi, exact hi+lo carry
    for (int s = 0; s < NSTEPS; s++) {
        long iin = (long)(s & 1) * FEL;
        long iou = (long)(1 - (s & 1)) * FEL;
        prop_gemm<<<dim3(8, 1, NBH), 256, SMEMP>>>(
            pDTh + iin, 128L * SEQT, SEQT,
            pAf, (long)SEQT * SEQT, SEQT,
            (s == NSTEPS - 1) ? pDT : nullptr,
            pDTh + iin, pDTl + iin,
            pDTh + iou, pDTl + iou,
            128L * SEQT, SEQT, SEQT, lam);
    }

    // readout + gating (writes gate + P fp16 hi/lo)
    readout2_k<<<NBH * DHEAD / 8, 256>>>(pDT, pproj, gate, pPh, pPl);

    // out = P @ W_O
    fgemm<2,0><<<dim3(DMODEL / 128, BT / 128, 1), 256, SMEM2>>>(
        pPh, pPl, 0, DMODEL, pWOf, nullptr, 0, DMODEL,
        out, nullptr, 0, DMODEL, DMODEL, 1.f);
}

// round 13
// speedup vs baseline: 1.6583x; 1.1192x over previous
#include <cuda_runtime.h>
#include <cuda_bf16.h>
#include <cuda_fp16.h>
#include <math.h>
#include <stdint.h>

// Problem constants
#define BATCH 4
#define SEQT  1024
#define DMODEL 1024
#define NHEAD 16
#define DHEAD 64
#define NBH   (BATCH*NHEAD)      // 64
#define BT    (BATCH*SEQT)       // 4096
#define NSTEPS 3

#define HEADEL (NBH*SEQT*DHEAD)          // 4,194,304
#define FEL    (2L*HEADEL)               // fused re|im D: [bh][128][1024]
#define AEL    ((size_t)NBH*SEQT*SEQT)   // 67,108,864

// ---------------- scratch (device globals; no allocation allowed) ------------
__device__ float g_Dri[(size_t)BT*2048];           // compact [b*T+t][re|im] fp32
__device__ float g_DT[FEL];                        // final-step D fp32 for readout
__device__ float g_gate_scratch[HEADEL];
__device__ float g_Vc[HEADEL];                     // V compact per-head [bh][t][d] fp32
__device__ float4 g_stats[NBH*DHEAD];              // per-(bh,d): {mr, mi, cmax, csum}

__device__ __half g_xh[BT*DMODEL], g_xl[BT*DMODEL];        // x fp16 hi/lo
__device__ __half g_Wqkv[3*DMODEL*DMODEL];                 // [n][k] single fp16
__device__ __half g_Wri_h[2*DMODEL*DMODEL], g_Wri_l[2*DMODEL*DMODEL]; // re/im hi/lo
__device__ __half g_WOf[DMODEL*DMODEL];                    // [n][k] single fp16
__device__ __half g_Qh[HEADEL], g_Ql[HEADEL];              // Q fp16 hi/lo
__device__ __half g_Kf[HEADEL];                            // K single fp16
__device__ __half g_Sh[AEL];                               // scores fp16
__device__ __half g_Af[AEL];                               // adjacency single fp16
__device__ __half g_DTh[2L*FEL], g_DTl[2L*FEL];            // D fp16 hi/lo [pp]
__device__ __half g_Ph[BT*DMODEL], g_Pl[BT*DMODEL];        // P fp16 hi/lo

// ---------------- PTX helpers ------------------------------------------------
__device__ __forceinline__ uint32_t smem_u32(const void* p) {
    return (uint32_t)__cvta_generic_to_shared(p);
}
__device__ __forceinline__ void cp16(uint32_t dst, const void* src) {
    asm volatile("cp.async.cg.shared.global [%0], [%1], 16;\n" :: "r"(dst), "l"(src));
}
__device__ __forceinline__ void cp_commit() { asm volatile("cp.async.commit_group;\n"); }
template<int N> __device__ __forceinline__ void cp_wait() {
    asm volatile("cp.async.wait_group %0;\n" :: "n"(N));
}
__device__ __forceinline__ void ldsm4(uint32_t& r0, uint32_t& r1, uint32_t& r2, uint32_t& r3, uint32_t addr) {
    asm volatile("ldmatrix.sync.aligned.m8n8.x4.shared.b16 {%0,%1,%2,%3}, [%4];\n"
                 : "=r"(r0), "=r"(r1), "=r"(r2), "=r"(r3) : "r"(addr));
}
__device__ __forceinline__ void mma_f16(float* c, const uint32_t* a, const uint32_t* b) {
    asm volatile("mma.sync.aligned.m16n8k16.row.col.f32.f16.f16.f32 "
                 "{%0,%1,%2,%3}, {%4,%5,%6,%7}, {%8,%9}, {%0,%1,%2,%3};\n"
                 : "+f"(c[0]), "+f"(c[1]), "+f"(c[2]), "+f"(c[3])
                 : "r"(a[0]), "r"(a[1]), "r"(a[2]), "r"(a[3]), "r"(b[0]), "r"(b[1]));
}
__device__ __forceinline__ __half hf_hi(float v) { return __float2half(v); }
__device__ __forceinline__ __half hf_lo(float v, __half h) {
    return __float2half(v - __half2float(h));
}

// ---------------- fp16 GEMM --------------------------------------------------
// C[m][n] = alpha * sum_k (A[m][k] * B[n][k])
// A always fp16 hi/lo. NPROD==2: B single (Ah*B + Al*B).
// NPROD==3: B hi/lo (Ah*Bh + Al*Bh + Ah*Bl).
// OUT: 0 = fp32 C; 1 = fp16 C16; 2 = fused QKV per-head split
//      (col0<1024 -> Q hi/lo, <2048 -> K single, else -> V fp32 compact).
// BM=128, BN=128, WM=64, WN=32, BK=32.
template<int NPROD, int OUT>
__global__ __launch_bounds__(256)
void fgemm(const __half* __restrict__ Ahi, const __half* __restrict__ Alo,
           long sA, int lda,
           const __half* __restrict__ Bh_, const __half* __restrict__ Bl_,
           long sB, int ldb,
           float* __restrict__ C, __half* __restrict__ C16, long sC, int ldc,
           int K, float alpha,
           __half* __restrict__ qh, __half* __restrict__ ql,
           __half* __restrict__ kf, float* __restrict__ vc)
{
    constexpr int BM = 128, BN = 128, WM = 64, WN = 32;
    constexpr int STAGES = (NPROD == 3) ? 3 : 4;
    constexpr int ACH = BM * 4;
    constexpr int BCH = BN * 4;
    constexpr int MI = WM / 16;   // 4
    constexpr int NI = WN / 8;    // 4
    constexpr int WROWS = BM / WM;

    extern __shared__ uint4 sm[];
    uint4* sAh_ = sm;
    uint4* sAl_ = sAh_ + STAGES * ACH;
    uint4* sBh_ = sAl_ + STAGES * ACH;
    uint4* sBl_ = sBh_ + STAGES * BCH;   // only used for NPROD==3

    const int z = blockIdx.z;
    const __half* pAh = Ahi + (long)z * sA;
    const __half* pAl = Alo + (long)z * sA;
    const __half* pBh = Bh_ + (long)z * sB;
    const __half* pBl = (NPROD == 3) ? (Bl_ + (long)z * sB) : nullptr;

    const int row0 = blockIdx.y * BM;
    const int col0 = blockIdx.x * BN;
    const int tid  = threadIdx.x;
    const int warp = tid >> 5, lane = tid & 31;
    const int wm = (warp % WROWS) * WM;
    const int wn = (warp / WROWS) * WN;

    float acc[MI][NI][4];
#pragma unroll
    for (int i = 0; i < MI; i++)
#pragma unroll
        for (int j = 0; j < NI; j++)
#pragma unroll
            for (int q = 0; q < 4; q++) acc[i][j][q] = 0.f;

    auto load_tile = [&](int st, int kt) {
#pragma unroll
        for (int i = tid; i < ACH; i += 256) {
            int r = i >> 2, c = i & 3;
            int phys = c ^ ((r >> 1) & 3);
            long src = (long)(row0 + r) * lda + kt * 32 + c * 8;
            cp16(smem_u32(&sAh_[st * ACH + r * 4 + phys]), pAh + src);
            cp16(smem_u32(&sAl_[st * ACH + r * 4 + phys]), pAl + src);
        }
#pragma unroll
        for (int i = tid; i < BCH; i += 256) {
            int r = i >> 2, c = i & 3;
            int phys = c ^ ((r >> 1) & 3);
            long src = (long)(col0 + r) * ldb + kt * 32 + c * 8;
            cp16(smem_u32(&sBh_[st * BCH + r * 4 + phys]), pBh + src);
            if (NPROD == 3)
                cp16(smem_u32(&sBl_[st * BCH + r * 4 + phys]), pBl + src);
        }
        cp_commit();
    };

    const int KT = K / 32;
#pragma unroll
    for (int i = 0; i < STAGES - 1; i++) {
        if (i < KT) load_tile(i, i);
        else cp_commit();
    }

    for (int kt = 0; kt < KT; kt++) {
        cp_wait<STAGES - 2>();
        __syncthreads();

        {
            int next = kt + STAGES - 1;
            if (next < KT) load_tile(next % STAGES, next);
            else cp_commit();
        }

        const int st = kt % STAGES;
        const uint4* tAh = sAh_ + st * ACH;
        const uint4* tAl = sAl_ + st * ACH;
        const uint4* tBh = sBh_ + st * BCH;
        const uint4* tBl = sBl_ + st * BCH;
        const int tr = lane & 7;

#pragma unroll
        for (int ks8 = 0; ks8 < 2; ks8++) {
            uint32_t ah[MI][4], al[MI][4];
            const int akc = ks8 * 2 + (lane >> 4);
#pragma unroll
            for (int mi = 0; mi < MI; mi++) {
                int r = wm + mi * 16 + tr + ((lane >> 3) & 1) * 8;
                int off = r * 4 + (akc ^ ((r >> 1) & 3));
                ldsm4(ah[mi][0], ah[mi][1], ah[mi][2], ah[mi][3], smem_u32(tAh + off));
                ldsm4(al[mi][0], al[mi][1], al[mi][2], al[mi][3], smem_u32(tAl + off));
            }
            uint32_t bh[NI][2], bl[NI][2];
            const int bkc = ks8 * 2 + ((lane >> 3) & 1);
#pragma unroll
            for (int p = 0; p < NI / 2; p++) {
                int r = wn + p * 16 + tr + (lane >> 4) * 8;
                int off = r * 4 + (bkc ^ ((r >> 1) & 3));
                ldsm4(bh[2*p][0], bh[2*p][1], bh[2*p+1][0], bh[2*p+1][1], smem_u32(tBh + off));
                if (NPROD == 3)
                    ldsm4(bl[2*p][0], bl[2*p][1], bl[2*p+1][0], bl[2*p+1][1], smem_u32(tBl + off));
            }
#pragma unroll
            for (int mi = 0; mi < MI; mi++)
#pragma unroll
                for (int ni = 0; ni < NI; ni++) {
                    mma_f16(acc[mi][ni], ah[mi], bh[ni]);
                    mma_f16(acc[mi][ni], al[mi], bh[ni]);
                    if (NPROD == 3) mma_f16(acc[mi][ni], ah[mi], bl[ni]);
                }
        }
    }

    const long zC = (long)z * sC;
    const int g = lane >> 2, tig = lane & 3;
#pragma unroll
    for (int mi = 0; mi < MI; mi++) {
#pragma unroll
        for (int ni = 0; ni < NI; ni++) {
#pragma unroll
            for (int half_ = 0; half_ < 2; half_++) {
                int rr = row0 + wm + mi * 16 + g + half_ * 8;
                int cc = col0 + wn + ni * 8 + tig * 2;
                float v0 = alpha * acc[mi][ni][half_ * 2 + 0];
                float v1 = alpha * acc[mi][ni][half_ * 2 + 1];
                if (OUT == 0) {
                    float2 f2; f2.x = v0; f2.y = v1;
                    *(float2*)&C[zC + (long)rr * ldc + cc] = f2;
                } else if (OUT == 1) {
                    __half2 hv; hv.x = __float2half(v0); hv.y = __float2half(v1);
                    *(__half2*)&C16[zC + (long)rr * ldc + cc] = hv;
                } else {
                    int b = rr >> 10, t = rr & 1023;
                    int lc = cc & 1023, h = lc >> 6, d = lc & 63;
                    long o = ((long)((b << 4) | h) * SEQT + t) * DHEAD + d;
                    if (col0 < 1024) {          // Q hi/lo
                        __half2 hv, lv;
                        hv.x = hf_hi(v0); hv.y = hf_hi(v1);
                        lv.x = hf_lo(v0, hv.x); lv.y = hf_lo(v1, hv.y);
                        *(__half2*)&qh[o] = hv;
                        *(__half2*)&ql[o] = lv;
                    } else if (col0 < 2048) {   // K single
                        __half2 hv; hv.x = __float2half(v0); hv.y = __float2half(v1);
                        *(__half2*)&kf[o] = hv;
                    } else {                    // V fp32 compact
                        float2 f2; f2.x = v0; f2.y = v1;
                        *(float2*)&vc[o] = f2;
                    }
                }
            }
        }
    }
}

// ---------------- fp16 propagation GEMM (single-product mma) ------------------
// DT'[m][t] = lam * sum_s (DThi[m][s]*Aadj[t][s]) + (1-lam)*(DThi+DTlo)[m][t]
__global__ __launch_bounds__(256)
void prop_gemm(const __half* __restrict__ Ahi,
               long sA, int lda,
               const __half* __restrict__ Bh_, long sB, int ldb,
               float* __restrict__ Cf,
               const __half* __restrict__ Cinh, const __half* __restrict__ Cinl,
               __half* __restrict__ Chi, __half* __restrict__ Clo,
               long sZ, int ldz, int K, const float* __restrict__ lam_ptr)
{
    constexpr int BM = 128, BN = 128, WM = 64, WN = 32, STAGES = 4;
    constexpr int ACH = BM * 4;
    constexpr int BCH = BN * 4;
    constexpr int MI = WM / 16;
    constexpr int NI = WN / 8;
    constexpr int WROWS = BM / WM;

    extern __shared__ uint4 sm[];
    uint4* sAh_ = sm;
    uint4* sBh_ = sAh_ + STAGES * ACH;

    const int z = blockIdx.z;
    const __half* pAh = Ahi + (long)z * sA;
    const __half* pBh = Bh_ + (long)z * sB;

    const int row0 = blockIdx.y * BM;
    const int col0 = blockIdx.x * BN;
    const int tid  = threadIdx.x;
    const int warp = tid >> 5, lane = tid & 31;
    const int wm = (warp % WROWS) * WM;
    const int wn = (warp / WROWS) * WN;

    float acc[MI][NI][4];
#pragma unroll
    for (int i = 0; i < MI; i++)
#pragma unroll
        for (int j = 0; j < NI; j++)
#pragma unroll
            for (int q = 0; q < 4; q++) acc[i][j][q] = 0.f;

    auto load_tile = [&](int st, int kt) {
#pragma unroll
        for (int i = tid; i < ACH; i += 256) {
            int r = i >> 2, c = i & 3;
            int phys = c ^ ((r >> 1) & 3);
            long src = (long)(row0 + r) * lda + kt * 32 + c * 8;
            cp16(smem_u32(&sAh_[st * ACH + r * 4 + phys]), pAh + src);
        }
#pragma unroll
        for (int i = tid; i < BCH; i += 256) {
            int r = i >> 2, c = i & 3;
            int phys = c ^ ((r >> 1) & 3);
            long src = (long)(col0 + r) * ldb + kt * 32 + c * 8;
            cp16(smem_u32(&sBh_[st * BCH + r * 4 + phys]), pBh + src);
        }
        cp_commit();
    };

    const int KT = K / 32;
#pragma unroll
    for (int i = 0; i < STAGES - 1; i++) {
        if (i < KT) load_tile(i, i);
        else cp_commit();
    }

    for (int kt = 0; kt < KT; kt++) {
        cp_wait<STAGES - 2>();
        __syncthreads();

        {
            int next = kt + STAGES - 1;
            if (next < KT) load_tile(next % STAGES, next);
            else cp_commit();
        }

        const int st = kt % STAGES;
        const uint4* tAh = sAh_ + st * ACH;
        const uint4* tBh = sBh_ + st * BCH;
        const int tr = lane & 7;

#pragma unroll
        for (int ks8 = 0; ks8 < 2; ks8++) {
            uint32_t ah[MI][4];
            const int akc = ks8 * 2 + (lane >> 4);
#pragma unroll
            for (int mi = 0; mi < MI; mi++) {
                int r = wm + mi * 16 + tr + ((lane >> 3) & 1) * 8;
                int off = r * 4 + (akc ^ ((r >> 1) & 3));
                ldsm4(ah[mi][0], ah[mi][1], ah[mi][2], ah[mi][3], smem_u32(tAh + off));
            }
            uint32_t bh[NI][2];
            const int bkc = ks8 * 2 + ((lane >> 3) & 1);
#pragma unroll
            for (int p = 0; p < NI / 2; p++) {
                int r = wn + p * 16 + tr + (lane >> 4) * 8;
                int off = r * 4 + (bkc ^ ((r >> 1) & 3));
                ldsm4(bh[2*p][0], bh[2*p][1], bh[2*p+1][0], bh[2*p+1][1], smem_u32(tBh + off));
            }
#pragma unroll
            for (int mi = 0; mi < MI; mi++)
#pragma unroll
                for (int ni = 0; ni < NI; ni++)
                    mma_f16(acc[mi][ni], ah[mi], bh[ni]);
        }
    }

    const float lm = 1.f / (1.f + __expf(-lam_ptr[0]));
    const float be = 1.f - lm;
    const long zZ = (long)z * sZ;
    const int g = lane >> 2, tig = lane & 3;
#pragma unroll
    for (int mi = 0; mi < MI; mi++) {
#pragma unroll
        for (int ni = 0; ni < NI; ni++) {
            int r = row0 + wm + mi * 16 + g;
            int cc = col0 + wn + ni * 8 + tig * 2;
#pragma unroll
            for (int half_ = 0; half_ < 2; half_++) {
                int rr = r + half_ * 8;
                long o = zZ + (long)rr * ldz + cc;
                __half2 ch = *(const __half2*)&Cinh[o];
                __half2 cl = *(const __half2*)&Cinl[o];
                float c0 = __half2float(ch.x) + __half2float(cl.x);
                float c1 = __half2float(ch.y) + __half2float(cl.y);
                float v0 = lm * acc[mi][ni][half_ * 2 + 0] + be * c0;
                float v1 = lm * acc[mi][ni][half_ * 2 + 1] + be * c1;
                __half2 hv, lv;
                hv.x = hf_hi(v0); hv.y = hf_hi(v1);
                lv.x = hf_lo(v0, hv.x); lv.y = hf_lo(v1, hv.y);
                *(__half2*)&Chi[o] = hv;
                *(__half2*)&Clo[o] = lv;
                if (Cf) {
                    float2 f2; f2.x = v0; f2.y = v1;
                    *(float2*)&Cf[o] = f2;
                }
            }
        }
    }
}

// ---------------- conversions ------------------------------------------------
__global__ void split_x_k(const float* __restrict__ src,
                          __half* __restrict__ hi, __half* __restrict__ lo, int n)
{
    int i = blockIdx.x * 256 + threadIdx.x;
    if (i < n) {
        float v = src[i];
        __half h = hf_hi(v);
        hi[i] = h; lo[i] = hf_lo(v, h);
    }
}

// 6 weights [k][n] -> [n][k]; zz 0-2 -> Wqkv single (WQ, WK, WV);
// zz 3-4 -> Wri hi/lo (Wre, Wim); zz 5 -> WO single.
__global__ void splitT_w_all(const float* __restrict__ W0, const float* __restrict__ W1,
                             const float* __restrict__ W2, const float* __restrict__ W3,
                             const float* __restrict__ W4, const float* __restrict__ W5,
                             __half* __restrict__ Wqkv,
                             __half* __restrict__ Wri_h, __half* __restrict__ Wri_l,
                             __half* __restrict__ WOf)
{
    __shared__ float t[32][33];
    int zz = blockIdx.z;
    const float* W = (zz == 0) ? W0 : (zz == 1) ? W1 : (zz == 2) ? W2
                   : (zz == 3) ? W3 : (zz == 4) ? W4 : W5;
    int k0 = blockIdx.y * 32, n0 = blockIdx.x * 32;
    for (int i = threadIdx.y; i < 32; i += 8)
        t[i][threadIdx.x] = W[(k0 + i) * DMODEL + n0 + threadIdx.x];
    __syncthreads();
    for (int i = threadIdx.y; i < 32; i += 8) {
        float v = t[threadIdx.x][i];
        long o = (long)(n0 + i) * DMODEL + k0 + threadIdx.x;
        if (zz < 3) {
            Wqkv[(long)zz * DMODEL * DMODEL + o] = __float2half(v);
        } else if (zz < 5) {
            __half h = hf_hi(v);
            Wri_h[(long)(zz - 3) * DMODEL * DMODEL + o] = h;
            Wri_l[(long)(zz - 3) * DMODEL * DMODEL + o] = hf_lo(v, h);
        } else {
            WOf[o] = __float2half(v);
        }
    }
}

// compact Dri [b*T+t][2048] -> fused transposed [bh][rowoff+d][t] fp16 hi/lo
__global__ void split_D16_k(const float* __restrict__ Dri,
                            __half* __restrict__ hi, __half* __restrict__ lo)
{
    __shared__ float tb[32][33];
    int zz = blockIdx.z;
    int bh = zz >> 1, half_ = zz & 1;
    int coloff = half_ * 1024, rowoff = half_ * 64;
    int b = bh >> 4, h = bh & 15;
    int t0 = blockIdx.x * 32, d0 = blockIdx.y * 32;
    for (int i = threadIdx.y; i < 32; i += 8)
        tb[i][threadIdx.x] = Dri[((long)(b * SEQT + t0 + i)) * 2048 + coloff + h * DHEAD + d0 + threadIdx.x];
    __syncthreads();
    long base = (long)bh * (128 * SEQT);
    for (int i = threadIdx.y; i < 32; i += 8) {
        float v = tb[threadIdx.x][i];
        long o = base + (long)(rowoff + d0 + i) * SEQT + t0 + threadIdx.x;
        __half hh = hf_hi(v);
        hi[o] = hh; lo[o] = hf_lo(v, hh);
    }
}

// ---------------- single-pass softmax over fp16 rows of 1024 -> fp16 A -------
__global__ void softmax_f16_k(const __half* __restrict__ S, __half* __restrict__ Af)
{
    const long rb = (long)blockIdx.x * SEQT;
    const int tid = threadIdx.x;
    __shared__ float sh[8];

    __half2 h01 = *(const __half2*)(S + rb + tid * 4);
    __half2 h23 = *(const __half2*)(S + rb + tid * 4 + 2);
    float v0 = __half2float(h01.x), v1 = __half2float(h01.y);
    float v2 = __half2float(h23.x), v3 = __half2float(h23.y);

    float m = fmaxf(fmaxf(v0, v1), fmaxf(v2, v3));
#pragma unroll
    for (int o = 16; o; o >>= 1) m = fmaxf(m, __shfl_xor_sync(0xffffffffu, m, o));
    if ((tid & 31) == 0) sh[tid >> 5] = m;
    __syncthreads();
    if (tid < 8) {
        float mm = sh[tid];
#pragma unroll
        for (int o = 4; o; o >>= 1) mm = fmaxf(mm, __shfl_xor_sync(0xffu, mm, o));
        sh[tid] = mm;
    }
    __syncthreads();
    m = sh[0];
    __syncthreads();

    float e0 = __expf(v0 - m), e1 = __expf(v1 - m);
    float e2 = __expf(v2 - m), e3 = __expf(v3 - m);
    float s = e0 + e1 + e2 + e3;
#pragma unroll
    for (int o = 16; o; o >>= 1) s += __shfl_xor_sync(0xffffffffu, s, o);
    if ((tid & 31) == 0) sh[tid >> 5] = s;
    __syncthreads();
    if (tid < 8) {
        float ss = sh[tid];
#pragma unroll
        for (int o = 4; o; o >>= 1) ss += __shfl_xor_sync(0xffu, ss, o);
        sh[tid] = ss;
    }
    __syncthreads();
    const float inv = 1.f / sh[0];

    __half2 a01, a23;
    a01.x = __float2half(e0 * inv); a01.y = __float2half(e1 * inv);
    a23.x = __float2half(e2 * inv); a23.y = __float2half(e3 * inv);
    *(__half2*)(Af + rb + tid * 4)     = a01;
    *(__half2*)(Af + rb + tid * 4 + 2) = a23;
}

// ---------------- readout phase 1: per-(bh,d) stats (coalesced D reads) ------
__global__ void readout_stats_k(const float* __restrict__ F, float4* __restrict__ stats)
{
    int warp = threadIdx.x >> 5, lane = threadIdx.x & 31;
    int gid = blockIdx.x * 8 + warp;            // 0..4095
    int bh = gid >> 6, d = gid & 63;
    const float* rre = F + (long)bh * (128 * SEQT) + d * SEQT;
    const float* rim = rre + 64 * SEQT;

    float re[32], im[32];
    float sre = 0.f, sim = 0.f;
#pragma unroll
    for (int j = 0; j < 32; j++) {
        re[j] = rre[lane + j * 32]; im[j] = rim[lane + j * 32];
        sre += re[j]; sim += im[j];
    }
#pragma unroll
    for (int o = 16; o; o >>= 1) {
        sre += __shfl_xor_sync(0xffffffffu, sre, o);
        sim += __shfl_xor_sync(0xffffffffu, sim, o);
    }
    float mr = sre * (1.f / SEQT), mi = sim * (1.f / SEQT);
    float mn = sqrtf(mr * mr + mi * mi);

    float cs[32]; float mx = -1e30f;
#pragma unroll
    for (int j = 0; j < 32; j++) {
        float dot = re[j] * mr + im[j] * mi;
        float nrm = sqrtf(re[j] * re[j] + im[j] * im[j]) * mn + 1e-8f;
        cs[j] = dot / nrm;
        mx = fmaxf(mx, cs[j]);
    }
#pragma unroll
    for (int o = 16; o; o >>= 1) mx = fmaxf(mx, __shfl_xor_sync(0xffffffffu, mx, o));
    float s = 0.f;
#pragma unroll
    for (int j = 0; j < 32; j++) s += __expf(cs[j] - mx);
#pragma unroll
    for (int o = 16; o; o >>= 1) s += __shfl_xor_sync(0xffffffffu, s, o);

    if (lane == 0) stats[bh * DHEAD + d] = make_float4(mr, mi, mx, s);
}

// ---------------- readout phase 2: tiled apply (all accesses coalesced) ------
// block = (ttile of 128, bh). smem-staged D transpose; writes gate, P hi/lo.
__global__ __launch_bounds__(256)
void readout_apply_k(const float* __restrict__ F, const float* __restrict__ Vc,
                     const float4* __restrict__ stats,
                     float* __restrict__ gate,
                     __half* __restrict__ Ph, __half* __restrict__ Pl)
{
    constexpr int TP = 129;                 // row pad: conflict-free column reads
    extern __shared__ float smD[];          // [128][TP]
    __shared__ float4 sst[64];

    const int t0 = blockIdx.x * 128;
    const int bh = blockIdx.y;
    const int b = bh >> 4, h = bh & 15;
    const int tid = threadIdx.x;

    const float* Fb = F + (long)bh * (128 * SEQT);
    for (int i = tid; i < 128 * 32; i += 256) {
        int r = i >> 5, c4 = (i & 31) * 4;
        float4 v = *(const float4*)&Fb[(long)r * SEQT + t0 + c4];
        float* dst = &smD[r * TP + c4];
        dst[0] = v.x; dst[1] = v.y; dst[2] = v.z; dst[3] = v.w;
    }
    if (tid < 64) sst[tid] = stats[bh * DHEAD + tid];
    __syncthreads();

    for (int j = 0; j < 32; j++) {
        int idx = j * 256 + tid;            // over 128 t x 64 d
        int tl = idx >> 6, d = idx & 63;
        int t = t0 + tl;
        float4 st = sst[d];
        float mn = sqrtf(st.x * st.x + st.y * st.y);
        float re = smD[d * TP + tl];
        float im = smD[(d + 64) * TP + tl];
        float dot = re * st.x + im * st.y;
        float nrm = sqrtf(re * re + im * im) * mn + 1e-8f;
        float gq = __expf(dot / nrm - st.z) * (1.f / st.w);
        long go = ((long)bh * SEQT + t) * DHEAD + d;
        gate[go] = gq;
        float pv = gq * Vc[go];
        __half hh = hf_hi(pv);
        long po = ((long)(b * SEQT + t)) * DMODEL + h * DHEAD + d;
        Ph[po] = hh; Pl[po] = hf_lo(pv, hh);
    }
}

// -----------------------------------------------------------------------------
extern "C" void kernel_launch(void* const* d_in, const int* in_sizes, int n_in,
                              void* d_out, int out_size)
{
    const float* x   = (const float*)d_in[0];
    const float* WQ  = (const float*)d_in[1];
    const float* WK  = (const float*)d_in[2];
    const float* Wre = (const float*)d_in[3];
    const float* Wim = (const float*)d_in[4];
    const float* WV  = (const float*)d_in[5];
    const float* WO  = (const float*)d_in[6];
    const float* lam = (const float*)d_in[7];
    float* out = (float*)d_out;

    float *pDri, *pDT, *pGateScr, *pVc;
    float4* pStats;
    __half *pxh, *pxl, *pWqkv, *pWrih, *pWril, *pWOf;
    __half *pQh, *pQl, *pKf, *pSh, *pAf, *pDTh, *pDTl, *pPh, *pPl;
    cudaGetSymbolAddress((void**)&pDri, g_Dri);
    cudaGetSymbolAddress((void**)&pDT, g_DT);
    cudaGetSymbolAddress((void**)&pGateScr, g_gate_scratch);
    cudaGetSymbolAddress((void**)&pVc, g_Vc);
    cudaGetSymbolAddress((void**)&pStats, g_stats);
    cudaGetSymbolAddress((void**)&pxh, g_xh);
    cudaGetSymbolAddress((void**)&pxl, g_xl);
    cudaGetSymbolAddress((void**)&pWqkv, g_Wqkv);
    cudaGetSymbolAddress((void**)&pWrih, g_Wri_h);
    cudaGetSymbolAddress((void**)&pWril, g_Wri_l);
    cudaGetSymbolAddress((void**)&pWOf, g_WOf);
    cudaGetSymbolAddress((void**)&pQh, g_Qh);
    cudaGetSymbolAddress((void**)&pQl, g_Ql);
    cudaGetSymbolAddress((void**)&pKf, g_Kf);
    cudaGetSymbolAddress((void**)&pSh, g_Sh);
    cudaGetSymbolAddress((void**)&pAf, g_Af);
    cudaGetSymbolAddress((void**)&pDTh, g_DTh);
    cudaGetSymbolAddress((void**)&pDTl, g_DTl);
    cudaGetSymbolAddress((void**)&pPh, g_Ph);
    cudaGetSymbolAddress((void**)&pPl, g_Pl);

    const long OUT_ELEMS  = (long)BT * DMODEL;
    const long GATE_ELEMS = (long)HEADEL;
    float* gate = (out_size >= (int)(OUT_ELEMS + GATE_ELEMS)) ? (out + OUT_ELEMS) : pGateScr;

    const int SMEM2 = 4 * (128 * 4 * 3) * 16;   // NPROD=2: 4 stages x 3 arrays = 96 KB
    const int SMEM3 = 3 * (128 * 4 * 4) * 16;   // NPROD=3: 3 stages x 4 arrays = 96 KB
    const int SMEMP = 4 * (128 * 4 * 2) * 16;   // prop: 4 stages x 2 arrays = 64 KB
    const int SMEMR = 128 * 129 * 4;            // readout apply: ~66 KB
    cudaFuncSetAttribute(fgemm<2,0>, cudaFuncAttributeMaxDynamicSharedMemorySize, SMEM2);
    cudaFuncSetAttribute(fgemm<2,1>, cudaFuncAttributeMaxDynamicSharedMemorySize, SMEM2);
    cudaFuncSetAttribute(fgemm<2,2>, cudaFuncAttributeMaxDynamicSharedMemorySize, SMEM2);
    cudaFuncSetAttribute(fgemm<3,0>, cudaFuncAttributeMaxDynamicSharedMemorySize, SMEM3);
    cudaFuncSetAttribute(prop_gemm,  cudaFuncAttributeMaxDynamicSharedMemorySize, SMEMP);
    cudaFuncSetAttribute(readout_apply_k, cudaFuncAttributeMaxDynamicSharedMemorySize, SMEMR);

    // x -> fp16 hi/lo; weights -> transposed fp16 (re/im hi/lo)
    split_x_k<<<(BT * DMODEL + 255) / 256, 256>>>(x, pxh, pxl, BT * DMODEL);
    splitT_w_all<<<dim3(32, 32, 6), dim3(32, 8)>>>(WQ, WK, WV, Wre, Wim, WO,
                                                   pWqkv, pWrih, pWril, pWOf);

    // proj part A: x @ [WQ|WK|WV], 2-product, fused per-head split epilogue
    fgemm<2,2><<<dim3(3072 / 128, BT / 128, 1), 256, SMEM2>>>(
        pxh, pxl, 0, DMODEL, pWqkv, nullptr, 0, DMODEL,
        nullptr, nullptr, 0, 0, DMODEL, 1.f,
        pQh, pQl, pKf, pVc);
    // proj part B: x @ [Wre|Wim], 3-product -> compact Dri fp32
    fgemm<3,0><<<dim3(2048 / 128, BT / 128, 1), 256, SMEM3>>>(
        pxh, pxl, 0, DMODEL, pWrih, pWril, 0, DMODEL,
        pDri, nullptr, 0, 2048, DMODEL, 1.f,
        nullptr, nullptr, nullptr, nullptr);

    // D fused transposed fp16 hi/lo (from compact Dri)
    split_D16_k<<<dim3(32, 2, 2 * NBH), dim3(32, 8)>>>(pDri, pDTh, pDTl);

    // scores = Q @ K^T / 8, fp16 output
    fgemm<2,1><<<dim3(8, 8, NBH), 256, SMEM2>>>(
        pQh, pQl, (long)SEQT * DHEAD, DHEAD,
        pKf, nullptr, (long)SEQT * DHEAD, DHEAD,
        nullptr, pSh, (long)SEQT * SEQT, SEQT, DHEAD, 0.125f,
        nullptr, nullptr, nullptr, nullptr);

    // softmax rows -> A fp16
    softmax_f16_k<<<NBH * SEQT, 256>>>(pSh, pAf);

    // propagation: single-product mma on D-hi, exact hi+lo carry
    for (int s = 0; s < NSTEPS; s++) {
        long iin = (long)(s & 1) * FEL;
        long iou = (long)(1 - (s & 1)) * FEL;
        prop_gemm<<<dim3(8, 1, NBH), 256, SMEMP>>>(
            pDTh + iin, 128L * SEQT, SEQT,
            pAf, (long)SEQT * SEQT, SEQT,
            (s == NSTEPS - 1) ? pDT : nullptr,
            pDTh + iin, pDTl + iin,
            pDTh + iou, pDTl + iou,
            128L * SEQT, SEQT, SEQT, lam);
    }

    // readout: stats (coalesced reductions) + tiled apply (coalesced writes)
    readout_stats_k<<<NBH * DHEAD / 8, 256>>>(pDT, pStats);
    readout_apply_k<<<dim3(SEQT / 128, NBH), 256, SMEMR>>>(pDT, pVc, pStats,
                                                           gate, pPh, pPl);

    // out = P @ W_O
    fgemm<2,0><<<dim3(DMODEL / 128, BT / 128, 1), 256, SMEM2>>>(
        pPh, pPl, 0, DMODEL, pWOf, nullptr, 0, DMODEL,
        out, nullptr, 0, DMODEL, DMODEL, 1.f,
        nullptr, nullptr, nullptr, nullptr);
}

// round 15
// speedup vs baseline: 1.7411x; 1.0499x over previous
#include <cuda_runtime.h>
#include <cuda_bf16.h>
#include <cuda_fp16.h>
#include <math.h>
#include <stdint.h>

// Problem constants
#define BATCH 4
#define SEQT  1024
#define DMODEL 1024
#define NHEAD 16
#define DHEAD 64
#define NBH   (BATCH*NHEAD)      // 64
#define BT    (BATCH*SEQT)       // 4096
#define NSTEPS 3

#define HEADEL (NBH*SEQT*DHEAD)          // 4,194,304
#define FEL    (2L*HEADEL)               // fused re|im D: [bh][128][1024]
#define AEL    ((size_t)NBH*SEQT*SEQT)   // 67,108,864

// ---------------- scratch (device globals; no allocation allowed) ------------
__device__ float g_Dri[(size_t)BT*2048];           // compact [b*T+t][re|im] fp32
__device__ float g_DT[FEL];                        // final-step D fp32 for readout
__device__ float g_gate_scratch[HEADEL];
__device__ float g_Vc[HEADEL];                     // V compact per-head [bh][t][d] fp32
__device__ float4 g_stats[NBH*DHEAD];              // per-(bh,d): {mr, mi, cmax, csum}

__device__ __half g_xh[BT*DMODEL], g_xl[BT*DMODEL];        // x fp16 hi/lo
__device__ __half g_Wqkv[3*DMODEL*DMODEL];                 // [n][k] single fp16
__device__ __half g_Wri_h[2*DMODEL*DMODEL], g_Wri_l[2*DMODEL*DMODEL]; // re/im hi/lo
__device__ __half g_WOf[DMODEL*DMODEL];                    // [n][k] single fp16
__device__ __half g_Qf[HEADEL];                            // Q single fp16
__device__ __half g_Kf[HEADEL];                            // K single fp16
__device__ __half g_Sh[AEL];                               // scores fp16
__device__ __half g_Af[AEL];                               // adjacency single fp16
__device__ __half g_DTh[2L*FEL], g_DTl[2L*FEL];            // D fp16 hi/lo [pp]
__device__ __half g_Pf[BT*DMODEL];                         // P single fp16

// ---------------- PTX helpers ------------------------------------------------
__device__ __forceinline__ uint32_t smem_u32(const void* p) {
    return (uint32_t)__cvta_generic_to_shared(p);
}
__device__ __forceinline__ void cp16(uint32_t dst, const void* src) {
    asm volatile("cp.async.cg.shared.global [%0], [%1], 16;\n" :: "r"(dst), "l"(src));
}
__device__ __forceinline__ void cp_commit() { asm volatile("cp.async.commit_group;\n"); }
template<int N> __device__ __forceinline__ void cp_wait() {
    asm volatile("cp.async.wait_group %0;\n" :: "n"(N));
}
__device__ __forceinline__ void ldsm4(uint32_t& r0, uint32_t& r1, uint32_t& r2, uint32_t& r3, uint32_t addr) {
    asm volatile("ldmatrix.sync.aligned.m8n8.x4.shared.b16 {%0,%1,%2,%3}, [%4];\n"
                 : "=r"(r0), "=r"(r1), "=r"(r2), "=r"(r3) : "r"(addr));
}
__device__ __forceinline__ void mma_f16(float* c, const uint32_t* a, const uint32_t* b) {
    asm volatile("mma.sync.aligned.m16n8k16.row.col.f32.f16.f16.f32 "
                 "{%0,%1,%2,%3}, {%4,%5,%6,%7}, {%8,%9}, {%0,%1,%2,%3};\n"
                 : "+f"(c[0]), "+f"(c[1]), "+f"(c[2]), "+f"(c[3])
                 : "r"(a[0]), "r"(a[1]), "r"(a[2]), "r"(a[3]), "r"(b[0]), "r"(b[1]));
}
__device__ __forceinline__ __half hf_hi(float v) { return __float2half(v); }
__device__ __forceinline__ __half hf_lo(float v, __half h) {
    return __float2half(v - __half2float(h));
}

// ---------------- fp16 GEMM --------------------------------------------------
// C[m][n] = alpha * sum_k (A[m][k] * B[n][k])
// NPROD==1: A single, B single (1 mma/step).
// NPROD==2: A hi/lo, B single (Ah*B + Al*B).
// NPROD==3: A hi/lo, B hi/lo (Ah*Bh + Al*Bh + Ah*Bl).
// OUT: 0 = fp32 C; 1 = fp16 C16; 2 = fused QKV per-head split
//      (col0<1024 -> Q single fp16, <2048 -> K single, else -> V fp32 compact).
// BM=128, BN=128, WM=64, WN=32, BK=32.
template<int NPROD, int OUT>
__global__ __launch_bounds__(256)
void fgemm(const __half* __restrict__ Ahi, const __half* __restrict__ Alo,
           long sA, int lda,
           const __half* __restrict__ Bh_, const __half* __restrict__ Bl_,
           long sB, int ldb,
           float* __restrict__ C, __half* __restrict__ C16, long sC, int ldc,
           int K, float alpha,
           __half* __restrict__ qh, __half* __restrict__ kf, float* __restrict__ vc)
{
    constexpr int BM = 128, BN = 128, WM = 64, WN = 32;
    constexpr int STAGES = (NPROD == 3) ? 3 : 4;
    constexpr int ACH = BM * 4;
    constexpr int BCH = BN * 4;
    constexpr int MI = WM / 16;   // 4
    constexpr int NI = WN / 8;    // 4
    constexpr int WROWS = BM / WM;

    extern __shared__ uint4 sm[];
    uint4* sAh_ = sm;
    uint4* sAl_ = sAh_ + STAGES * ACH;                         // NPROD>=2 only
    uint4* sBh_ = (NPROD >= 2) ? (sAl_ + STAGES * ACH) : (sAh_ + STAGES * ACH);
    uint4* sBl_ = sBh_ + STAGES * BCH;                         // NPROD==3 only

    const int z = blockIdx.z;
    const __half* pAh = Ahi + (long)z * sA;
    const __half* pAl = (NPROD >= 2) ? (Alo + (long)z * sA) : nullptr;
    const __half* pBh = Bh_ + (long)z * sB;
    const __half* pBl = (NPROD == 3) ? (Bl_ + (long)z * sB) : nullptr;

    const int row0 = blockIdx.y * BM;
    const int col0 = blockIdx.x * BN;
    const int tid  = threadIdx.x;
    const int warp = tid >> 5, lane = tid & 31;
    const int wm = (warp % WROWS) * WM;
    const int wn = (warp / WROWS) * WN;

    float acc[MI][NI][4];
#pragma unroll
    for (int i = 0; i < MI; i++)
#pragma unroll
        for (int j = 0; j < NI; j++)
#pragma unroll
            for (int q = 0; q < 4; q++) acc[i][j][q] = 0.f;

    auto load_tile = [&](int st, int kt) {
#pragma unroll
        for (int i = tid; i < ACH; i += 256) {
            int r = i >> 2, c = i & 3;
            int phys = c ^ ((r >> 1) & 3);
            long src = (long)(row0 + r) * lda + kt * 32 + c * 8;
            cp16(smem_u32(&sAh_[st * ACH + r * 4 + phys]), pAh + src);
            if (NPROD >= 2)
                cp16(smem_u32(&sAl_[st * ACH + r * 4 + phys]), pAl + src);
        }
#pragma unroll
        for (int i = tid; i < BCH; i += 256) {
            int r = i >> 2, c = i & 3;
            int phys = c ^ ((r >> 1) & 3);
            long src = (long)(col0 + r) * ldb + kt * 32 + c * 8;
            cp16(smem_u32(&sBh_[st * BCH + r * 4 + phys]), pBh + src);
            if (NPROD == 3)
                cp16(smem_u32(&sBl_[st * BCH + r * 4 + phys]), pBl + src);
        }
        cp_commit();
    };

    const int KT = K / 32;
#pragma unroll
    for (int i = 0; i < STAGES - 1; i++) {
        if (i < KT) load_tile(i, i);
        else cp_commit();
    }

    for (int kt = 0; kt < KT; kt++) {
        cp_wait<STAGES - 2>();
        __syncthreads();

        {
            int next = kt + STAGES - 1;
            if (next < KT) load_tile(next % STAGES, next);
            else cp_commit();
        }

        const int st = kt % STAGES;
        const uint4* tAh = sAh_ + st * ACH;
        const uint4* tAl = sAl_ + st * ACH;
        const uint4* tBh = sBh_ + st * BCH;
        const uint4* tBl = sBl_ + st * BCH;
        const int tr = lane & 7;

#pragma unroll
        for (int ks8 = 0; ks8 < 2; ks8++) {
            uint32_t ah[MI][4], al[MI][4];
            const int akc = ks8 * 2 + (lane >> 4);
#pragma unroll
            for (int mi = 0; mi < MI; mi++) {
                int r = wm + mi * 16 + tr + ((lane >> 3) & 1) * 8;
                int off = r * 4 + (akc ^ ((r >> 1) & 3));
                ldsm4(ah[mi][0], ah[mi][1], ah[mi][2], ah[mi][3], smem_u32(tAh + off));
                if (NPROD >= 2)
                    ldsm4(al[mi][0], al[mi][1], al[mi][2], al[mi][3], smem_u32(tAl + off));
            }
            uint32_t bh[NI][2], bl[NI][2];
            const int bkc = ks8 * 2 + ((lane >> 3) & 1);
#pragma unroll
            for (int p = 0; p < NI / 2; p++) {
                int r = wn + p * 16 + tr + (lane >> 4) * 8;
                int off = r * 4 + (bkc ^ ((r >> 1) & 3));
                ldsm4(bh[2*p][0], bh[2*p][1], bh[2*p+1][0], bh[2*p+1][1], smem_u32(tBh + off));
                if (NPROD == 3)
                    ldsm4(bl[2*p][0], bl[2*p][1], bl[2*p+1][0], bl[2*p+1][1], smem_u32(tBl + off));
            }
#pragma unroll
            for (int mi = 0; mi < MI; mi++)
#pragma unroll
                for (int ni = 0; ni < NI; ni++) {
                    mma_f16(acc[mi][ni], ah[mi], bh[ni]);
                    if (NPROD >= 2) mma_f16(acc[mi][ni], al[mi], bh[ni]);
                    if (NPROD == 3) mma_f16(acc[mi][ni], ah[mi], bl[ni]);
                }
        }
    }

    const long zC = (long)z * sC;
    const int g = lane >> 2, tig = lane & 3;
#pragma unroll
    for (int mi = 0; mi < MI; mi++) {
#pragma unroll
        for (int ni = 0; ni < NI; ni++) {
#pragma unroll
            for (int half_ = 0; half_ < 2; half_++) {
                int rr = row0 + wm + mi * 16 + g + half_ * 8;
                int cc = col0 + wn + ni * 8 + tig * 2;
                float v0 = alpha * acc[mi][ni][half_ * 2 + 0];
                float v1 = alpha * acc[mi][ni][half_ * 2 + 1];
                if (OUT == 0) {
                    float2 f2; f2.x = v0; f2.y = v1;
                    *(float2*)&C[zC + (long)rr * ldc + cc] = f2;
                } else if (OUT == 1) {
                    __half2 hv; hv.x = __float2half(v0); hv.y = __float2half(v1);
                    *(__half2*)&C16[zC + (long)rr * ldc + cc] = hv;
                } else {
                    int b = rr >> 10, t = rr & 1023;
                    int lc = cc & 1023, h = lc >> 6, d = lc & 63;
                    long o = ((long)((b << 4) | h) * SEQT + t) * DHEAD + d;
                    if (col0 < 2048) {          // Q or K: single fp16
                        __half2 hv; hv.x = __float2half(v0); hv.y = __float2half(v1);
                        *(__half2*)&((col0 < 1024) ? qh : kf)[o] = hv;
                    } else {                    // V fp32 compact
                        float2 f2; f2.x = v0; f2.y = v1;
                        *(float2*)&vc[o] = f2;
                    }
                }
            }
        }
    }
}

// ---------------- fp16 propagation GEMM (single-product mma) ------------------
// DT'[m][t] = lam * sum_s (DThi[m][s]*Aadj[t][s]) + (1-lam)*(DThi+DTlo)[m][t]
__global__ __launch_bounds__(256)
void prop_gemm(const __half* __restrict__ Ahi,
               long sA, int lda,
               const __half* __restrict__ Bh_, long sB, int ldb,
               float* __restrict__ Cf,
               const __half* __restrict__ Cinh, const __half* __restrict__ Cinl,
               __half* __restrict__ Chi, __half* __restrict__ Clo,
               long sZ, int ldz, int K, const float* __restrict__ lam_ptr)
{
    constexpr int BM = 128, BN = 128, WM = 64, WN = 32, STAGES = 4;
    constexpr int ACH = BM * 4;
    constexpr int BCH = BN * 4;
    constexpr int MI = WM / 16;
    constexpr int NI = WN / 8;
    constexpr int WROWS = BM / WM;

    extern __shared__ uint4 sm[];
    uint4* sAh_ = sm;
    uint4* sBh_ = sAh_ + STAGES * ACH;

    const int z = blockIdx.z;
    const __half* pAh = Ahi + (long)z * sA;
    const __half* pBh = Bh_ + (long)z * sB;

    const int row0 = blockIdx.y * BM;
    const int col0 = blockIdx.x * BN;
    const int tid  = threadIdx.x;
    const int warp = tid >> 5, lane = tid & 31;
    const int wm = (warp % WROWS) * WM;
    const int wn = (warp / WROWS) * WN;

    float acc[MI][NI][4];
#pragma unroll
    for (int i = 0; i < MI; i++)
#pragma unroll
        for (int j = 0; j < NI; j++)
#pragma unroll
            for (int q = 0; q < 4; q++) acc[i][j][q] = 0.f;

    auto load_tile = [&](int st, int kt) {
#pragma unroll
        for (int i = tid; i < ACH; i += 256) {
            int r = i >> 2, c = i & 3;
            int phys = c ^ ((r >> 1) & 3);
            long src = (long)(row0 + r) * lda + kt * 32 + c * 8;
            cp16(smem_u32(&sAh_[st * ACH + r * 4 + phys]), pAh + src);
        }
#pragma unroll
        for (int i = tid; i < BCH; i += 256) {
            int r = i >> 2, c = i & 3;
            int phys = c ^ ((r >> 1) & 3);
            long src = (long)(col0 + r) * ldb + kt * 32 + c * 8;
            cp16(smem_u32(&sBh_[st * BCH + r * 4 + phys]), pBh + src);
        }
        cp_commit();
    };

    const int KT = K / 32;
#pragma unroll
    for (int i = 0; i < STAGES - 1; i++) {
        if (i < KT) load_tile(i, i);
        else cp_commit();
    }

    for (int kt = 0; kt < KT; kt++) {
        cp_wait<STAGES - 2>();
        __syncthreads();

        {
            int next = kt + STAGES - 1;
            if (next < KT) load_tile(next % STAGES, next);
            else cp_commit();
        }

        const int st = kt % STAGES;
        const uint4* tAh = sAh_ + st * ACH;
        const uint4* tBh = sBh_ + st * BCH;
        const int tr = lane & 7;

#pragma unroll
        for (int ks8 = 0; ks8 < 2; ks8++) {
            uint32_t ah[MI][4];
            const int akc = ks8 * 2 + (lane >> 4);
#pragma unroll
            for (int mi = 0; mi < MI; mi++) {
                int r = wm + mi * 16 + tr + ((lane >> 3) & 1) * 8;
                int off = r * 4 + (akc ^ ((r >> 1) & 3));
                ldsm4(ah[mi][0], ah[mi][1], ah[mi][2], ah[mi][3], smem_u32(tAh + off));
            }
            uint32_t bh[NI][2];
            const int bkc = ks8 * 2 + ((lane >> 3) & 1);
#pragma unroll
            for (int p = 0; p < NI / 2; p++) {
                int r = wn + p * 16 + tr + (lane >> 4) * 8;
                int off = r * 4 + (bkc ^ ((r >> 1) & 3));
                ldsm4(bh[2*p][0], bh[2*p][1], bh[2*p+1][0], bh[2*p+1][1], smem_u32(tBh + off));
            }
#pragma unroll
            for (int mi = 0; mi < MI; mi++)
#pragma unroll
                for (int ni = 0; ni < NI; ni++)
                    mma_f16(acc[mi][ni], ah[mi], bh[ni]);
        }
    }

    const float lm = 1.f / (1.f + __expf(-lam_ptr[0]));
    const float be = 1.f - lm;
    const long zZ = (long)z * sZ;
    const int g = lane >> 2, tig = lane & 3;
#pragma unroll
    for (int mi = 0; mi < MI; mi++) {
#pragma unroll
        for (int ni = 0; ni < NI; ni++) {
            int r = row0 + wm + mi * 16 + g;
            int cc = col0 + wn + ni * 8 + tig * 2;
#pragma unroll
            for (int half_ = 0; half_ < 2; half_++) {
                int rr = r + half_ * 8;
                long o = zZ + (long)rr * ldz + cc;
                __half2 ch = *(const __half2*)&Cinh[o];
                __half2 cl = *(const __half2*)&Cinl[o];
                float c0 = __half2float(ch.x) + __half2float(cl.x);
                float c1 = __half2float(ch.y) + __half2float(cl.y);
                float v0 = lm * acc[mi][ni][half_ * 2 + 0] + be * c0;
                float v1 = lm * acc[mi][ni][half_ * 2 + 1] + be * c1;
                __half2 hv, lv;
                hv.x = hf_hi(v0); hv.y = hf_hi(v1);
                lv.x = hf_lo(v0, hv.x); lv.y = hf_lo(v1, hv.y);
                *(__half2*)&Chi[o] = hv;
                *(__half2*)&Clo[o] = lv;
                if (Cf) {
                    float2 f2; f2.x = v0; f2.y = v1;
                    *(float2*)&Cf[o] = f2;
                }
            }
        }
    }
}

// ---------------- conversions ------------------------------------------------
__global__ void split_x_k(const float* __restrict__ src,
                          __half* __restrict__ hi, __half* __restrict__ lo, int n)
{
    int i = blockIdx.x * 256 + threadIdx.x;
    if (i < n) {
        float v = src[i];
        __half h = hf_hi(v);
        hi[i] = h; lo[i] = hf_lo(v, h);
    }
}

// 6 weights [k][n] -> [n][k]; zz 0-2 -> Wqkv single (WQ, WK, WV);
// zz 3-4 -> Wri hi/lo (Wre, Wim); zz 5 -> WO single.
__global__ void splitT_w_all(const float* __restrict__ W0, const float* __restrict__ W1,
                             const float* __restrict__ W2, const float* __restrict__ W3,
                             const float* __restrict__ W4, const float* __restrict__ W5,
                             __half* __restrict__ Wqkv,
                             __half* __restrict__ Wri_h, __half* __restrict__ Wri_l,
                             __half* __restrict__ WOf)
{
    __shared__ float t[32][33];
    int zz = blockIdx.z;
    const float* W = (zz == 0) ? W0 : (zz == 1) ? W1 : (zz == 2) ? W2
                   : (zz == 3) ? W3 : (zz == 4) ? W4 : W5;
    int k0 = blockIdx.y * 32, n0 = blockIdx.x * 32;
    for (int i = threadIdx.y; i < 32; i += 8)
        t[i][threadIdx.x] = W[(k0 + i) * DMODEL + n0 + threadIdx.x];
    __syncthreads();
    for (int i = threadIdx.y; i < 32; i += 8) {
        float v = t[threadIdx.x][i];
        long o = (long)(n0 + i) * DMODEL + k0 + threadIdx.x;
        if (zz < 3) {
            Wqkv[(long)zz * DMODEL * DMODEL + o] = __float2half(v);
        } else if (zz < 5) {
            __half h = hf_hi(v);
            Wri_h[(long)(zz - 3) * DMODEL * DMODEL + o] = h;
            Wri_l[(long)(zz - 3) * DMODEL * DMODEL + o] = hf_lo(v, h);
        } else {
            WOf[o] = __float2half(v);
        }
    }
}

// compact Dri [b*T+t][2048] -> fused transposed [bh][rowoff+d][t] fp16 hi/lo
__global__ void split_D16_k(const float* __restrict__ Dri,
                            __half* __restrict__ hi, __half* __restrict__ lo)
{
    __shared__ float tb[32][33];
    int zz = blockIdx.z;
    int bh = zz >> 1, half_ = zz & 1;
    int coloff = half_ * 1024, rowoff = half_ * 64;
    int b = bh >> 4, h = bh & 15;
    int t0 = blockIdx.x * 32, d0 = blockIdx.y * 32;
    for (int i = threadIdx.y; i < 32; i += 8)
        tb[i][threadIdx.x] = Dri[((long)(b * SEQT + t0 + i)) * 2048 + coloff + h * DHEAD + d0 + threadIdx.x];
    __syncthreads();
    long base = (long)bh * (128 * SEQT);
    for (int i = threadIdx.y; i < 32; i += 8) {
        float v = tb[threadIdx.x][i];
        long o = base + (long)(rowoff + d0 + i) * SEQT + t0 + threadIdx.x;
        __half hh = hf_hi(v);
        hi[o] = hh; lo[o] = hf_lo(v, hh);
    }
}

// ---------------- single-pass softmax over fp16 rows of 1024 -> fp16 A -------
__global__ void softmax_f16_k(const __half* __restrict__ S, __half* __restrict__ Af)
{
    const long rb = (long)blockIdx.x * SEQT;
    const int tid = threadIdx.x;
    __shared__ float sh[8];

    __half2 h01 = *(const __half2*)(S + rb + tid * 4);
    __half2 h23 = *(const __half2*)(S + rb + tid * 4 + 2);
    float v0 = __half2float(h01.x), v1 = __half2float(h01.y);
    float v2 = __half2float(h23.x), v3 = __half2float(h23.y);

    float m = fmaxf(fmaxf(v0, v1), fmaxf(v2, v3));
#pragma unroll
    for (int o = 16; o; o >>= 1) m = fmaxf(m, __shfl_xor_sync(0xffffffffu, m, o));
    if ((tid & 31) == 0) sh[tid >> 5] = m;
    __syncthreads();
    if (tid < 8) {
        float mm = sh[tid];
#pragma unroll
        for (int o = 4; o; o >>= 1) mm = fmaxf(mm, __shfl_xor_sync(0xffu, mm, o));
        sh[tid] = mm;
    }
    __syncthreads();
    m = sh[0];
    __syncthreads();

    float e0 = __expf(v0 - m), e1 = __expf(v1 - m);
    float e2 = __expf(v2 - m), e3 = __expf(v3 - m);
    float s = e0 + e1 + e2 + e3;
#pragma unroll
    for (int o = 16; o; o >>= 1) s += __shfl_xor_sync(0xffffffffu, s, o);
    if ((tid & 31) == 0) sh[tid >> 5] = s;
    __syncthreads();
    if (tid < 8) {
        float ss = sh[tid];
#pragma unroll
        for (int o = 4; o; o >>= 1) ss += __shfl_xor_sync(0xffu, ss, o);
        sh[tid] = ss;
    }
    __syncthreads();
    const float inv = 1.f / sh[0];

    __half2 a01, a23;
    a01.x = __float2half(e0 * inv); a01.y = __float2half(e1 * inv);
    a23.x = __float2half(e2 * inv); a23.y = __float2half(e3 * inv);
    *(__half2*)(Af + rb + tid * 4)     = a01;
    *(__half2*)(Af + rb + tid * 4 + 2) = a23;
}

// ---------------- readout phase 1: per-(bh,d) stats (coalesced D reads) ------
__global__ void readout_stats_k(const float* __restrict__ F, float4* __restrict__ stats)
{
    int warp = threadIdx.x >> 5, lane = threadIdx.x & 31;
    int gid = blockIdx.x * 8 + warp;            // 0..4095
    int bh = gid >> 6, d = gid & 63;
    const float* rre = F + (long)bh * (128 * SEQT) + d * SEQT;
    const float* rim = rre + 64 * SEQT;

    float re[32], im[32];
    float sre = 0.f, sim = 0.f;
#pragma unroll
    for (int j = 0; j < 32; j++) {
        re[j] = rre[lane + j * 32]; im[j] = rim[lane + j * 32];
        sre += re[j]; sim += im[j];
    }
#pragma unroll
    for (int o = 16; o; o >>= 1) {
        sre += __shfl_xor_sync(0xffffffffu, sre, o);
        sim += __shfl_xor_sync(0xffffffffu, sim, o);
    }
    float mr = sre * (1.f / SEQT), mi = sim * (1.f / SEQT);
    float mn = sqrtf(mr * mr + mi * mi);

    float cs[32]; float mx = -1e30f;
#pragma unroll
    for (int j = 0; j < 32; j++) {
        float dot = re[j] * mr + im[j] * mi;
        float nrm = sqrtf(re[j] * re[j] + im[j] * im[j]) * mn + 1e-8f;
        cs[j] = dot / nrm;
        mx = fmaxf(mx, cs[j]);
    }
#pragma unroll
    for (int o = 16; o; o >>= 1) mx = fmaxf(mx, __shfl_xor_sync(0xffffffffu, mx, o));
    float s = 0.f;
#pragma unroll
    for (int j = 0; j < 32; j++) s += __expf(cs[j] - mx);
#pragma unroll
    for (int o = 16; o; o >>= 1) s += __shfl_xor_sync(0xffffffffu, s, o);

    if (lane == 0) stats[bh * DHEAD + d] = make_float4(mr, mi, mx, s);
}

// ---------------- readout phase 2: tiled apply (all accesses coalesced) ------
// block = (ttile of 128, bh). smem-staged D transpose; writes gate, P fp16.
__global__ __launch_bounds__(256)
void readout_apply_k(const float* __restrict__ F, const float* __restrict__ Vc,
                     const float4* __restrict__ stats,
                     float* __restrict__ gate, __half* __restrict__ Pf)
{
    constexpr int TP = 129;                 // row pad: conflict-free column reads
    extern __shared__ float smD[];          // [128][TP]
    __shared__ float4 sst[64];

    const int t0 = blockIdx.x * 128;
    const int bh = blockIdx.y;
    const int b = bh >> 4, h = bh & 15;
    const int tid = threadIdx.x;

    const float* Fb = F + (long)bh * (128 * SEQT);
    for (int i = tid; i < 128 * 32; i += 256) {
        int r = i >> 5, c4 = (i & 31) * 4;
        float4 v = *(const float4*)&Fb[(long)r * SEQT + t0 + c4];
        float* dst = &smD[r * TP + c4];
        dst[0] = v.x; dst[1] = v.y; dst[2] = v.z; dst[3] = v.w;
    }
    if (tid < 64) sst[tid] = stats[bh * DHEAD + tid];
    __syncthreads();

    for (int j = 0; j < 32; j++) {
        int idx = j * 256 + tid;            // over 128 t x 64 d
        int tl = idx >> 6, d = idx & 63;
        int t = t0 + tl;
        float4 st = sst[d];
        float mn = sqrtf(st.x * st.x + st.y * st.y);
        float re = smD[d * TP + tl];
        float im = smD[(d + 64) * TP + tl];
        float dot = re * st.x + im * st.y;
        float nrm = sqrtf(re * re + im * im) * mn + 1e-8f;
        float gq = __expf(dot / nrm - st.z) * (1.f / st.w);
        long go = ((long)bh * SEQT + t) * DHEAD + d;
        gate[go] = gq;
        float pv = gq * Vc[go];
        long po = ((long)(b * SEQT + t)) * DMODEL + h * DHEAD + d;
        Pf[po] = __float2half(pv);
    }
}

// -----------------------------------------------------------------------------
extern "C" void kernel_launch(void* const* d_in, const int* in_sizes, int n_in,
                              void* d_out, int out_size)
{
    const float* x   = (const float*)d_in[0];
    const float* WQ  = (const float*)d_in[1];
    const float* WK  = (const float*)d_in[2];
    const float* Wre = (const float*)d_in[3];
    const float* Wim = (const float*)d_in[4];
    const float* WV  = (const float*)d_in[5];
    const float* WO  = (const float*)d_in[6];
    const float* lam = (const float*)d_in[7];
    float* out = (float*)d_out;

    float *pDri, *pDT, *pGateScr, *pVc;
    float4* pStats;
    __half *pxh, *pxl, *pWqkv, *pWrih, *pWril, *pWOf;
    __half *pQf, *pKf, *pSh, *pAf, *pDTh, *pDTl, *pPf;
    cudaGetSymbolAddress((void**)&pDri, g_Dri);
    cudaGetSymbolAddress((void**)&pDT, g_DT);
    cudaGetSymbolAddress((void**)&pGateScr, g_gate_scratch);
    cudaGetSymbolAddress((void**)&pVc, g_Vc);
    cudaGetSymbolAddress((void**)&pStats, g_stats);
    cudaGetSymbolAddress((void**)&pxh, g_xh);
    cudaGetSymbolAddress((void**)&pxl, g_xl);
    cudaGetSymbolAddress((void**)&pWqkv, g_Wqkv);
    cudaGetSymbolAddress((void**)&pWrih, g_Wri_h);
    cudaGetSymbolAddress((void**)&pWril, g_Wri_l);
    cudaGetSymbolAddress((void**)&pWOf, g_WOf);
    cudaGetSymbolAddress((void**)&pQf, g_Qf);
    cudaGetSymbolAddress((void**)&pKf, g_Kf);
    cudaGetSymbolAddress((void**)&pSh, g_Sh);
    cudaGetSymbolAddress((void**)&pAf, g_Af);
    cudaGetSymbolAddress((void**)&pDTh, g_DTh);
    cudaGetSymbolAddress((void**)&pDTl, g_DTl);
    cudaGetSymbolAddress((void**)&pPf, g_Pf);

    const long OUT_ELEMS  = (long)BT * DMODEL;
    const long GATE_ELEMS = (long)HEADEL;
    float* gate = (out_size >= (int)(OUT_ELEMS + GATE_ELEMS)) ? (out + OUT_ELEMS) : pGateScr;

    const int SMEM1 = 4 * (128 * 4 * 2) * 16;   // NPROD=1: 4 stages x 2 arrays = 64 KB
    const int SMEM2 = 4 * (128 * 4 * 3) * 16;   // NPROD=2: 4 stages x 3 arrays = 96 KB
    const int SMEM3 = 3 * (128 * 4 * 4) * 16;   // NPROD=3: 3 stages x 4 arrays = 96 KB
    const int SMEMP = 4 * (128 * 4 * 2) * 16;   // prop: 64 KB
    const int SMEMR = 128 * 129 * 4;            // readout apply: ~66 KB
    cudaFuncSetAttribute(fgemm<1,0>, cudaFuncAttributeMaxDynamicSharedMemorySize, SMEM1);
    cudaFuncSetAttribute(fgemm<1,1>, cudaFuncAttributeMaxDynamicSharedMemorySize, SMEM1);
    cudaFuncSetAttribute(fgemm<2,2>, cudaFuncAttributeMaxDynamicSharedMemorySize, SMEM2);
    cudaFuncSetAttribute(fgemm<3,0>, cudaFuncAttributeMaxDynamicSharedMemorySize, SMEM3);
    cudaFuncSetAttribute(prop_gemm,  cudaFuncAttributeMaxDynamicSharedMemorySize, SMEMP);
    cudaFuncSetAttribute(readout_apply_k, cudaFuncAttributeMaxDynamicSharedMemorySize, SMEMR);

    // x -> fp16 hi/lo; weights -> transposed fp16 (re/im hi/lo)
    split_x_k<<<(BT * DMODEL + 255) / 256, 256>>>(x, pxh, pxl, BT * DMODEL);
    splitT_w_all<<<dim3(32, 32, 6), dim3(32, 8)>>>(WQ, WK, WV, Wre, Wim, WO,
                                                   pWqkv, pWrih, pWril, pWOf);

    // proj part A: x @ [WQ|WK|WV], 2-product, fused per-head split epilogue
    fgemm<2,2><<<dim3(3072 / 128, BT / 128, 1), 256, SMEM2>>>(
        pxh, pxl, 0, DMODEL, pWqkv, nullptr, 0, DMODEL,
        nullptr, nullptr, 0, 0, DMODEL, 1.f,
        pQf, pKf, pVc);
    // proj part B: x @ [Wre|Wim], 3-product -> compact Dri fp32
    fgemm<3,0><<<dim3(2048 / 128, BT / 128, 1), 256, SMEM3>>>(
        pxh, pxl, 0, DMODEL, pWrih, pWril, 0, DMODEL,
        pDri, nullptr, 0, 2048, DMODEL, 1.f,
        nullptr, nullptr, nullptr);

    // D fused transposed fp16 hi/lo (from compact Dri)
    split_D16_k<<<dim3(32, 2, 2 * NBH), dim3(32, 8)>>>(pDri, pDTh, pDTl);

    // scores = Q @ K^T / 8, single-product, fp16 output
    fgemm<1,1><<<dim3(8, 8, NBH), 256, SMEM1>>>(
        pQf, nullptr, (long)SEQT * DHEAD, DHEAD,
        pKf, nullptr, (long)SEQT * DHEAD, DHEAD,
        nullptr, pSh, (long)SEQT * SEQT, SEQT, DHEAD, 0.125f,
        nullptr, nullptr, nullptr);

    // softmax rows -> A fp16
    softmax_f16_k<<<NBH * SEQT, 256>>>(pSh, pAf);

    // propagation: single-product mma on D-hi, exact hi+lo carry
    for (int s = 0; s < NSTEPS; s++) {
        long iin = (long)(s & 1) * FEL;
        long iou = (long)(1 - (s & 1)) * FEL;
        prop_gemm<<<dim3(8, 1, NBH), 256, SMEMP>>>(
            pDTh + iin, 128L * SEQT, SEQT,
            pAf, (long)SEQT * SEQT, SEQT,
            (s == NSTEPS - 1) ? pDT : nullptr,
            pDTh + iin, pDTl + iin,
            pDTh + iou, pDTl + iou,
            128L * SEQT, SEQT, SEQT, lam);
    }

    // readout: stats (coalesced reductions) + tiled apply (coalesced writes)
    readout_stats_k<<<NBH * DHEAD / 8, 256>>>(pDT, pStats);
    readout_apply_k<<<dim3(SEQT / 128, NBH), 256, SMEMR>>>(pDT, pVc, pStats,
                                                           gate, pPf);

    // out = P @ W_O, single-product
    fgemm<1,0><<<dim3(DMODEL / 128, BT / 128, 1), 256, SMEM1>>>(
        pPf, nullptr, 0, DMODEL, pWOf, nullptr, 0, DMODEL,
        out, nullptr, 0, DMODEL, DMODEL, 1.f,
        nullptr, nullptr, nullptr);
}

// round 16
// speedup vs baseline: 1.7780x; 1.0212x over previous
#include <cuda_runtime.h>
#include <cuda_bf16.h>
#include <cuda_fp16.h>
#include <math.h>
#include <stdint.h>

// Problem constants
#define BATCH 4
#define SEQT  1024
#define DMODEL 1024
#define NHEAD 16
#define DHEAD 64
#define NBH   (BATCH*NHEAD)      // 64
#define BT    (BATCH*SEQT)       // 4096
#define NSTEPS 3

#define HEADEL (NBH*SEQT*DHEAD)          // 4,194,304
#define FEL    (2L*HEADEL)               // fused re|im D: [bh][128][1024]
#define AEL    ((size_t)NBH*SEQT*SEQT)   // 67,108,864

// ---------------- scratch (device globals; no allocation allowed) ------------
__device__ float g_gate_scratch[HEADEL];
__device__ float g_Vc[HEADEL];                     // V compact per-head [bh][t][d] fp32
__device__ float4 g_stats[NBH*DHEAD];              // per-(bh,d): {mr, mi, cmax, csum}

__device__ __half g_xh[BT*DMODEL], g_xl[BT*DMODEL];        // x fp16 hi/lo
__device__ __half g_Wqkv[3*DMODEL*DMODEL];                 // [n][k] single fp16
__device__ __half g_Wri_h[2*DMODEL*DMODEL], g_Wri_l[2*DMODEL*DMODEL]; // re/im hi/lo
__device__ __half g_WOf[DMODEL*DMODEL];                    // [n][k] single fp16
__device__ __half g_Qf[HEADEL];                            // Q single fp16
__device__ __half g_Kf[HEADEL];                            // K single fp16
__device__ __half g_Sh[AEL];                               // scores fp16
__device__ __half g_Af[AEL];                               // adjacency single fp16
__device__ __half g_DTh[2L*FEL], g_DTl[2L*FEL];            // D fp16 hi/lo [pp]
__device__ __half g_Pf[BT*DMODEL];                         // P single fp16

// ---------------- PTX helpers ------------------------------------------------
__device__ __forceinline__ uint32_t smem_u32(const void* p) {
    return (uint32_t)__cvta_generic_to_shared(p);
}
__device__ __forceinline__ void cp16(uint32_t dst, const void* src) {
    asm volatile("cp.async.cg.shared.global [%0], [%1], 16;\n" :: "r"(dst), "l"(src));
}
__device__ __forceinline__ void cp_commit() { asm volatile("cp.async.commit_group;\n"); }
template<int N> __device__ __forceinline__ void cp_wait() {
    asm volatile("cp.async.wait_group %0;\n" :: "n"(N));
}
__device__ __forceinline__ void ldsm4(uint32_t& r0, uint32_t& r1, uint32_t& r2, uint32_t& r3, uint32_t addr) {
    asm volatile("ldmatrix.sync.aligned.m8n8.x4.shared.b16 {%0,%1,%2,%3}, [%4];\n"
                 : "=r"(r0), "=r"(r1), "=r"(r2), "=r"(r3) : "r"(addr));
}
__device__ __forceinline__ void mma_f16(float* c, const uint32_t* a, const uint32_t* b) {
    asm volatile("mma.sync.aligned.m16n8k16.row.col.f32.f16.f16.f32 "
                 "{%0,%1,%2,%3}, {%4,%5,%6,%7}, {%8,%9}, {%0,%1,%2,%3};\n"
                 : "+f"(c[0]), "+f"(c[1]), "+f"(c[2]), "+f"(c[3])
                 : "r"(a[0]), "r"(a[1]), "r"(a[2]), "r"(a[3]), "r"(b[0]), "r"(b[1]));
}
__device__ __forceinline__ __half hf_hi(float v) { return __float2half(v); }
__device__ __forceinline__ __half hf_lo(float v, __half h) {
    return __float2half(v - __half2float(h));
}

// ---------------- fp16 GEMM --------------------------------------------------
// C[m][n] = alpha * sum_k (A[m][k] * B[n][k])
// NPROD==1: A single, B single. NPROD==2: A hi/lo, B single.
// NPROD==3: A hi/lo, B hi/lo (Ah*Bh + Al*Bh + Ah*Bl).
// OUT: 0 = fp32 C; 1 = fp16 C16;
//      2 = fused QKV per-head split (col0<1024 Q, <2048 K, else V fp32);
//      3 = fused D transpose+split: writes qh/kf as DTh/DTl in [bh][d][t],
//          via in-smem fp32 transpose after the mainloop (smem reused).
// BM=128, BN=128, WM=64, WN=32, BK=32.
template<int NPROD, int OUT>
__global__ __launch_bounds__(256)
void fgemm(const __half* __restrict__ Ahi, const __half* __restrict__ Alo,
           long sA, int lda,
           const __half* __restrict__ Bh_, const __half* __restrict__ Bl_,
           long sB, int ldb,
           float* __restrict__ C, __half* __restrict__ C16, long sC, int ldc,
           int K, float alpha,
           __half* __restrict__ qh, __half* __restrict__ kf, float* __restrict__ vc)
{
    constexpr int BM = 128, BN = 128, WM = 64, WN = 32;
    constexpr int STAGES = (NPROD == 3) ? 3 : 4;
    constexpr int ACH = BM * 4;
    constexpr int BCH = BN * 4;
    constexpr int MI = WM / 16;   // 4
    constexpr int NI = WN / 8;    // 4
    constexpr int WROWS = BM / WM;

    extern __shared__ uint4 sm[];
    uint4* sAh_ = sm;
    uint4* sAl_ = sAh_ + STAGES * ACH;                         // NPROD>=2 only
    uint4* sBh_ = (NPROD >= 2) ? (sAl_ + STAGES * ACH) : (sAh_ + STAGES * ACH);
    uint4* sBl_ = sBh_ + STAGES * BCH;                         // NPROD==3 only

    const int z = blockIdx.z;
    const __half* pAh = Ahi + (long)z * sA;
    const __half* pAl = (NPROD >= 2) ? (Alo + (long)z * sA) : nullptr;
    const __half* pBh = Bh_ + (long)z * sB;
    const __half* pBl = (NPROD == 3) ? (Bl_ + (long)z * sB) : nullptr;

    const int row0 = blockIdx.y * BM;
    const int col0 = blockIdx.x * BN;
    const int tid  = threadIdx.x;
    const int warp = tid >> 5, lane = tid & 31;
    const int wm = (warp % WROWS) * WM;
    const int wn = (warp / WROWS) * WN;

    float acc[MI][NI][4];
#pragma unroll
    for (int i = 0; i < MI; i++)
#pragma unroll
        for (int j = 0; j < NI; j++)
#pragma unroll
            for (int q = 0; q < 4; q++) acc[i][j][q] = 0.f;

    auto load_tile = [&](int st, int kt) {
#pragma unroll
        for (int i = tid; i < ACH; i += 256) {
            int r = i >> 2, c = i & 3;
            int phys = c ^ ((r >> 1) & 3);
            long src = (long)(row0 + r) * lda + kt * 32 + c * 8;
            cp16(smem_u32(&sAh_[st * ACH + r * 4 + phys]), pAh + src);
            if (NPROD >= 2)
                cp16(smem_u32(&sAl_[st * ACH + r * 4 + phys]), pAl + src);
        }
#pragma unroll
        for (int i = tid; i < BCH; i += 256) {
            int r = i >> 2, c = i & 3;
            int phys = c ^ ((r >> 1) & 3);
            long src = (long)(col0 + r) * ldb + kt * 32 + c * 8;
            cp16(smem_u32(&sBh_[st * BCH + r * 4 + phys]), pBh + src);
            if (NPROD == 3)
                cp16(smem_u32(&sBl_[st * BCH + r * 4 + phys]), pBl + src);
        }
        cp_commit();
    };

    const int KT = K / 32;
#pragma unroll
    for (int i = 0; i < STAGES - 1; i++) {
        if (i < KT) load_tile(i, i);
        else cp_commit();
    }

    for (int kt = 0; kt < KT; kt++) {
        cp_wait<STAGES - 2>();
        __syncthreads();

        {
            int next = kt + STAGES - 1;
            if (next < KT) load_tile(next % STAGES, next);
            else cp_commit();
        }

        const int st = kt % STAGES;
        const uint4* tAh = sAh_ + st * ACH;
        const uint4* tAl = sAl_ + st * ACH;
        const uint4* tBh = sBh_ + st * BCH;
        const uint4* tBl = sBl_ + st * BCH;
        const int tr = lane & 7;

#pragma unroll
        for (int ks8 = 0; ks8 < 2; ks8++) {
            uint32_t ah[MI][4], al[MI][4];
            const int akc = ks8 * 2 + (lane >> 4);
#pragma unroll
            for (int mi = 0; mi < MI; mi++) {
                int r = wm + mi * 16 + tr + ((lane >> 3) & 1) * 8;
                int off = r * 4 + (akc ^ ((r >> 1) & 3));
                ldsm4(ah[mi][0], ah[mi][1], ah[mi][2], ah[mi][3], smem_u32(tAh + off));
                if (NPROD >= 2)
                    ldsm4(al[mi][0], al[mi][1], al[mi][2], al[mi][3], smem_u32(tAl + off));
            }
            uint32_t bh[NI][2], bl[NI][2];
            const int bkc = ks8 * 2 + ((lane >> 3) & 1);
#pragma unroll
            for (int p = 0; p < NI / 2; p++) {
                int r = wn + p * 16 + tr + (lane >> 4) * 8;
                int off = r * 4 + (bkc ^ ((r >> 1) & 3));
                ldsm4(bh[2*p][0], bh[2*p][1], bh[2*p+1][0], bh[2*p+1][1], smem_u32(tBh + off));
                if (NPROD == 3)
                    ldsm4(bl[2*p][0], bl[2*p][1], bl[2*p+1][0], bl[2*p+1][1], smem_u32(tBl + off));
            }
#pragma unroll
            for (int mi = 0; mi < MI; mi++)
#pragma unroll
                for (int ni = 0; ni < NI; ni++) {
                    mma_f16(acc[mi][ni], ah[mi], bh[ni]);
                    if (NPROD >= 2) mma_f16(acc[mi][ni], al[mi], bh[ni]);
                    if (NPROD == 3) mma_f16(acc[mi][ni], ah[mi], bl[ni]);
                }
        }
    }

    const int g = lane >> 2, tig = lane & 3;

    if (OUT == 3) {
        // ---- fused D transpose+split: tile fp32 -> smem -> [bh][d][t] hi/lo ----
        constexpr int TW = 132;             // transpose row width (floats)
        __syncthreads();                    // mainloop smem dead
        float* smT = (float*)sm;            // [128 cc][TW]
#pragma unroll
        for (int mi = 0; mi < MI; mi++)
#pragma unroll
            for (int ni = 0; ni < NI; ni++)
#pragma unroll
                for (int half_ = 0; half_ < 2; half_++) {
                    int rrl = wm + mi * 16 + g + half_ * 8;
                    int ccl = wn + ni * 8 + tig * 2;
                    smT[ccl * TW + rrl]       = acc[mi][ni][half_ * 2 + 0];
                    smT[(ccl + 1) * TW + rrl] = acc[mi][ni][half_ * 2 + 1];
                }
        __syncthreads();
        const int b = row0 >> 10, t0 = row0 & 1023;
        for (int i = tid; i < 128 * 32; i += 256) {
            int ccl = i >> 5, tg = (i & 31) * 4;
            int cc = col0 + ccl;
            int half_ = cc >> 10, lc = cc & 1023, h = lc >> 6, d = lc & 63;
            long o = (long)((b << 4) | h) * (128 * SEQT) + (long)(half_ * 64 + d) * SEQT + t0 + tg;
            const float* src = &smT[ccl * TW + tg];
            __half2 h01, h23, l01, l23;
            h01.x = hf_hi(src[0]); h01.y = hf_hi(src[1]);
            h23.x = hf_hi(src[2]); h23.y = hf_hi(src[3]);
            l01.x = hf_lo(src[0], h01.x); l01.y = hf_lo(src[1], h01.y);
            l23.x = hf_lo(src[2], h23.x); l23.y = hf_lo(src[3], h23.y);
            *(__half2*)&qh[o]     = h01;
            *(__half2*)&qh[o + 2] = h23;
            *(__half2*)&kf[o]     = l01;
            *(__half2*)&kf[o + 2] = l23;
        }
        return;
    }

    const long zC = (long)z * sC;
#pragma unroll
    for (int mi = 0; mi < MI; mi++) {
#pragma unroll
        for (int ni = 0; ni < NI; ni++) {
#pragma unroll
            for (int half_ = 0; half_ < 2; half_++) {
                int rr = row0 + wm + mi * 16 + g + half_ * 8;
                int cc = col0 + wn + ni * 8 + tig * 2;
                float v0 = alpha * acc[mi][ni][half_ * 2 + 0];
                float v1 = alpha * acc[mi][ni][half_ * 2 + 1];
                if (OUT == 0) {
                    float2 f2; f2.x = v0; f2.y = v1;
                    *(float2*)&C[zC + (long)rr * ldc + cc] = f2;
                } else if (OUT == 1) {
                    __half2 hv; hv.x = __float2half(v0); hv.y = __float2half(v1);
                    *(__half2*)&C16[zC + (long)rr * ldc + cc] = hv;
                } else {
                    int b = rr >> 10, t = rr & 1023;
                    int lc = cc & 1023, h = lc >> 6, d = lc & 63;
                    long o = ((long)((b << 4) | h) * SEQT + t) * DHEAD + d;
                    if (col0 < 2048) {          // Q or K: single fp16
                        __half2 hv; hv.x = __float2half(v0); hv.y = __float2half(v1);
                        *(__half2*)&((col0 < 1024) ? qh : kf)[o] = hv;
                    } else {                    // V fp32 compact
                        float2 f2; f2.x = v0; f2.y = v1;
                        *(float2*)&vc[o] = f2;
                    }
                }
            }
        }
    }
}

// ---------------- fp16 propagation GEMM (single-product mma) ------------------
// DT'[m][t] = lam * sum_s (DThi[m][s]*Aadj[t][s]) + (1-lam)*(DThi+DTlo)[m][t]
__global__ __launch_bounds__(256)
void prop_gemm(const __half* __restrict__ Ahi,
               long sA, int lda,
               const __half* __restrict__ Bh_, long sB, int ldb,
               const __half* __restrict__ Cinh, const __half* __restrict__ Cinl,
               __half* __restrict__ Chi, __half* __restrict__ Clo,
               long sZ, int ldz, int K, const float* __restrict__ lam_ptr)
{
    constexpr int BM = 128, BN = 128, WM = 64, WN = 32, STAGES = 4;
    constexpr int ACH = BM * 4;
    constexpr int BCH = BN * 4;
    constexpr int MI = WM / 16;
    constexpr int NI = WN / 8;
    constexpr int WROWS = BM / WM;

    extern __shared__ uint4 sm[];
    uint4* sAh_ = sm;
    uint4* sBh_ = sAh_ + STAGES * ACH;

    const int z = blockIdx.z;
    const __half* pAh = Ahi + (long)z * sA;
    const __half* pBh = Bh_ + (long)z * sB;

    const int row0 = blockIdx.y * BM;
    const int col0 = blockIdx.x * BN;
    const int tid  = threadIdx.x;
    const int warp = tid >> 5, lane = tid & 31;
    const int wm = (warp % WROWS) * WM;
    const int wn = (warp / WROWS) * WN;

    float acc[MI][NI][4];
#pragma unroll
    for (int i = 0; i < MI; i++)
#pragma unroll
        for (int j = 0; j < NI; j++)
#pragma unroll
            for (int q = 0; q < 4; q++) acc[i][j][q] = 0.f;

    auto load_tile = [&](int st, int kt) {
#pragma unroll
        for (int i = tid; i < ACH; i += 256) {
            int r = i >> 2, c = i & 3;
            int phys = c ^ ((r >> 1) & 3);
            long src = (long)(row0 + r) * lda + kt * 32 + c * 8;
            cp16(smem_u32(&sAh_[st * ACH + r * 4 + phys]), pAh + src);
        }
#pragma unroll
        for (int i = tid; i < BCH; i += 256) {
            int r = i >> 2, c = i & 3;
            int phys = c ^ ((r >> 1) & 3);
            long src = (long)(col0 + r) * ldb + kt * 32 + c * 8;
            cp16(smem_u32(&sBh_[st * BCH + r * 4 + phys]), pBh + src);
        }
        cp_commit();
    };

    const int KT = K / 32;
#pragma unroll
    for (int i = 0; i < STAGES - 1; i++) {
        if (i < KT) load_tile(i, i);
        else cp_commit();
    }

    for (int kt = 0; kt < KT; kt++) {
        cp_wait<STAGES - 2>();
        __syncthreads();

        {
            int next = kt + STAGES - 1;
            if (next < KT) load_tile(next % STAGES, next);
            else cp_commit();
        }

        const int st = kt % STAGES;
        const uint4* tAh = sAh_ + st * ACH;
        const uint4* tBh = sBh_ + st * BCH;
        const int tr = lane & 7;

#pragma unroll
        for (int ks8 = 0; ks8 < 2; ks8++) {
            uint32_t ah[MI][4];
            const int akc = ks8 * 2 + (lane >> 4);
#pragma unroll
            for (int mi = 0; mi < MI; mi++) {
                int r = wm + mi * 16 + tr + ((lane >> 3) & 1) * 8;
                int off = r * 4 + (akc ^ ((r >> 1) & 3));
                ldsm4(ah[mi][0], ah[mi][1], ah[mi][2], ah[mi][3], smem_u32(tAh + off));
            }
            uint32_t bh[NI][2];
            const int bkc = ks8 * 2 + ((lane >> 3) & 1);
#pragma unroll
            for (int p = 0; p < NI / 2; p++) {
                int r = wn + p * 16 + tr + (lane >> 4) * 8;
                int off = r * 4 + (bkc ^ ((r >> 1) & 3));
                ldsm4(bh[2*p][0], bh[2*p][1], bh[2*p+1][0], bh[2*p+1][1], smem_u32(tBh + off));
            }
#pragma unroll
            for (int mi = 0; mi < MI; mi++)
#pragma unroll
                for (int ni = 0; ni < NI; ni++)
                    mma_f16(acc[mi][ni], ah[mi], bh[ni]);
        }
    }

    const float lm = 1.f / (1.f + __expf(-lam_ptr[0]));
    const float be = 1.f - lm;
    const long zZ = (long)z * sZ;
    const int g = lane >> 2, tig = lane & 3;
#pragma unroll
    for (int mi = 0; mi < MI; mi++) {
#pragma unroll
        for (int ni = 0; ni < NI; ni++) {
            int r = row0 + wm + mi * 16 + g;
            int cc = col0 + wn + ni * 8 + tig * 2;
#pragma unroll
            for (int half_ = 0; half_ < 2; half_++) {
                int rr = r + half_ * 8;
                long o = zZ + (long)rr * ldz + cc;
                __half2 ch = *(const __half2*)&Cinh[o];
                __half2 cl = *(const __half2*)&Cinl[o];
                float c0 = __half2float(ch.x) + __half2float(cl.x);
                float c1 = __half2float(ch.y) + __half2float(cl.y);
                float v0 = lm * acc[mi][ni][half_ * 2 + 0] + be * c0;
                float v1 = lm * acc[mi][ni][half_ * 2 + 1] + be * c1;
                __half2 hv, lv;
                hv.x = hf_hi(v0); hv.y = hf_hi(v1);
                lv.x = hf_lo(v0, hv.x); lv.y = hf_lo(v1, hv.y);
                *(__half2*)&Chi[o] = hv;
                *(__half2*)&Clo[o] = lv;
            }
        }
    }
}

// ---------------- conversions ------------------------------------------------
__global__ void split_x_k(const float* __restrict__ src,
                          __half* __restrict__ hi, __half* __restrict__ lo, int n)
{
    int i = blockIdx.x * 256 + threadIdx.x;
    if (i < n) {
        float v = src[i];
        __half h = hf_hi(v);
        hi[i] = h; lo[i] = hf_lo(v, h);
    }
}

// 6 weights [k][n] -> [n][k]; zz 0-2 -> Wqkv single (WQ, WK, WV);
// zz 3-4 -> Wri hi/lo (Wre, Wim); zz 5 -> WO single.
__global__ void splitT_w_all(const float* __restrict__ W0, const float* __restrict__ W1,
                             const float* __restrict__ W2, const float* __restrict__ W3,
                             const float* __restrict__ W4, const float* __restrict__ W5,
                             __half* __restrict__ Wqkv,
                             __half* __restrict__ Wri_h, __half* __restrict__ Wri_l,
                             __half* __restrict__ WOf)
{
    __shared__ float t[32][33];
    int zz = blockIdx.z;
    const float* W = (zz == 0) ? W0 : (zz == 1) ? W1 : (zz == 2) ? W2
                   : (zz == 3) ? W3 : (zz == 4) ? W4 : W5;
    int k0 = blockIdx.y * 32, n0 = blockIdx.x * 32;
    for (int i = threadIdx.y; i < 32; i += 8)
        t[i][threadIdx.x] = W[(k0 + i) * DMODEL + n0 + threadIdx.x];
    __syncthreads();
    for (int i = threadIdx.y; i < 32; i += 8) {
        float v = t[threadIdx.x][i];
        long o = (long)(n0 + i) * DMODEL + k0 + threadIdx.x;
        if (zz < 3) {
            Wqkv[(long)zz * DMODEL * DMODEL + o] = __float2half(v);
        } else if (zz < 5) {
            __half h = hf_hi(v);
            Wri_h[(long)(zz - 3) * DMODEL * DMODEL + o] = h;
            Wri_l[(long)(zz - 3) * DMODEL * DMODEL + o] = hf_lo(v, h);
        } else {
            WOf[o] = __float2half(v);
        }
    }
}

// ---------------- single-pass softmax over fp16 rows of 1024 -> fp16 A -------
__global__ void softmax_f16_k(const __half* __restrict__ S, __half* __restrict__ Af)
{
    const long rb = (long)blockIdx.x * SEQT;
    const int tid = threadIdx.x;
    __shared__ float sh[8];

    __half2 h01 = *(const __half2*)(S + rb + tid * 4);
    __half2 h23 = *(const __half2*)(S + rb + tid * 4 + 2);
    float v0 = __half2float(h01.x), v1 = __half2float(h01.y);
    float v2 = __half2float(h23.x), v3 = __half2float(h23.y);

    float m = fmaxf(fmaxf(v0, v1), fmaxf(v2, v3));
#pragma unroll
    for (int o = 16; o; o >>= 1) m = fmaxf(m, __shfl_xor_sync(0xffffffffu, m, o));
    if ((tid & 31) == 0) sh[tid >> 5] = m;
    __syncthreads();
    if (tid < 8) {
        float mm = sh[tid];
#pragma unroll
        for (int o = 4; o; o >>= 1) mm = fmaxf(mm, __shfl_xor_sync(0xffu, mm, o));
        sh[tid] = mm;
    }
    __syncthreads();
    m = sh[0];
    __syncthreads();

    float e0 = __expf(v0 - m), e1 = __expf(v1 - m);
    float e2 = __expf(v2 - m), e3 = __expf(v3 - m);
    float s = e0 + e1 + e2 + e3;
#pragma unroll
    for (int o = 16; o; o >>= 1) s += __shfl_xor_sync(0xffffffffu, s, o);
    if ((tid & 31) == 0) sh[tid >> 5] = s;
    __syncthreads();
    if (tid < 8) {
        float ss = sh[tid];
#pragma unroll
        for (int o = 4; o; o >>= 1) ss += __shfl_xor_sync(0xffu, ss, o);
        sh[tid] = ss;
    }
    __syncthreads();
    const float inv = 1.f / sh[0];

    __half2 a01, a23;
    a01.x = __float2half(e0 * inv); a01.y = __float2half(e1 * inv);
    a23.x = __float2half(e2 * inv); a23.y = __float2half(e3 * inv);
    *(__half2*)(Af + rb + tid * 4)     = a01;
    *(__half2*)(Af + rb + tid * 4 + 2) = a23;
}

// ---------------- readout phase 1: per-(bh,d) stats from D hi/lo -------------
__global__ void readout_stats_k(const __half* __restrict__ Fh, const __half* __restrict__ Fl,
                                float4* __restrict__ stats)
{
    int warp = threadIdx.x >> 5, lane = threadIdx.x & 31;
    int gid = blockIdx.x * 8 + warp;            // 0..4095
    int bh = gid >> 6, d = gid & 63;
    const long rbase = (long)bh * (128 * SEQT) + (long)d * SEQT;
    const long ibase = rbase + 64L * SEQT;

    float re[32], im[32];
    float sre = 0.f, sim = 0.f;
#pragma unroll
    for (int j = 0; j < 32; j++) {
        long o = lane + j * 32;
        re[j] = __half2float(Fh[rbase + o]) + __half2float(Fl[rbase + o]);
        im[j] = __half2float(Fh[ibase + o]) + __half2float(Fl[ibase + o]);
        sre += re[j]; sim += im[j];
    }
#pragma unroll
    for (int o = 16; o; o >>= 1) {
        sre += __shfl_xor_sync(0xffffffffu, sre, o);
        sim += __shfl_xor_sync(0xffffffffu, sim, o);
    }
    float mr = sre * (1.f / SEQT), mi = sim * (1.f / SEQT);
    float mn = sqrtf(mr * mr + mi * mi);

    float cs[32]; float mx = -1e30f;
#pragma unroll
    for (int j = 0; j < 32; j++) {
        float dot = re[j] * mr + im[j] * mi;
        float nrm = sqrtf(re[j] * re[j] + im[j] * im[j]) * mn + 1e-8f;
        cs[j] = dot / nrm;
        mx = fmaxf(mx, cs[j]);
    }
#pragma unroll
    for (int o = 16; o; o >>= 1) mx = fmaxf(mx, __shfl_xor_sync(0xffffffffu, mx, o));
    float s = 0.f;
#pragma unroll
    for (int j = 0; j < 32; j++) s += __expf(cs[j] - mx);
#pragma unroll
    for (int o = 16; o; o >>= 1) s += __shfl_xor_sync(0xffffffffu, s, o);

    if (lane == 0) stats[bh * DHEAD + d] = make_float4(mr, mi, mx, s);
}

// ---------------- readout phase 2: tiled apply (all accesses coalesced) ------
// block = (ttile of 128, bh). smem-staged D (hi+lo) transpose; writes gate, P.
__global__ __launch_bounds__(256)
void readout_apply_k(const __half* __restrict__ Fh, const __half* __restrict__ Fl,
                     const float* __restrict__ Vc,
                     const float4* __restrict__ stats,
                     float* __restrict__ gate, __half* __restrict__ Pf)
{
    constexpr int TP = 129;                 // row pad: conflict-free column reads
    extern __shared__ float smD[];          // [128][TP]
    __shared__ float4 sst[64];

    const int t0 = blockIdx.x * 128;
    const int bh = blockIdx.y;
    const int b = bh >> 4, h = bh & 15;
    const int tid = threadIdx.x;

    const long fb = (long)bh * (128 * SEQT);
    for (int i = tid; i < 128 * 32; i += 256) {
        int r = i >> 5, c4 = (i & 31) * 4;
        long o = fb + (long)r * SEQT + t0 + c4;
        __half2 a0 = *(const __half2*)&Fh[o], a1 = *(const __half2*)&Fh[o + 2];
        __half2 b0 = *(const __half2*)&Fl[o], b1 = *(const __half2*)&Fl[o + 2];
        float* dst = &smD[r * TP + c4];
        dst[0] = __half2float(a0.x) + __half2float(b0.x);
        dst[1] = __half2float(a0.y) + __half2float(b0.y);
        dst[2] = __half2float(a1.x) + __half2float(b1.x);
        dst[3] = __half2float(a1.y) + __half2float(b1.y);
    }
    if (tid < 64) sst[tid] = stats[bh * DHEAD + tid];
    __syncthreads();

    for (int j = 0; j < 32; j++) {
        int idx = j * 256 + tid;            // over 128 t x 64 d
        int tl = idx >> 6, d = idx & 63;
        int t = t0 + tl;
        float4 st = sst[d];
        float mn = sqrtf(st.x * st.x + st.y * st.y);
        float re = smD[d * TP + tl];
        float im = smD[(d + 64) * TP + tl];
        float dot = re * st.x + im * st.y;
        float nrm = sqrtf(re * re + im * im) * mn + 1e-8f;
        float gq = __expf(dot / nrm - st.z) * (1.f / st.w);
        long go = ((long)bh * SEQT + t) * DHEAD + d;
        gate[go] = gq;
        float pv = gq * Vc[go];
        long po = ((long)(b * SEQT + t)) * DMODEL + h * DHEAD + d;
        Pf[po] = __float2half(pv);
    }
}

// -----------------------------------------------------------------------------
extern "C" void kernel_launch(void* const* d_in, const int* in_sizes, int n_in,
                              void* d_out, int out_size)
{
    const float* x   = (const float*)d_in[0];
    const float* WQ  = (const float*)d_in[1];
    const float* WK  = (const float*)d_in[2];
    const float* Wre = (const float*)d_in[3];
    const float* Wim = (const float*)d_in[4];
    const float* WV  = (const float*)d_in[5];
    const float* WO  = (const float*)d_in[6];
    const float* lam = (const float*)d_in[7];
    float* out = (float*)d_out;

    float *pGateScr, *pVc;
    float4* pStats;
    __half *pxh, *pxl, *pWqkv, *pWrih, *pWril, *pWOf;
    __half *pQf, *pKf, *pSh, *pAf, *pDTh, *pDTl, *pPf;
    cudaGetSymbolAddress((void**)&pGateScr, g_gate_scratch);
    cudaGetSymbolAddress((void**)&pVc, g_Vc);
    cudaGetSymbolAddress((void**)&pStats, g_stats);
    cudaGetSymbolAddress((void**)&pxh, g_xh);
    cudaGetSymbolAddress((void**)&pxl, g_xl);
    cudaGetSymbolAddress((void**)&pWqkv, g_Wqkv);
    cudaGetSymbolAddress((void**)&pWrih, g_Wri_h);
    cudaGetSymbolAddress((void**)&pWril, g_Wri_l);
    cudaGetSymbolAddress((void**)&pWOf, g_WOf);
    cudaGetSymbolAddress((void**)&pQf, g_Qf);
    cudaGetSymbolAddress((void**)&pKf, g_Kf);
    cudaGetSymbolAddress((void**)&pSh, g_Sh);
    cudaGetSymbolAddress((void**)&pAf, g_Af);
    cudaGetSymbolAddress((void**)&pDTh, g_DTh);
    cudaGetSymbolAddress((void**)&pDTl, g_DTl);
    cudaGetSymbolAddress((void**)&pPf, g_Pf);

    const long OUT_ELEMS  = (long)BT * DMODEL;
    const long GATE_ELEMS = (long)HEADEL;
    float* gate = (out_size >= (int)(OUT_ELEMS + GATE_ELEMS)) ? (out + OUT_ELEMS) : pGateScr;

    const int SMEM1 = 4 * (128 * 4 * 2) * 16;   // NPROD=1: 64 KB
    const int SMEM2 = 4 * (128 * 4 * 3) * 16;   // NPROD=2: 96 KB
    const int SMEM3 = 3 * (128 * 4 * 4) * 16;   // NPROD=3: 96 KB (>= 128*132*4 transpose)
    const int SMEMP = 4 * (128 * 4 * 2) * 16;   // prop: 64 KB
    const int SMEMR = 128 * 129 * 4;            // readout apply: ~66 KB
    cudaFuncSetAttribute(fgemm<1,0>, cudaFuncAttributeMaxDynamicSharedMemorySize, SMEM1);
    cudaFuncSetAttribute(fgemm<1,1>, cudaFuncAttributeMaxDynamicSharedMemorySize, SMEM1);
    cudaFuncSetAttribute(fgemm<2,2>, cudaFuncAttributeMaxDynamicSharedMemorySize, SMEM2);
    cudaFuncSetAttribute(fgemm<3,3>, cudaFuncAttributeMaxDynamicSharedMemorySize, SMEM3);
    cudaFuncSetAttribute(prop_gemm,  cudaFuncAttributeMaxDynamicSharedMemorySize, SMEMP);
    cudaFuncSetAttribute(readout_apply_k, cudaFuncAttributeMaxDynamicSharedMemorySize, SMEMR);

    // x -> fp16 hi/lo; weights -> transposed fp16 (re/im hi/lo)
    split_x_k<<<(BT * DMODEL + 255) / 256, 256>>>(x, pxh, pxl, BT * DMODEL);
    splitT_w_all<<<dim3(32, 32, 6), dim3(32, 8)>>>(WQ, WK, WV, Wre, Wim, WO,
                                                   pWqkv, pWrih, pWril, pWOf);

    // proj part A: x @ [WQ|WK|WV], 2-product, fused per-head split epilogue
    fgemm<2,2><<<dim3(3072 / 128, BT / 128, 1), 256, SMEM2>>>(
        pxh, pxl, 0, DMODEL, pWqkv, nullptr, 0, DMODEL,
        nullptr, nullptr, 0, 0, DMODEL, 1.f,
        pQf, pKf, pVc);
    // proj part B: x @ [Wre|Wim], 3-product, fused transpose+split -> DTh/DTl (pp=0)
    fgemm<3,3><<<dim3(2048 / 128, BT / 128, 1), 256, SMEM3>>>(
        pxh, pxl, 0, DMODEL, pWrih, pWril, 0, DMODEL,
        nullptr, nullptr, 0, 0, DMODEL, 1.f,
        pDTh, pDTl, nullptr);

    // scores = Q @ K^T / 8, single-product, fp16 output
    fgemm<1,1><<<dim3(8, 8, NBH), 256, SMEM1>>>(
        pQf, nullptr, (long)SEQT * DHEAD, DHEAD,
        pKf, nullptr, (long)SEQT * DHEAD, DHEAD,
        nullptr, pSh, (long)SEQT * SEQT, SEQT, DHEAD, 0.125f,
        nullptr, nullptr, nullptr);

    // softmax rows -> A fp16
    softmax_f16_k<<<NBH * SEQT, 256>>>(pSh, pAf);

    // propagation: single-product mma on D-hi, exact hi+lo carry
    for (int s = 0; s < NSTEPS; s++) {
        long iin = (long)(s & 1) * FEL;
        long iou = (long)(1 - (s & 1)) * FEL;
        prop_gemm<<<dim3(8, 1, NBH), 256, SMEMP>>>(
            pDTh + iin, 128L * SEQT, SEQT,
            pAf, (long)SEQT * SEQT, SEQT,
            pDTh + iin, pDTl + iin,
            pDTh + iou, pDTl + iou,
            128L * SEQT, SEQT, SEQT, lam);
    }
    // after 3 steps, final D is at pp=1 (offset FEL)

    // readout: stats + tiled apply, both reading D hi/lo
    readout_stats_k<<<NBH * DHEAD / 8, 256>>>(pDTh + FEL, pDTl + FEL, pStats);
    readout_apply_k<<<dim3(SEQT / 128, NBH), 256, SMEMR>>>(pDTh + FEL, pDTl + FEL,
                                                           pVc, pStats, gate, pPf);

    // out = P @ W_O, single-product
    fgemm<1,0><<<dim3(DMODEL / 128, BT / 128, 1), 256, SMEM1>>>(
        pPf, nullptr, 0, DMODEL, pWOf, nullptr, 0, DMODEL,
        out, nullptr, 0, DMODEL, DMODEL, 1.f,
        nullptr, nullptr, nullptr);
}

// round 17
// speedup vs baseline: 1.8885x; 1.0621x over previous
#include <cuda_runtime.h>
#include <cuda_bf16.h>
#include <cuda_fp16.h>
#include <math.h>
#include <stdint.h>

// Problem constants
#define BATCH 4
#define SEQT  1024
#define DMODEL 1024
#define NHEAD 16
#define DHEAD 64
#define NBH   (BATCH*NHEAD)      // 64
#define BT    (BATCH*SEQT)       // 4096
#define NSTEPS 3

#define HEADEL (NBH*SEQT*DHEAD)          // 4,194,304
#define FEL    (2L*HEADEL)               // fused re|im D: [bh][128][1024]
#define AEL    ((size_t)NBH*SEQT*SEQT)   // 67,108,864

// ---------------- scratch (device globals; no allocation allowed) ------------
__device__ float g_gate_scratch[HEADEL];
__device__ float g_Vc[HEADEL];                     // V compact per-head [bh][t][d] fp32
__device__ float4 g_stats[NBH*DHEAD];              // per-(bh,d): {mr, mi, cmax, csum}
__device__ float g_psum[(size_t)NBH*SEQT*32];      // per-(bh,t) 32 partial exp-sums

__device__ __half g_xh[BT*DMODEL], g_xl[BT*DMODEL];        // x fp16 hi/lo
__device__ __half g_Wqkv[3*DMODEL*DMODEL];                 // [n][k] single fp16
__device__ __half g_Wri_h[2*DMODEL*DMODEL], g_Wri_l[2*DMODEL*DMODEL]; // re/im hi/lo
__device__ __half g_WOf[DMODEL*DMODEL];                    // [n][k] single fp16
__device__ __half g_Qf[HEADEL];                            // Q single fp16
__device__ __half g_Kf[HEADEL];                            // K single fp16
__device__ __half g_Ef[AEL];                               // unnormalized exp(s/8-8) fp16
__device__ __half g_DTh[2L*FEL], g_DTl[2L*FEL];            // D fp16 hi/lo [pp]
__device__ __half g_Pf[BT*DMODEL];                         // P single fp16

// ---------------- PTX helpers ------------------------------------------------
__device__ __forceinline__ uint32_t smem_u32(const void* p) {
    return (uint32_t)__cvta_generic_to_shared(p);
}
__device__ __forceinline__ void cp16(uint32_t dst, const void* src) {
    asm volatile("cp.async.cg.shared.global [%0], [%1], 16;\n" :: "r"(dst), "l"(src));
}
__device__ __forceinline__ void cp_commit() { asm volatile("cp.async.commit_group;\n"); }
template<int N> __device__ __forceinline__ void cp_wait() {
    asm volatile("cp.async.wait_group %0;\n" :: "n"(N));
}
__device__ __forceinline__ void ldsm4(uint32_t& r0, uint32_t& r1, uint32_t& r2, uint32_t& r3, uint32_t addr) {
    asm volatile("ldmatrix.sync.aligned.m8n8.x4.shared.b16 {%0,%1,%2,%3}, [%4];\n"
                 : "=r"(r0), "=r"(r1), "=r"(r2), "=r"(r3) : "r"(addr));
}
__device__ __forceinline__ void mma_f16(float* c, const uint32_t* a, const uint32_t* b) {
    asm volatile("mma.sync.aligned.m16n8k16.row.col.f32.f16.f16.f32 "
                 "{%0,%1,%2,%3}, {%4,%5,%6,%7}, {%8,%9}, {%0,%1,%2,%3};\n"
                 : "+f"(c[0]), "+f"(c[1]), "+f"(c[2]), "+f"(c[3])
                 : "r"(a[0]), "r"(a[1]), "r"(a[2]), "r"(a[3]), "r"(b[0]), "r"(b[1]));
}
__device__ __forceinline__ __half hf_hi(float v) { return __float2half(v); }
__device__ __forceinline__ __half hf_lo(float v, __half h) {
    return __float2half(v - __half2float(h));
}

// ---------------- fp16 GEMM --------------------------------------------------
// C[m][n] = alpha * sum_k (A[m][k] * B[n][k])
// NPROD==1: A single, B single. NPROD==2: A hi/lo, B single.
// NPROD==3: A hi/lo, B hi/lo (Ah*Bh + Al*Bh + Ah*Bl).
// OUT: 0 = fp32 C; 1 = fp16 C16;
//      2 = fused QKV per-head split (col0<1024 Q, <2048 K, else V fp32);
//      3 = fused D transpose+split -> qh/kf as DTh/DTl in [bh][d][t];
//      4 = scores->E: E=exp(alpha*acc-8) fp16 + per-(row,subtile) partial sums.
// BM=128, BN=128, WM=64, WN=32, BK=32.
template<int NPROD, int OUT>
__global__ __launch_bounds__(256)
void fgemm(const __half* __restrict__ Ahi, const __half* __restrict__ Alo,
           long sA, int lda,
           const __half* __restrict__ Bh_, const __half* __restrict__ Bl_,
           long sB, int ldb,
           float* __restrict__ C, __half* __restrict__ C16, long sC, int ldc,
           int K, float alpha,
           __half* __restrict__ qh, __half* __restrict__ kf, float* __restrict__ vc,
           float* __restrict__ psum)
{
    constexpr int BM = 128, BN = 128, WM = 64, WN = 32;
    constexpr int STAGES = (NPROD == 3) ? 3 : 4;
    constexpr int ACH = BM * 4;
    constexpr int BCH = BN * 4;
    constexpr int MI = WM / 16;   // 4
    constexpr int NI = WN / 8;    // 4
    constexpr int WROWS = BM / WM;

    extern __shared__ uint4 sm[];
    uint4* sAh_ = sm;
    uint4* sAl_ = sAh_ + STAGES * ACH;                         // NPROD>=2 only
    uint4* sBh_ = (NPROD >= 2) ? (sAl_ + STAGES * ACH) : (sAh_ + STAGES * ACH);
    uint4* sBl_ = sBh_ + STAGES * BCH;                         // NPROD==3 only

    const int z = blockIdx.z;
    const __half* pAh = Ahi + (long)z * sA;
    const __half* pAl = (NPROD >= 2) ? (Alo + (long)z * sA) : nullptr;
    const __half* pBh = Bh_ + (long)z * sB;
    const __half* pBl = (NPROD == 3) ? (Bl_ + (long)z * sB) : nullptr;

    const int row0 = blockIdx.y * BM;
    const int col0 = blockIdx.x * BN;
    const int tid  = threadIdx.x;
    const int warp = tid >> 5, lane = tid & 31;
    const int wm = (warp % WROWS) * WM;
    const int wn = (warp / WROWS) * WN;

    float acc[MI][NI][4];
#pragma unroll
    for (int i = 0; i < MI; i++)
#pragma unroll
        for (int j = 0; j < NI; j++)
#pragma unroll
            for (int q = 0; q < 4; q++) acc[i][j][q] = 0.f;

    auto load_tile = [&](int st, int kt) {
#pragma unroll
        for (int i = tid; i < ACH; i += 256) {
            int r = i >> 2, c = i & 3;
            int phys = c ^ ((r >> 1) & 3);
            long src = (long)(row0 + r) * lda + kt * 32 + c * 8;
            cp16(smem_u32(&sAh_[st * ACH + r * 4 + phys]), pAh + src);
            if (NPROD >= 2)
                cp16(smem_u32(&sAl_[st * ACH + r * 4 + phys]), pAl + src);
        }
#pragma unroll
        for (int i = tid; i < BCH; i += 256) {
            int r = i >> 2, c = i & 3;
            int phys = c ^ ((r >> 1) & 3);
            long src = (long)(col0 + r) * ldb + kt * 32 + c * 8;
            cp16(smem_u32(&sBh_[st * BCH + r * 4 + phys]), pBh + src);
            if (NPROD == 3)
                cp16(smem_u32(&sBl_[st * BCH + r * 4 + phys]), pBl + src);
        }
        cp_commit();
    };

    const int KT = K / 32;
#pragma unroll
    for (int i = 0; i < STAGES - 1; i++) {
        if (i < KT) load_tile(i, i);
        else cp_commit();
    }

    for (int kt = 0; kt < KT; kt++) {
        cp_wait<STAGES - 2>();
        __syncthreads();

        {
            int next = kt + STAGES - 1;
            if (next < KT) load_tile(next % STAGES, next);
            else cp_commit();
        }

        const int st = kt % STAGES;
        const uint4* tAh = sAh_ + st * ACH;
        const uint4* tAl = sAl_ + st * ACH;
        const uint4* tBh = sBh_ + st * BCH;
        const uint4* tBl = sBl_ + st * BCH;
        const int tr = lane & 7;

#pragma unroll
        for (int ks8 = 0; ks8 < 2; ks8++) {
            uint32_t ah[MI][4], al[MI][4];
            const int akc = ks8 * 2 + (lane >> 4);
#pragma unroll
            for (int mi = 0; mi < MI; mi++) {
                int r = wm + mi * 16 + tr + ((lane >> 3) & 1) * 8;
                int off = r * 4 + (akc ^ ((r >> 1) & 3));
                ldsm4(ah[mi][0], ah[mi][1], ah[mi][2], ah[mi][3], smem_u32(tAh + off));
                if (NPROD >= 2)
                    ldsm4(al[mi][0], al[mi][1], al[mi][2], al[mi][3], smem_u32(tAl + off));
            }
            uint32_t bh[NI][2], bl[NI][2];
            const int bkc = ks8 * 2 + ((lane >> 3) & 1);
#pragma unroll
            for (int p = 0; p < NI / 2; p++) {
                int r = wn + p * 16 + tr + (lane >> 4) * 8;
                int off = r * 4 + (bkc ^ ((r >> 1) & 3));
                ldsm4(bh[2*p][0], bh[2*p][1], bh[2*p+1][0], bh[2*p+1][1], smem_u32(tBh + off));
                if (NPROD == 3)
                    ldsm4(bl[2*p][0], bl[2*p][1], bl[2*p+1][0], bl[2*p+1][1], smem_u32(tBl + off));
            }
#pragma unroll
            for (int mi = 0; mi < MI; mi++)
#pragma unroll
                for (int ni = 0; ni < NI; ni++) {
                    mma_f16(acc[mi][ni], ah[mi], bh[ni]);
                    if (NPROD >= 2) mma_f16(acc[mi][ni], al[mi], bh[ni]);
                    if (NPROD == 3) mma_f16(acc[mi][ni], ah[mi], bl[ni]);
                }
        }
    }

    const int g = lane >> 2, tig = lane & 3;

    if (OUT == 3) {
        // ---- fused D transpose+split: tile fp32 -> smem -> [bh][d][t] hi/lo ----
        constexpr int TW = 132;             // transpose row width (floats)
        __syncthreads();                    // mainloop smem dead
        float* smT = (float*)sm;            // [128 cc][TW]
#pragma unroll
        for (int mi = 0; mi < MI; mi++)
#pragma unroll
            for (int ni = 0; ni < NI; ni++)
#pragma unroll
                for (int half_ = 0; half_ < 2; half_++) {
                    int rrl = wm + mi * 16 + g + half_ * 8;
                    int ccl = wn + ni * 8 + tig * 2;
                    smT[ccl * TW + rrl]       = acc[mi][ni][half_ * 2 + 0];
                    smT[(ccl + 1) * TW + rrl] = acc[mi][ni][half_ * 2 + 1];
                }
        __syncthreads();
        const int b = row0 >> 10, t0 = row0 & 1023;
        for (int i = tid; i < 128 * 32; i += 256) {
            int ccl = i >> 5, tg = (i & 31) * 4;
            int cc = col0 + ccl;
            int half_ = cc >> 10, lc = cc & 1023, h = lc >> 6, d = lc & 63;
            long o = (long)((b << 4) | h) * (128 * SEQT) + (long)(half_ * 64 + d) * SEQT + t0 + tg;
            const float* src = &smT[ccl * TW + tg];
            __half2 h01, h23, l01, l23;
            h01.x = hf_hi(src[0]); h01.y = hf_hi(src[1]);
            h23.x = hf_hi(src[2]); h23.y = hf_hi(src[3]);
            l01.x = hf_lo(src[0], h01.x); l01.y = hf_lo(src[1], h01.y);
            l23.x = hf_lo(src[2], h23.x); l23.y = hf_lo(src[3], h23.y);
            *(__half2*)&qh[o]     = h01;
            *(__half2*)&qh[o + 2] = h23;
            *(__half2*)&kf[o]     = l01;
            *(__half2*)&kf[o + 2] = l23;
        }
        return;
    }

    if (OUT == 4) {
        // ---- scores -> unnormalized E + per-(row, 32-col subtile) partials ----
        const long zC = (long)z * sC;
        float rowp[MI][2];
#pragma unroll
        for (int mi = 0; mi < MI; mi++) { rowp[mi][0] = 0.f; rowp[mi][1] = 0.f; }
#pragma unroll
        for (int mi = 0; mi < MI; mi++)
#pragma unroll
            for (int ni = 0; ni < NI; ni++)
#pragma unroll
                for (int half_ = 0; half_ < 2; half_++) {
                    int rr = row0 + wm + mi * 16 + g + half_ * 8;
                    int cc = col0 + wn + ni * 8 + tig * 2;
                    float e0 = __expf(alpha * acc[mi][ni][half_ * 2 + 0] - 8.f);
                    float e1 = __expf(alpha * acc[mi][ni][half_ * 2 + 1] - 8.f);
                    rowp[mi][half_] += e0 + e1;
                    __half2 hv; hv.x = __float2half(e0); hv.y = __float2half(e1);
                    *(__half2*)&C16[zC + (long)rr * ldc + cc] = hv;
                }
        const int warpN = warp >> 1;        // 0..3 (WROWS=2)
#pragma unroll
        for (int mi = 0; mi < MI; mi++)
#pragma unroll
            for (int half_ = 0; half_ < 2; half_++) {
                float s = rowp[mi][half_];
                s += __shfl_xor_sync(0xffffffffu, s, 1);
                s += __shfl_xor_sync(0xffffffffu, s, 2);
                if ((lane & 3) == 0) {
                    int rr = row0 + wm + mi * 16 + g + half_ * 8;
                    psum[((long)z * SEQT + rr) * 32 + blockIdx.x * 4 + warpN] = s;
                }
            }
        return;
    }

    const long zC = (long)z * sC;
#pragma unroll
    for (int mi = 0; mi < MI; mi++) {
#pragma unroll
        for (int ni = 0; ni < NI; ni++) {
#pragma unroll
            for (int half_ = 0; half_ < 2; half_++) {
                int rr = row0 + wm + mi * 16 + g + half_ * 8;
                int cc = col0 + wn + ni * 8 + tig * 2;
                float v0 = alpha * acc[mi][ni][half_ * 2 + 0];
                float v1 = alpha * acc[mi][ni][half_ * 2 + 1];
                if (OUT == 0) {
                    float2 f2; f2.x = v0; f2.y = v1;
                    *(float2*)&C[zC + (long)rr * ldc + cc] = f2;
                } else if (OUT == 1) {
                    __half2 hv; hv.x = __float2half(v0); hv.y = __float2half(v1);
                    *(__half2*)&C16[zC + (long)rr * ldc + cc] = hv;
                } else {
                    int b = rr >> 10, t = rr & 1023;
                    int lc = cc & 1023, h = lc >> 6, d = lc & 63;
                    long o = ((long)((b << 4) | h) * SEQT + t) * DHEAD + d;
                    if (col0 < 2048) {          // Q or K: single fp16
                        __half2 hv; hv.x = __float2half(v0); hv.y = __float2half(v1);
                        *(__half2*)&((col0 < 1024) ? qh : kf)[o] = hv;
                    } else {                    // V fp32 compact
                        float2 f2; f2.x = v0; f2.y = v1;
                        *(float2*)&vc[o] = f2;
                    }
                }
            }
        }
    }
}

// ---------------- fp16 propagation GEMM (single-product mma) ------------------
// DT'[m][t] = lam * r_t * sum_s (DThi[m][s]*E[t][s]) + (1-lam)*(DThi+DTlo)[m][t]
// where r_t = 1 / sum(psum[t][0..31])  (deferred softmax normalization).
__global__ __launch_bounds__(256)
void prop_gemm(const __half* __restrict__ Ahi,
               long sA, int lda,
               const __half* __restrict__ Bh_, long sB, int ldb,
               const float* __restrict__ psum,
               const __half* __restrict__ Cinh, const __half* __restrict__ Cinl,
               __half* __restrict__ Chi, __half* __restrict__ Clo,
               long sZ, int ldz, int K, const float* __restrict__ lam_ptr)
{
    constexpr int BM = 128, BN = 128, WM = 64, WN = 32, STAGES = 4;
    constexpr int ACH = BM * 4;
    constexpr int BCH = BN * 4;
    constexpr int MI = WM / 16;
    constexpr int NI = WN / 8;
    constexpr int WROWS = BM / WM;

    extern __shared__ uint4 sm[];
    uint4* sAh_ = sm;
    uint4* sBh_ = sAh_ + STAGES * ACH;
    __shared__ float rs[128];

    const int z = blockIdx.z;
    const __half* pAh = Ahi + (long)z * sA;
    const __half* pBh = Bh_ + (long)z * sB;

    const int row0 = blockIdx.y * BM;
    const int col0 = blockIdx.x * BN;
    const int tid  = threadIdx.x;
    const int warp = tid >> 5, lane = tid & 31;
    const int wm = (warp % WROWS) * WM;
    const int wn = (warp / WROWS) * WN;

    // softmax row scales for the 128 output columns of this CTA
    if (tid < 128) {
        const float* p = psum + ((long)z * SEQT + col0 + tid) * 32;
        float s = 0.f;
#pragma unroll
        for (int j = 0; j < 32; j++) s += p[j];
        rs[tid] = 1.f / s;
    }

    float acc[MI][NI][4];
#pragma unroll
    for (int i = 0; i < MI; i++)
#pragma unroll
        for (int j = 0; j < NI; j++)
#pragma unroll
            for (int q = 0; q < 4; q++) acc[i][j][q] = 0.f;

    auto load_tile = [&](int st, int kt) {
#pragma unroll
        for (int i = tid; i < ACH; i += 256) {
            int r = i >> 2, c = i & 3;
            int phys = c ^ ((r >> 1) & 3);
            long src = (long)(row0 + r) * lda + kt * 32 + c * 8;
            cp16(smem_u32(&sAh_[st * ACH + r * 4 + phys]), pAh + src);
        }
#pragma unroll
        for (int i = tid; i < BCH; i += 256) {
            int r = i >> 2, c = i & 3;
            int phys = c ^ ((r >> 1) & 3);
            long src = (long)(col0 + r) * ldb + kt * 32 + c * 8;
            cp16(smem_u32(&sBh_[st * BCH + r * 4 + phys]), pBh + src);
        }
        cp_commit();
    };

    const int KT = K / 32;
#pragma unroll
    for (int i = 0; i < STAGES - 1; i++) {
        if (i < KT) load_tile(i, i);
        else cp_commit();
    }

    for (int kt = 0; kt < KT; kt++) {
        cp_wait<STAGES - 2>();
        __syncthreads();

        {
            int next = kt + STAGES - 1;
            if (next < KT) load_tile(next % STAGES, next);
            else cp_commit();
        }

        const int st = kt % STAGES;
        const uint4* tAh = sAh_ + st * ACH;
        const uint4* tBh = sBh_ + st * BCH;
        const int tr = lane & 7;

#pragma unroll
        for (int ks8 = 0; ks8 < 2; ks8++) {
            uint32_t ah[MI][4];
            const int akc = ks8 * 2 + (lane >> 4);
#pragma unroll
            for (int mi = 0; mi < MI; mi++) {
                int r = wm + mi * 16 + tr + ((lane >> 3) & 1) * 8;
                int off = r * 4 + (akc ^ ((r >> 1) & 3));
                ldsm4(ah[mi][0], ah[mi][1], ah[mi][2], ah[mi][3], smem_u32(tAh + off));
            }
            uint32_t bh[NI][2];
            const int bkc = ks8 * 2 + ((lane >> 3) & 1);
#pragma unroll
            for (int p = 0; p < NI / 2; p++) {
                int r = wn + p * 16 + tr + (lane >> 4) * 8;
                int off = r * 4 + (bkc ^ ((r >> 1) & 3));
                ldsm4(bh[2*p][0], bh[2*p][1], bh[2*p+1][0], bh[2*p+1][1], smem_u32(tBh + off));
            }
#pragma unroll
            for (int mi = 0; mi < MI; mi++)
#pragma unroll
                for (int ni = 0; ni < NI; ni++)
                    mma_f16(acc[mi][ni], ah[mi], bh[ni]);
        }
    }

    const float lm = 1.f / (1.f + __expf(-lam_ptr[0]));
    const float be = 1.f - lm;
    const long zZ = (long)z * sZ;
    const int g = lane >> 2, tig = lane & 3;
#pragma unroll
    for (int mi = 0; mi < MI; mi++) {
#pragma unroll
        for (int ni = 0; ni < NI; ni++) {
            int r = row0 + wm + mi * 16 + g;
            int ccl = wn + ni * 8 + tig * 2;
            int cc = col0 + ccl;
            float r0 = rs[ccl], r1 = rs[ccl + 1];
#pragma unroll
            for (int half_ = 0; half_ < 2; half_++) {
                int rr = r + half_ * 8;
                long o = zZ + (long)rr * ldz + cc;
                __half2 ch = *(const __half2*)&Cinh[o];
                __half2 cl = *(const __half2*)&Cinl[o];
                float c0 = __half2float(ch.x) + __half2float(cl.x);
                float c1 = __half2float(ch.y) + __half2float(cl.y);
                float v0 = lm * acc[mi][ni][half_ * 2 + 0] * r0 + be * c0;
                float v1 = lm * acc[mi][ni][half_ * 2 + 1] * r1 + be * c1;
                __half2 hv, lv;
                hv.x = hf_hi(v0); hv.y = hf_hi(v1);
                lv.x = hf_lo(v0, hv.x); lv.y = hf_lo(v1, hv.y);
                *(__half2*)&Chi[o] = hv;
                *(__half2*)&Clo[o] = lv;
            }
        }
    }
}

// ---------------- conversions ------------------------------------------------
__global__ void split_x_k(const float* __restrict__ src,
                          __half* __restrict__ hi, __half* __restrict__ lo, int n)
{
    int i = blockIdx.x * 256 + threadIdx.x;
    if (i < n) {
        float v = src[i];
        __half h = hf_hi(v);
        hi[i] = h; lo[i] = hf_lo(v, h);
    }
}

// 6 weights [k][n] -> [n][k]; zz 0-2 -> Wqkv single (WQ, WK, WV);
// zz 3-4 -> Wri hi/lo (Wre, Wim); zz 5 -> WO single.
__global__ void splitT_w_all(const float* __restrict__ W0, const float* __restrict__ W1,
                             const float* __restrict__ W2, const float* __restrict__ W3,
                             const float* __restrict__ W4, const float* __restrict__ W5,
                             __half* __restrict__ Wqkv,
                             __half* __restrict__ Wri_h, __half* __restrict__ Wri_l,
                             __half* __restrict__ WOf)
{
    __shared__ float t[32][33];
    int zz = blockIdx.z;
    const float* W = (zz == 0) ? W0 : (zz == 1) ? W1 : (zz == 2) ? W2
                   : (zz == 3) ? W3 : (zz == 4) ? W4 : W5;
    int k0 = blockIdx.y * 32, n0 = blockIdx.x * 32;
    for (int i = threadIdx.y; i < 32; i += 8)
        t[i][threadIdx.x] = W[(k0 + i) * DMODEL + n0 + threadIdx.x];
    __syncthreads();
    for (int i = threadIdx.y; i < 32; i += 8) {
        float v = t[threadIdx.x][i];
        long o = (long)(n0 + i) * DMODEL + k0 + threadIdx.x;
        if (zz < 3) {
            Wqkv[(long)zz * DMODEL * DMODEL + o] = __float2half(v);
        } else if (zz < 5) {
            __half h = hf_hi(v);
            Wri_h[(long)(zz - 3) * DMODEL * DMODEL + o] = h;
            Wri_l[(long)(zz - 3) * DMODEL * DMODEL + o] = hf_lo(v, h);
        } else {
            WOf[o] = __float2half(v);
        }
    }
}

// ---------------- readout phase 1: per-(bh,d) stats from D hi/lo -------------
__global__ void readout_stats_k(const __half* __restrict__ Fh, const __half* __restrict__ Fl,
                                float4* __restrict__ stats)
{
    int warp = threadIdx.x >> 5, lane = threadIdx.x & 31;
    int gid = blockIdx.x * 8 + warp;            // 0..4095
    int bh = gid >> 6, d = gid & 63;
    const long rbase = (long)bh * (128 * SEQT) + (long)d * SEQT;
    const long ibase = rbase + 64L * SEQT;

    float re[32], im[32];
    float sre = 0.f, sim = 0.f;
#pragma unroll
    for (int j = 0; j < 32; j++) {
        long o = lane + j * 32;
        re[j] = __half2float(Fh[rbase + o]) + __half2float(Fl[rbase + o]);
        im[j] = __half2float(Fh[ibase + o]) + __half2float(Fl[ibase + o]);
        sre += re[j]; sim += im[j];
    }
#pragma unroll
    for (int o = 16; o; o >>= 1) {
        sre += __shfl_xor_sync(0xffffffffu, sre, o);
        sim += __shfl_xor_sync(0xffffffffu, sim, o);
    }
    float mr = sre * (1.f / SEQT), mi = sim * (1.f / SEQT);
    float mn = sqrtf(mr * mr + mi * mi);

    float cs[32]; float mx = -1e30f;
#pragma unroll
    for (int j = 0; j < 32; j++) {
        float dot = re[j] * mr + im[j] * mi;
        float nrm = sqrtf(re[j] * re[j] + im[j] * im[j]) * mn + 1e-8f;
        cs[j] = dot / nrm;
        mx = fmaxf(mx, cs[j]);
    }
#pragma unroll
    for (int o = 16; o; o >>= 1) mx = fmaxf(mx, __shfl_xor_sync(0xffffffffu, mx, o));
    float s = 0.f;
#pragma unroll
    for (int j = 0; j < 32; j++) s += __expf(cs[j] - mx);
#pragma unroll
    for (int o = 16; o; o >>= 1) s += __shfl_xor_sync(0xffffffffu, s, o);

    if (lane == 0) stats[bh * DHEAD + d] = make_float4(mr, mi, mx, s);
}

// ---------------- readout phase 2: tiled apply (all accesses coalesced) ------
// block = (ttile of 128, bh). smem-staged D (hi+lo) transpose; writes gate, P.
__global__ __launch_bounds__(256)
void readout_apply_k(const __half* __restrict__ Fh, const __half* __restrict__ Fl,
                     const float* __restrict__ Vc,
                     const float4* __restrict__ stats,
                     float* __restrict__ gate, __half* __restrict__ Pf)
{
    constexpr int TP = 129;                 // row pad: conflict-free column reads
    extern __shared__ float smD[];          // [128][TP]
    __shared__ float4 sst[64];

    const int t0 = blockIdx.x * 128;
    const int bh = blockIdx.y;
    const int b = bh >> 4, h = bh & 15;
    const int tid = threadIdx.x;

    const long fb = (long)bh * (128 * SEQT);
    for (int i = tid; i < 128 * 32; i += 256) {
        int r = i >> 5, c4 = (i & 31) * 4;
        long o = fb + (long)r * SEQT + t0 + c4;
        __half2 a0 = *(const __half2*)&Fh[o], a1 = *(const __half2*)&Fh[o + 2];
        __half2 b0 = *(const __half2*)&Fl[o], b1 = *(const __half2*)&Fl[o + 2];
        float* dst = &smD[r * TP + c4];
        dst[0] = __half2float(a0.x) + __half2float(b0.x);
        dst[1] = __half2float(a0.y) + __half2float(b0.y);
        dst[2] = __half2float(a1.x) + __half2float(b1.x);
        dst[3] = __half2float(a1.y) + __half2float(b1.y);
    }
    if (tid < 64) sst[tid] = stats[bh * DHEAD + tid];
    __syncthreads();

    for (int j = 0; j < 32; j++) {
        int idx = j * 256 + tid;            // over 128 t x 64 d
        int tl = idx >> 6, d = idx & 63;
        int t = t0 + tl;
        float4 st = sst[d];
        float mn = sqrtf(st.x * st.x + st.y * st.y);
        float re = smD[d * TP + tl];
        float im = smD[(d + 64) * TP + tl];
        float dot = re * st.x + im * st.y;
        float nrm = sqrtf(re * re + im * im) * mn + 1e-8f;
        float gq = __expf(dot / nrm - st.z) * (1.f / st.w);
        long go = ((long)bh * SEQT + t) * DHEAD + d;
        gate[go] = gq;
        float pv = gq * Vc[go];
        long po = ((long)(b * SEQT + t)) * DMODEL + h * DHEAD + d;
        Pf[po] = __float2half(pv);
    }
}

// -----------------------------------------------------------------------------
extern "C" void kernel_launch(void* const* d_in, const int* in_sizes, int n_in,
                              void* d_out, int out_size)
{
    const float* x   = (const float*)d_in[0];
    const float* WQ  = (const float*)d_in[1];
    const float* WK  = (const float*)d_in[2];
    const float* Wre = (const float*)d_in[3];
    const float* Wim = (const float*)d_in[4];
    const float* WV  = (const float*)d_in[5];
    const float* WO  = (const float*)d_in[6];
    const float* lam = (const float*)d_in[7];
    float* out = (float*)d_out;

    float *pGateScr, *pVc, *pPsum;
    float4* pStats;
    __half *pxh, *pxl, *pWqkv, *pWrih, *pWril, *pWOf;
    __half *pQf, *pKf, *pEf, *pDTh, *pDTl, *pPf;
    cudaGetSymbolAddress((void**)&pGateScr, g_gate_scratch);
    cudaGetSymbolAddress((void**)&pVc, g_Vc);
    cudaGetSymbolAddress((void**)&pStats, g_stats);
    cudaGetSymbolAddress((void**)&pPsum, g_psum);
    cudaGetSymbolAddress((void**)&pxh, g_xh);
    cudaGetSymbolAddress((void**)&pxl, g_xl);
    cudaGetSymbolAddress((void**)&pWqkv, g_Wqkv);
    cudaGetSymbolAddress((void**)&pWrih, g_Wri_h);
    cudaGetSymbolAddress((void**)&pWril, g_Wri_l);
    cudaGetSymbolAddress((void**)&pWOf, g_WOf);
    cudaGetSymbolAddress((void**)&pQf, g_Qf);
    cudaGetSymbolAddress((void**)&pKf, g_Kf);
    cudaGetSymbolAddress((void**)&pEf, g_Ef);
    cudaGetSymbolAddress((void**)&pDTh, g_DTh);
    cudaGetSymbolAddress((void**)&pDTl, g_DTl);
    cudaGetSymbolAddress((void**)&pPf, g_Pf);

    const long OUT_ELEMS  = (long)BT * DMODEL;
    const long GATE_ELEMS = (long)HEADEL;
    float* gate = (out_size >= (int)(OUT_ELEMS + GATE_ELEMS)) ? (out + OUT_ELEMS) : pGateScr;

    const int SMEM1 = 4 * (128 * 4 * 2) * 16;   // NPROD=1: 64 KB
    const int SMEM2 = 4 * (128 * 4 * 3) * 16;   // NPROD=2: 96 KB
    const int SMEM3 = 3 * (128 * 4 * 4) * 16;   // NPROD=3: 96 KB (>= 128*132*4 transpose)
    const int SMEMP = 4 * (128 * 4 * 2) * 16;   // prop: 64 KB
    const int SMEMR = 128 * 129 * 4;            // readout apply: ~66 KB
    cudaFuncSetAttribute(fgemm<1,0>, cudaFuncAttributeMaxDynamicSharedMemorySize, SMEM1);
    cudaFuncSetAttribute(fgemm<1,4>, cudaFuncAttributeMaxDynamicSharedMemorySize, SMEM1);
    cudaFuncSetAttribute(fgemm<2,2>, cudaFuncAttributeMaxDynamicSharedMemorySize, SMEM2);
    cudaFuncSetAttribute(fgemm<3,3>, cudaFuncAttributeMaxDynamicSharedMemorySize, SMEM3);
    cudaFuncSetAttribute(prop_gemm,  cudaFuncAttributeMaxDynamicSharedMemorySize, SMEMP);
    cudaFuncSetAttribute(readout_apply_k, cudaFuncAttributeMaxDynamicSharedMemorySize, SMEMR);

    // x -> fp16 hi/lo; weights -> transposed fp16 (re/im hi/lo)
    split_x_k<<<(BT * DMODEL + 255) / 256, 256>>>(x, pxh, pxl, BT * DMODEL);
    splitT_w_all<<<dim3(32, 32, 6), dim3(32, 8)>>>(WQ, WK, WV, Wre, Wim, WO,
                                                   pWqkv, pWrih, pWril, pWOf);

    // proj part A: x @ [WQ|WK|WV], 2-product, fused per-head split epilogue
    fgemm<2,2><<<dim3(3072 / 128, BT / 128, 1), 256, SMEM2>>>(
        pxh, pxl, 0, DMODEL, pWqkv, nullptr, 0, DMODEL,
        nullptr, nullptr, 0, 0, DMODEL, 1.f,
        pQf, pKf, pVc, nullptr);
    // proj part B: x @ [Wre|Wim], 3-product, fused transpose+split -> DTh/DTl (pp=0)
    fgemm<3,3><<<dim3(2048 / 128, BT / 128, 1), 256, SMEM3>>>(
        pxh, pxl, 0, DMODEL, pWrih, pWril, 0, DMODEL,
        nullptr, nullptr, 0, 0, DMODEL, 1.f,
        pDTh, pDTl, nullptr, nullptr);

    // scores -> E = exp(QK^T/8 - 8) fp16 + per-row partial sums (no softmax pass)
    fgemm<1,4><<<dim3(8, 8, NBH), 256, SMEM1>>>(
        pQf, nullptr, (long)SEQT * DHEAD, DHEAD,
        pKf, nullptr, (long)SEQT * DHEAD, DHEAD,
        nullptr, pEf, (long)SEQT * SEQT, SEQT, DHEAD, 0.125f,
        nullptr, nullptr, nullptr, pPsum);

    // propagation: single-product mma on D-hi vs E, deferred softmax scale r_t
    for (int s = 0; s < NSTEPS; s++) {
        long iin = (long)(s & 1) * FEL;
        long iou = (long)(1 - (s & 1)) * FEL;
        prop_gemm<<<dim3(8, 1, NBH), 256, SMEMP>>>(
            pDTh + iin, 128L * SEQT, SEQT,
            pEf, (long)SEQT * SEQT, SEQT,
            pPsum,
            pDTh + iin, pDTl + iin,
            pDTh + iou, pDTl + iou,
            128L * SEQT, SEQT, SEQT, lam);
    }
    // after 3 steps, final D is at pp=1 (offset FEL)

    // readout: stats + tiled apply, both reading D hi/lo
    readout_stats_k<<<NBH * DHEAD / 8, 256>>>(pDTh + FEL, pDTl + FEL, pStats);
    readout_apply_k<<<dim3(SEQT / 128, NBH), 256, SMEMR>>>(pDTh + FEL, pDTl + FEL,
                                                           pVc, pStats, gate, pPf);

    // out = P @ W_O, single-product
    fgemm<1,0><<<dim3(DMODEL / 128, BT / 128, 1), 256, SMEM1>>>(
        pPf, nullptr, 0, DMODEL, pWOf, nullptr, 0, DMODEL,
        out, nullptr, 0, DMODEL, DMODEL, 1.f,
        nullptr, nullptr, nullptr, nullptr);
}